// round 9
// baseline (speedup 1.0000x reference)
#include <cuda_runtime.h>
#include <math.h>

#define BB    8
#define CCH   64
#define C2    128
#define HH    224
#define WWID  224
#define HWSZ  (HH*WWID)          // 50176
#define NPIX  (BB*HWSZ)          // 401408

typedef unsigned long long ull;

// ---------------- packed f32x2 helpers (used by fftapply) ----------------
__device__ __forceinline__ ull pack2(float x) {
    ull r; asm("mov.b64 %0, {%1, %1};" : "=l"(r) : "f"(x)); return r;
}
__device__ __forceinline__ ull fma2(ull a, ull b, ull c) {
    ull d; asm("fma.rn.f32x2 %0, %1, %2, %3;" : "=l"(d) : "l"(a), "l"(b), "l"(c)); return d;
}

// ---------------- tf32 mma helpers ----------------
__device__ __forceinline__ unsigned cvt_tf32(float f) {
    unsigned u; asm("cvt.rna.tf32.f32 %0, %1;" : "=r"(u) : "f"(f)); return u;
}
__device__ __forceinline__ void mma8(float* c, unsigned a0, unsigned a1,
                                     unsigned a2, unsigned a3, float bx, float by) {
    unsigned b0 = __float_as_uint(bx), b1 = __float_as_uint(by);
    asm("mma.sync.aligned.m16n8k8.row.col.f32.tf32.tf32.f32 "
        "{%0,%1,%2,%3}, {%4,%5,%6,%7}, {%8,%9}, {%0,%1,%2,%3};"
        : "+f"(c[0]), "+f"(c[1]), "+f"(c[2]), "+f"(c[3])
        : "r"(a0), "r"(a1), "r"(a2), "r"(a3), "r"(b0), "r"(b1));
}

// ---------------- scratch (device globals; no allocation allowed) ----------------
static __device__ float g_buf2a[BB*C2*HWSZ];
static __device__ float g_buf2b[BB*C2*HWSZ];
static __device__ float g_bufc [BB*CCH*HWSZ];
static __device__ float g_y    [BB*CCH*HWSZ];
static __device__ float g_M    [C2*64*64];     // [c][in][out]
static __device__ float g_dctR [CCH*56];
static __device__ float g_dctC [CCH*56];
static __device__ float g_instS[BB*CCH], g_instQ[BB*CCH];
static __device__ float g_instMean[BB*CCH], g_instInv[BB*CCH];
static __device__ float g_scay[BB*CCH], g_z[BB*CCH];

// ---------------- tiny init kernels ----------------
__global__ void k_zero() {
    int t = threadIdx.x;
    if (t < BB*CCH) { g_instS[t] = 0.f; g_instQ[t] = 0.f; g_scay[t] = 0.f; }
}

__global__ void k_tables() {
    int t = blockIdx.x * blockDim.x + threadIdx.x;
    if (t >= CCH*56) return;
    int c = t / 56, i = t - c*56;
    const int mx[16] = {0,0,6,0,0,1,1,4,5,1,3,0,0,0,3,2};
    const int my[16] = {0,1,0,5,2,0,2,0,0,6,0,4,6,3,2,5};
    int g = c >> 2;
    int ux = mx[g]*8, uy = my[g]*8;
    float inv = rsqrtf(56.f);
    float rv = cosf((float)M_PI * ux * (i + 0.5f) / 56.f) * inv;
    if (ux) rv *= 1.41421356237f;
    float cv = cosf((float)M_PI * uy * (i + 0.5f) / 56.f) * inv;
    if (uy) cv *= 1.41421356237f;
    g_dctR[t] = rv; g_dctC[t] = cv;
}

__global__ void k_fftmat(const float* __restrict__ fw) {
    int t = blockIdx.x * blockDim.x + threadIdx.x;
    if (t >= C2*64) return;
    int c = t >> 6, in = t & 63, i0 = in >> 3, j0 = in & 7;
    const float c8[8] = {1.f, 0.70710678118f, 0.f, -0.70710678118f,
                         -1.f, -0.70710678118f, 0.f, 0.70710678118f};
    const float s8[8] = {0.f, 0.70710678118f, 1.f, 0.70710678118f,
                         0.f, -0.70710678118f, -1.f, -0.70710678118f};
    for (int p = 0; p < 8; p++) {
        float Gr[5], Gi[5];
        for (int v = 0; v < 5; v++) {
            float gr = 0.f, gi = 0.f;
            for (int u = 0; u < 8; u++) {
                int idx = ((u*(p - i0) - v*j0) % 8 + 8) % 8;
                float w = fw[c*40 + u*5 + v];
                gr += w * c8[idx]; gi += w * s8[idx];
            }
            Gr[v] = gr; Gi[v] = gi;
        }
        for (int q = 0; q < 8; q++) {
            float val = Gr[0] + ((q & 1) ? -Gr[4] : Gr[4]);
            for (int v = 1; v < 4; v++) {
                int k = (v*q) & 7;
                val += 2.f * (Gr[v]*c8[k] - Gi[v]*s8[k]);
            }
            g_M[c*4096 + in*64 + (p*8 + q)] = val * (1.f/64.f);
        }
    }
}

// =====================================================================
// Tensor-core conv1x1 GEMM.  128 px x (NT*8) oc per block, K=64, tf32 mma.
// Static smem, one 64*APAD buffer reused: A stage -> B stage -> out stage.
// IMODE: 0 plain, 1 channel-LN, 2 z-scale, 3 gate-product(128ch in)
// OMODE: 0 acc+bias, 1 x + beta*(acc+bias), 2 acc+add
// =====================================================================
#define APAD 136
#define OPAD 132

template<int NT, int IMODE, int OMODE>
__global__ __launch_bounds__(256, 2) void k_tc(
    const float* __restrict__ in, const float* __restrict__ w,
    const float* __restrict__ bias, const float* __restrict__ lnw,
    const float* __restrict__ lnb, float eps,
    const float* __restrict__ xres, const float* __restrict__ beta,
    const float* __restrict__ addsrc, float* __restrict__ out, int ocStride)
{
    constexpr int NOC = NT*8;
    __shared__ __align__(16) float ABsm[64*APAD];   // 34.8KB: A, then B, then out-stage
    __shared__ float sbias[128];

    int tid = threadIdx.x;
    int pix0 = blockIdx.x*128;
    int b = pix0 / HWSZ, hw0 = pix0 - b*HWSZ;

    if (tid < NOC) sbias[tid] = bias ? __ldg(bias + tid) : 0.f;

    // ---- phase 1: stage A (activations), tf32, layout [c][px] pad APAD ----
    if (IMODE == 1) {
        int p = tid >> 1, h = tid & 1;
        const float* src = in + (b*64 + h*32)*HWSZ + hw0 + p;
        float v[32];
#pragma unroll
        for (int c = 0; c < 32; c++) v[c] = src[c*HWSZ];
        float s = 0.f;
#pragma unroll
        for (int c = 0; c < 32; c++) s += v[c];
        s += __shfl_xor_sync(0xffffffffu, s, 1);
        float mu = s * (1.f/64.f);
        float q = 0.f;
#pragma unroll
        for (int c = 0; c < 32; c++) { float d = v[c]-mu; q += d*d; }
        q += __shfl_xor_sync(0xffffffffu, q, 1);
        float is = rsqrtf(q*(1.f/64.f) + eps);
#pragma unroll
        for (int c = 0; c < 32; c++) {
            int ch = h*32 + c;
            float val = (v[c]-mu)*is*__ldg(lnw+ch) + __ldg(lnb+ch);
            ABsm[ch*APAD + p] = __uint_as_float(cvt_tf32(val));
        }
    } else {
        for (int i = tid; i < 8192; i += 256) {
            int px = i & 127, c = i >> 7;
            float val;
            if (IMODE == 3) {
                val = in[(b*128 + c)*HWSZ + hw0 + px] *
                      in[(b*128 + 64 + c)*HWSZ + hw0 + px];
            } else {
                val = in[(b*64 + c)*HWSZ + hw0 + px];
                if (IMODE == 2) val *= g_z[b*64 + c];
            }
            ABsm[c*APAD + px] = __uint_as_float(cvt_tf32(val));
        }
    }
    __syncthreads();

    // ---- phase 2: pull this warp's A fragments into registers ----
    int warp = tid >> 5, lane = tid & 31, g = lane >> 2, tig = lane & 3;
    int pxA = warp*16 + g;
    unsigned afrag[8][4];
#pragma unroll
    for (int kt = 0; kt < 8; kt++) {
        int ca = kt*8 + tig;
        afrag[kt][0] = __float_as_uint(ABsm[ca*APAD + pxA]);
        afrag[kt][1] = __float_as_uint(ABsm[ca*APAD + pxA + 8]);
        afrag[kt][2] = __float_as_uint(ABsm[(ca+4)*APAD + pxA]);
        afrag[kt][3] = __float_as_uint(ABsm[(ca+4)*APAD + pxA + 8]);
    }
    __syncthreads();

    // ---- phase 3: stage B (weights) into fragment layout (reuse buffer) ----
    for (int i = tid; i < NOC*64; i += 256) {
        int k = i & 63, oc = i >> 6;
        int kt = k >> 3, kk = k & 7, nt = oc >> 3, nn = oc & 7;
        unsigned v = cvt_tf32(__ldg(w + oc*64 + k));
        int idx = ((kt*(NT/2) + (nt>>1))*32 + nn*4 + (kk&3))*4 + ((nt&1)*2 + (kk>>2));
        ABsm[idx] = __uint_as_float(v);
    }
    __syncthreads();

    // ---- phase 4: MMA mainloop (A in regs, B from smem) ----
    float acc[NT][4];
#pragma unroll
    for (int nt = 0; nt < NT; nt++)
#pragma unroll
        for (int u = 0; u < 4; u++) acc[nt][u] = 0.f;

#pragma unroll
    for (int kt = 0; kt < 8; kt++) {
#pragma unroll
        for (int np = 0; np < NT/2; np++) {
            float4 bb = *(const float4*)&ABsm[((kt*(NT/2) + np)*32 + lane)*4];
            mma8(acc[2*np],   afrag[kt][0], afrag[kt][1], afrag[kt][2], afrag[kt][3], bb.x, bb.y);
            mma8(acc[2*np+1], afrag[kt][0], afrag[kt][1], afrag[kt][2], afrag[kt][3], bb.z, bb.w);
        }
    }

    // ---- phase 5: epilogue via smem transpose, 64-oc halves, coalesced STG ----
#pragma unroll
    for (int half = 0; half < NOC/64; half++) {
        __syncthreads();      // ABsm reads (B or previous half) complete
#pragma unroll
        for (int nt2 = 0; nt2 < 8; nt2++) {
            int nt = half*8 + nt2;
            int o0 = nt2*8 + 2*tig;          // local oc in [0,64)
            int px = warp*16 + g;
            ABsm[o0*OPAD + px]         = acc[nt][0];
            ABsm[(o0+1)*OPAD + px]     = acc[nt][1];
            ABsm[o0*OPAD + px + 8]     = acc[nt][2];
            ABsm[(o0+1)*OPAD + px + 8] = acc[nt][3];
        }
        __syncthreads();
        // 64 oc x 128 px, each thread 8 float4s, fully coalesced
        for (int i = tid; i < 2048; i += 256) {
            int o = i >> 5, v = i & 31;
            int oc = half*64 + o;
            float4 r = *(const float4*)&ABsm[o*OPAD + v*4];
            int off = (b*ocStride + oc)*HWSZ + hw0 + v*4;
            if (OMODE == 0) {
                float bv = sbias[oc];
                r.x += bv; r.y += bv; r.z += bv; r.w += bv;
            } else if (OMODE == 1) {
                float bv = sbias[oc];
                float bt = __ldg(beta + oc);
                float4 xv = *(const float4*)(xres + off);
                r.x = fmaf(r.x + bv, bt, xv.x);
                r.y = fmaf(r.y + bv, bt, xv.y);
                r.z = fmaf(r.z + bv, bt, xv.z);
                r.w = fmaf(r.w + bv, bt, xv.w);
            } else {
                float4 av = *(const float4*)(addsrc + off);
                r.x += av.x; r.y += av.y; r.z += av.z; r.w += av.w;
            }
            *(float4*)(out + off) = r;
        }
    }
}

// ---------------- depthwise 3x3 (+bias) with InstanceNorm stats ----------------
__global__ __launch_bounds__(256) void k_dw_stats(
    const float* __restrict__ in, const float* __restrict__ w,
    const float* __restrict__ bias, float* __restrict__ out)
{
    int bc = blockIdx.z;
    int c = bc & 127, b = bc >> 7;
    __shared__ float tile[10][34];
    __shared__ float redS[256], redQ[256];
    int tx0 = blockIdx.x*32, ty0 = blockIdx.y*8;
    int tid = threadIdx.y*32 + threadIdx.x;
    const float* src = in + bc*HWSZ;
    for (int i = tid; i < 340; i += 256) {
        int r = i/34, cc = i - r*34;
        int gy = ty0 + r - 1, gx = tx0 + cc - 1;
        tile[r][cc] = (gy >= 0 && gy < HH && gx >= 0 && gx < WWID) ? src[gy*WWID+gx] : 0.f;
    }
    __syncthreads();
    float acc = bias[c];
#pragma unroll
    for (int di = 0; di < 3; di++)
#pragma unroll
        for (int dj = 0; dj < 3; dj++)
            acc += w[c*9 + di*3 + dj] * tile[threadIdx.y+di][threadIdx.x+dj];
    out[bc*HWSZ + (ty0+threadIdx.y)*WWID + tx0 + threadIdx.x] = acc;

    if (c < 64) {
        redS[tid] = acc; redQ[tid] = acc*acc;
        __syncthreads();
        for (int s = 128; s > 0; s >>= 1) {
            if (tid < s) { redS[tid] += redS[tid+s]; redQ[tid] += redQ[tid+s]; }
            __syncthreads();
        }
        if (tid == 0) {
            atomicAdd(&g_instS[b*64 + c], redS[0]);
            atomicAdd(&g_instQ[b*64 + c], redQ[0]);
        }
    }
}

__global__ void k_instfin() {
    int t = blockIdx.x*blockDim.x + threadIdx.x;
    if (t < BB*CCH) {
        float m = g_instS[t] * (1.f/HWSZ);
        float v = g_instQ[t] * (1.f/HWSZ) - m*m;
        g_instMean[t] = m;
        g_instInv[t]  = rsqrtf(v + 1e-5f);
    }
}

// ---------------- instnorm(a)*g -> t3 (float4), DCT-weighted SCA pool ----------------
__global__ __launch_bounds__(256) void k_gate_sca4(
    const float* __restrict__ inw, const float* __restrict__ inb)
{
    int bc = blockIdx.y;
    int c = bc & 63, b = bc >> 6;
    int i4 = blockIdx.x*256 + threadIdx.x;
    const float4* A = (const float4*)(g_buf2b + (b*128 + c)*HWSZ);
    const float4* G = (const float4*)(g_buf2b + (b*128 + 64 + c)*HWSZ);
    float m = g_instMean[bc], iv = g_instInv[bc];
    float sw = inw[c], sb = inb[c];
    float4 a = A[i4], g = G[i4];
    float4 t;
    t.x = ((a.x - m)*iv*sw + sb) * g.x;
    t.y = ((a.y - m)*iv*sw + sb) * g.y;
    t.z = ((a.z - m)*iv*sw + sb) * g.z;
    t.w = ((a.w - m)*iv*sw + sb) * g.w;
    ((float4*)(g_bufc + bc*HWSZ))[i4] = t;
    int gy = i4 / 56, gx4 = i4 - gy*56;
    float ws = (t.x + t.y + t.z + t.w) * g_dctR[c*56 + (gy >> 2)] * g_dctC[c*56 + gx4];
    __shared__ float red[256];
    red[threadIdx.x] = ws; __syncthreads();
    for (int s = 128; s > 0; s >>= 1) {
        if (threadIdx.x < s) red[threadIdx.x] += red[threadIdx.x+s];
        __syncthreads();
    }
    if (threadIdx.x == 0) atomicAdd(&g_scay[bc], red[0]);
}

__global__ void k_se(const float* __restrict__ fc1, const float* __restrict__ fc2) {
    int b = blockIdx.x, c = threadIdx.x;
    __shared__ float ys[64];
    ys[c] = g_scay[b*64 + c] * (1.f/16.f);
    __syncthreads();
    float h[4];
#pragma unroll
    for (int j = 0; j < 4; j++) {
        float s = 0.f;
#pragma unroll
        for (int k = 0; k < 64; k++) s += fc1[j*64 + k] * ys[k];
        h[j] = fmaxf(s, 0.f);
    }
    float z = 0.f;
#pragma unroll
    for (int j = 0; j < 4; j++) z += fc2[c*4 + j] * h[j];
    g_z[b*64 + c] = 1.f / (1.f + expf(-z));
}

// ---------------- per-patch spectral transform (M resident per plane) ----------------
__global__ __launch_bounds__(128) void k_fftapply_rb() {
    int bc = blockIdx.x;
    int c  = bc & 127;
    __shared__ __align__(16) float Ms[4096];
    __shared__ __align__(16) float pat[64*60];
    int tid = threadIdx.x;
    const float* msrc = g_M + c*4096;
    for (int i = tid; i < 4096; i += 128) Ms[i] = msrc[i];
    const float* src = g_buf2b + bc*HWSZ;
    float* dstp = g_buf2a + bc*HWSZ;
    int og = tid & 15, pg = tid >> 4;
    for (int bp = 0; bp < 14; bp++) {
        for (int i = tid; i < 3584; i += 128) {
            int r = i / 224, wcol = i - r*224;
            int p = r & 7, band = r >> 3, pc = wcol >> 3, q = wcol & 7;
            pat[(p*8+q)*60 + band*28 + pc] = src[(bp*16 + r)*224 + wcol];
        }
        __syncthreads();
        ull acc[4][4];
#pragma unroll
        for (int j = 0; j < 4; j++)
#pragma unroll
            for (int u = 0; u < 4; u++) acc[j][u] = 0ULL;
        if (pg < 7) {
            const float* pI = pat + pg*8;
            for (int k = 0; k < 64; k++) {
                ulonglong2 va = *(const ulonglong2*)(pI + k*60);
                ulonglong2 vb = *(const ulonglong2*)(pI + k*60 + 4);
                float4 wv = *(const float4*)(Ms + k*64 + og*4);
                float wav[4] = {wv.x, wv.y, wv.z, wv.w};
#pragma unroll
                for (int j = 0; j < 4; j++) {
                    ull wp = pack2(wav[j]);
                    acc[j][0] = fma2(va.x, wp, acc[j][0]);
                    acc[j][1] = fma2(va.y, wp, acc[j][1]);
                    acc[j][2] = fma2(vb.x, wp, acc[j][2]);
                    acc[j][3] = fma2(vb.y, wp, acc[j][3]);
                }
            }
        }
        __syncthreads();
        if (pg < 7) {
#pragma unroll
            for (int j = 0; j < 4; j++) {
                int o = og*4 + j;
                ulonglong2 s0, s1;
                s0.x = acc[j][0]; s0.y = acc[j][1];
                s1.x = acc[j][2]; s1.y = acc[j][3];
                *(ulonglong2*)(pat + o*60 + pg*8) = s0;
                *(ulonglong2*)(pat + o*60 + pg*8 + 4) = s1;
            }
        }
        __syncthreads();
        for (int i = tid; i < 3584; i += 128) {
            int r = i / 224, wcol = i - r*224;
            int p = r & 7, band = r >> 3, pc = wcol >> 3, q = wcol & 7;
            dstp[(bp*16 + r)*224 + wcol] = pat[(p*8+q)*60 + band*28 + pc];
        }
        __syncthreads();
    }
}

// ---------------- DFFN depthwise 3x3 pair + gelu gate ----------------
__global__ __launch_bounds__(256) void k_dw_gelu(const float* __restrict__ w) {
    int bc = blockIdx.z;
    int c = bc & 63, b = bc >> 6;
    __shared__ float t1[10][34], t2[10][34];
    int tx0 = blockIdx.x*32, ty0 = blockIdx.y*8;
    int tid = threadIdx.y*32 + threadIdx.x;
    const float* s1 = g_buf2a + (b*128 + c)*HWSZ;
    const float* s2 = g_buf2a + (b*128 + 64 + c)*HWSZ;
    for (int i = tid; i < 340; i += 256) {
        int r = i/34, cc = i - r*34;
        int gy = ty0 + r - 1, gx = tx0 + cc - 1;
        bool ok = (gy >= 0 && gy < HH && gx >= 0 && gx < WWID);
        t1[r][cc] = ok ? s1[gy*WWID+gx] : 0.f;
        t2[r][cc] = ok ? s2[gy*WWID+gx] : 0.f;
    }
    __syncthreads();
    float d1 = 0.f, d2 = 0.f;
#pragma unroll
    for (int di = 0; di < 3; di++)
#pragma unroll
        for (int dj = 0; dj < 3; dj++) {
            d1 += w[c*9 + di*3 + dj]      * t1[threadIdx.y+di][threadIdx.x+dj];
            d2 += w[(64+c)*9 + di*3 + dj] * t2[threadIdx.y+di][threadIdx.x+dj];
        }
    float gel = 0.5f * d1 * (1.f + erff(d1 * 0.70710678118f));
    g_bufc[bc*HWSZ + (ty0+threadIdx.y)*WWID + tx0 + threadIdx.x] = gel * d2;
}

// ---------------- launch ----------------
extern "C" void kernel_launch(void* const* d_in, const int* in_sizes, int n_in,
                              void* d_out, int out_size)
{
    (void)in_sizes; (void)n_in; (void)out_size;
    const float* x       = (const float*)d_in[0];
    const float* n1_w    = (const float*)d_in[1];
    const float* n1_b    = (const float*)d_in[2];
    const float* conv1_w = (const float*)d_in[3];
    const float* conv1_b = (const float*)d_in[4];
    const float* conv2_w = (const float*)d_in[5];
    const float* conv2_b = (const float*)d_in[6];
    const float* in_w    = (const float*)d_in[7];
    const float* in_b    = (const float*)d_in[8];
    const float* fc1_w   = (const float*)d_in[9];
    const float* fc2_w   = (const float*)d_in[10];
    const float* conv3_w = (const float*)d_in[11];
    const float* conv3_b = (const float*)d_in[12];
    const float* beta    = (const float*)d_in[13];
    const float* n2n_w   = (const float*)d_in[14];
    const float* n2n_b   = (const float*)d_in[15];
    const float* conv4_w = (const float*)d_in[16];
    const float* conv4_b = (const float*)d_in[17];
    const float* conv5_w = (const float*)d_in[18];
    const float* conv5_b = (const float*)d_in[19];
    const float* ln_w    = (const float*)d_in[20];
    const float* ln_b    = (const float*)d_in[21];
    const float* pin_w   = (const float*)d_in[22];
    const float* dw_w    = (const float*)d_in[23];
    const float* fft_w   = (const float*)d_in[24];
    const float* pout_w  = (const float*)d_in[25];

    float *t2a, *t2b, *tc, *ty;
    cudaGetSymbolAddress((void**)&t2a, g_buf2a);
    cudaGetSymbolAddress((void**)&t2b, g_buf2b);
    cudaGetSymbolAddress((void**)&tc,  g_bufc);
    cudaGetSymbolAddress((void**)&ty,  g_y);

    const int GB = NPIX / 128;     // 3136 blocks (128 px each)

    k_zero<<<1, 512>>>();
    k_tables<<<28, 128>>>();
    k_fftmat<<<64, 128>>>(fft_w);

    // conv1: LN(n1) + 64->128 + bias  -> g_buf2a
    k_tc<16,1,0><<<GB, 256>>>(x, conv1_w, conv1_b, n1_w, n1_b, 1e-6f,
                              nullptr, nullptr, nullptr, t2a, 128);

    // depthwise 3x3 + conv2 bias, InstanceNorm stats on 'a' half -> g_buf2b
    {
        dim3 g(7, 28, BB*C2), blk(32, 8);
        k_dw_stats<<<g, blk>>>(t2a, conv2_w, conv2_b, t2b);
    }
    k_instfin<<<4, 128>>>();

    // instnorm(a)*g -> t3 (g_bufc), DCT-weighted SCA pooling
    {
        dim3 g(HWSZ/(4*256), BB*CCH);
        k_gate_sca4<<<g, 256>>>(in_w, in_b);
    }
    k_se<<<BB, 64>>>(fc1_w, fc2_w);

    // conv3 on z-scaled t3 + residual -> g_buf2a
    k_tc<8,2,1><<<GB, 256>>>(tc, conv3_w, conv3_b, nullptr, nullptr, 0.f,
                             x, beta, nullptr, t2a, 64);
    // conv4: LN(n2n) + 64->128 + bias (pre-gate) -> g_buf2b
    k_tc<16,1,0><<<GB, 256>>>(t2a, conv4_w, conv4_b, n2n_w, n2n_b, 1e-6f,
                              nullptr, nullptr, nullptr, t2b, 128);
    // conv5 with SimpleGate staging -> y
    k_tc<8,3,0><<<GB, 256>>>(t2b, conv5_w, conv5_b, nullptr, nullptr, 0.f,
                             nullptr, nullptr, nullptr, ty, 64);

    // DFFN: LN + pin (64->128) -> g_buf2b
    k_tc<16,1,0><<<GB, 256>>>(ty, pin_w, nullptr, ln_w, ln_b, 1e-5f,
                              nullptr, nullptr, nullptr, t2b, 128);
    // patch spectral transform -> g_buf2a
    k_fftapply_rb<<<BB*C2, 128>>>();
    // depthwise pair + gelu gate -> g_bufc
    {
        dim3 g(7, 28, BB*CCH), blk(32, 8);
        k_dw_gelu<<<g, blk>>>(dw_w);
    }
    // pout + y -> d_out
    k_tc<8,0,2><<<GB, 256>>>(tc, pout_w, nullptr, nullptr, nullptr, 0.f,
                             nullptr, nullptr, ty, (float*)d_out, 64);
}

// round 10
// speedup vs baseline: 1.2798x; 1.2798x over previous
#include <cuda_runtime.h>
#include <math.h>

#define BB    8
#define CCH   64
#define C2    128
#define HH    224
#define WWID  224
#define HWSZ  (HH*WWID)          // 50176
#define NPIX  (BB*HWSZ)          // 401408

typedef unsigned long long ull;

// ---------------- packed f32x2 helpers (used by fftapply) ----------------
__device__ __forceinline__ ull pack2(float x) {
    ull r; asm("mov.b64 %0, {%1, %1};" : "=l"(r) : "f"(x)); return r;
}
__device__ __forceinline__ ull fma2(ull a, ull b, ull c) {
    ull d; asm("fma.rn.f32x2 %0, %1, %2, %3;" : "=l"(d) : "l"(a), "l"(b), "l"(c)); return d;
}

// ---------------- tf32 mma helpers ----------------
__device__ __forceinline__ unsigned cvt_tf32(float f) {
    unsigned u; asm("cvt.rna.tf32.f32 %0, %1;" : "=r"(u) : "f"(f)); return u;
}
__device__ __forceinline__ void mma8(float* c, unsigned a0, unsigned a1,
                                     unsigned a2, unsigned a3, float bx, float by) {
    unsigned b0 = __float_as_uint(bx), b1 = __float_as_uint(by);
    asm("mma.sync.aligned.m16n8k8.row.col.f32.tf32.tf32.f32 "
        "{%0,%1,%2,%3}, {%4,%5,%6,%7}, {%8,%9}, {%0,%1,%2,%3};"
        : "+f"(c[0]), "+f"(c[1]), "+f"(c[2]), "+f"(c[3])
        : "r"(a0), "r"(a1), "r"(a2), "r"(a3), "r"(b0), "r"(b1));
}

// ---------------- scratch (device globals; no allocation allowed) ----------------
static __device__ float g_buf2a[BB*C2*HWSZ];
static __device__ float g_buf2b[BB*C2*HWSZ];
static __device__ float g_bufc [BB*CCH*HWSZ];
static __device__ float g_y    [BB*CCH*HWSZ];
static __device__ float g_M    [C2*64*64];     // [c][in][out]
static __device__ float g_dctR [CCH*56];
static __device__ float g_dctC [CCH*56];
static __device__ float g_instS[BB*CCH], g_instQ[BB*CCH];
static __device__ float g_instMean[BB*CCH], g_instInv[BB*CCH];
static __device__ float g_scay[BB*CCH], g_z[BB*CCH];
static __device__ int   g_fftNonId;

// ---------------- tiny init kernels ----------------
__global__ void k_zero() {
    int t = threadIdx.x;
    if (t < BB*CCH) { g_instS[t] = 0.f; g_instQ[t] = 0.f; g_scay[t] = 0.f; }
    if (t == 0) g_fftNonId = 0;
}

__global__ void k_tables() {
    int t = blockIdx.x * blockDim.x + threadIdx.x;
    if (t >= CCH*56) return;
    int c = t / 56, i = t - c*56;
    const int mx[16] = {0,0,6,0,0,1,1,4,5,1,3,0,0,0,3,2};
    const int my[16] = {0,1,0,5,2,0,2,0,0,6,0,4,6,3,2,5};
    int g = c >> 2;
    int ux = mx[g]*8, uy = my[g]*8;
    float inv = rsqrtf(56.f);
    float rv = cosf((float)M_PI * ux * (i + 0.5f) / 56.f) * inv;
    if (ux) rv *= 1.41421356237f;
    float cv = cosf((float)M_PI * uy * (i + 0.5f) / 56.f) * inv;
    if (uy) cv *= 1.41421356237f;
    g_dctR[t] = rv; g_dctC[t] = cv;
}

__global__ void k_fftmat(const float* __restrict__ fw) {
    int t = blockIdx.x * blockDim.x + threadIdx.x;
    if (t >= C2*64) return;
    int c = t >> 6, in = t & 63, i0 = in >> 3, j0 = in & 7;
    const float c8[8] = {1.f, 0.70710678118f, 0.f, -0.70710678118f,
                         -1.f, -0.70710678118f, 0.f, 0.70710678118f};
    const float s8[8] = {0.f, 0.70710678118f, 1.f, 0.70710678118f,
                         0.f, -0.70710678118f, -1.f, -0.70710678118f};
    int dev = 0;
    for (int p = 0; p < 8; p++) {
        float Gr[5], Gi[5];
        for (int v = 0; v < 5; v++) {
            float gr = 0.f, gi = 0.f;
            for (int u = 0; u < 8; u++) {
                int idx = ((u*(p - i0) - v*j0) % 8 + 8) % 8;
                float w = fw[c*40 + u*5 + v];
                gr += w * c8[idx]; gi += w * s8[idx];
            }
            Gr[v] = gr; Gi[v] = gi;
        }
        for (int q = 0; q < 8; q++) {
            float val = Gr[0] + ((q & 1) ? -Gr[4] : Gr[4]);
            for (int v = 1; v < 4; v++) {
                int k = (v*q) & 7;
                val += 2.f * (Gr[v]*c8[k] - Gi[v]*s8[k]);
            }
            val *= (1.f/64.f);
            int outp = p*8 + q;
            g_M[c*4096 + in*64 + outp] = val;
            float expect = (outp == in) ? 1.f : 0.f;
            if (fabsf(val - expect) > 1e-5f) dev = 1;
        }
    }
    if (dev) g_fftNonId = 1;
}

// =====================================================================
// Tensor-core conv1x1 GEMM.  128 px x (NT*8) oc per block, K=64, tf32 mma.
// Static smem, one 64*APAD buffer reused: A stage -> B stage.
// IMODE: 0 plain, 1 channel-LN, 2 z-scale
// OMODE: 0 acc+bias, 1 x + beta*(acc+bias), 2 acc+add
// =====================================================================
#define APAD 136

template<int NT, int IMODE, int OMODE>
__global__ __launch_bounds__(256, 2) void k_tc(
    const float* __restrict__ in, const float* __restrict__ w,
    const float* __restrict__ bias, const float* __restrict__ lnw,
    const float* __restrict__ lnb, float eps,
    const float* __restrict__ xres, const float* __restrict__ beta,
    const float* __restrict__ addsrc, float* __restrict__ out, int ocStride)
{
    constexpr int NOC = NT*8;
    __shared__ __align__(16) float ABsm[64*APAD];
    __shared__ float sbias[128];

    int tid = threadIdx.x;
    int pix0 = blockIdx.x*128;
    int b = pix0 / HWSZ, hw0 = pix0 - b*HWSZ;

    if (tid < NOC) sbias[tid] = bias ? __ldg(bias + tid) : 0.f;

    // ---- phase 1: stage A ----
    if (IMODE == 1) {
        int p = tid >> 1, h = tid & 1;
        const float* src = in + (b*64 + h*32)*HWSZ + hw0 + p;
        float v[32];
#pragma unroll
        for (int c = 0; c < 32; c++) v[c] = src[c*HWSZ];
        float s = 0.f;
#pragma unroll
        for (int c = 0; c < 32; c++) s += v[c];
        s += __shfl_xor_sync(0xffffffffu, s, 1);
        float mu = s * (1.f/64.f);
        float q = 0.f;
#pragma unroll
        for (int c = 0; c < 32; c++) { float d = v[c]-mu; q += d*d; }
        q += __shfl_xor_sync(0xffffffffu, q, 1);
        float is = rsqrtf(q*(1.f/64.f) + eps);
#pragma unroll
        for (int c = 0; c < 32; c++) {
            int ch = h*32 + c;
            float val = (v[c]-mu)*is*__ldg(lnw+ch) + __ldg(lnb+ch);
            ABsm[ch*APAD + p] = __uint_as_float(cvt_tf32(val));
        }
    } else {
        for (int i = tid; i < 8192; i += 256) {
            int px = i & 127, c = i >> 7;
            float val = in[(b*64 + c)*HWSZ + hw0 + px];
            if (IMODE == 2) val *= g_z[b*64 + c];
            ABsm[c*APAD + px] = __uint_as_float(cvt_tf32(val));
        }
    }
    __syncthreads();

    // ---- phase 2: A fragments to regs ----
    int warp = tid >> 5, lane = tid & 31, g = lane >> 2, tig = lane & 3;
    int pxA = warp*16 + g;
    unsigned afrag[8][4];
#pragma unroll
    for (int kt = 0; kt < 8; kt++) {
        int ca = kt*8 + tig;
        afrag[kt][0] = __float_as_uint(ABsm[ca*APAD + pxA]);
        afrag[kt][1] = __float_as_uint(ABsm[ca*APAD + pxA + 8]);
        afrag[kt][2] = __float_as_uint(ABsm[(ca+4)*APAD + pxA]);
        afrag[kt][3] = __float_as_uint(ABsm[(ca+4)*APAD + pxA + 8]);
    }
    __syncthreads();

    // ---- phase 3: stage B fragments ----
    for (int i = tid; i < NOC*64; i += 256) {
        int k = i & 63, oc = i >> 6;
        int kt = k >> 3, kk = k & 7, nt = oc >> 3, nn = oc & 7;
        unsigned v = cvt_tf32(__ldg(w + oc*64 + k));
        int idx = ((kt*(NT/2) + (nt>>1))*32 + nn*4 + (kk&3))*4 + ((nt&1)*2 + (kk>>2));
        ABsm[idx] = __uint_as_float(v);
    }
    __syncthreads();

    // ---- phase 4: MMA mainloop ----
    float acc[NT][4];
#pragma unroll
    for (int nt = 0; nt < NT; nt++)
#pragma unroll
        for (int u = 0; u < 4; u++) acc[nt][u] = 0.f;

#pragma unroll
    for (int kt = 0; kt < 8; kt++) {
#pragma unroll
        for (int np = 0; np < NT/2; np++) {
            float4 bb = *(const float4*)&ABsm[((kt*(NT/2) + np)*32 + lane)*4];
            mma8(acc[2*np],   afrag[kt][0], afrag[kt][1], afrag[kt][2], afrag[kt][3], bb.x, bb.y);
            mma8(acc[2*np+1], afrag[kt][0], afrag[kt][1], afrag[kt][2], afrag[kt][3], bb.z, bb.w);
        }
    }

    // ---- epilogue (scattered, R7 style) ----
    int pxg = hw0 + warp*16 + g;
#pragma unroll
    for (int nt = 0; nt < NT; nt++) {
        int o0 = nt*8 + 2*tig, o1 = o0 + 1;
        int base0 = (b*ocStride + o0)*HWSZ + pxg;
        int base1 = (b*ocStride + o1)*HWSZ + pxg;
        float r0 = acc[nt][0], r1 = acc[nt][1], r2 = acc[nt][2], r3 = acc[nt][3];
        if (OMODE == 0) {
            float b0v = sbias[o0], b1v = sbias[o1];
            out[base0]     = r0 + b0v;
            out[base1]     = r1 + b1v;
            out[base0 + 8] = r2 + b0v;
            out[base1 + 8] = r3 + b1v;
        } else if (OMODE == 1) {
            float b0v = sbias[o0], b1v = sbias[o1];
            float bt0 = __ldg(beta + o0), bt1 = __ldg(beta + o1);
            out[base0]     = fmaf(r0 + b0v, bt0, __ldg(xres + base0));
            out[base1]     = fmaf(r1 + b1v, bt1, __ldg(xres + base1));
            out[base0 + 8] = fmaf(r2 + b0v, bt0, __ldg(xres + base0 + 8));
            out[base1 + 8] = fmaf(r3 + b1v, bt1, __ldg(xres + base1 + 8));
        } else {
            out[base0]     = r0 + __ldg(addsrc + base0);
            out[base1]     = r1 + __ldg(addsrc + base1);
            out[base0 + 8] = r2 + __ldg(addsrc + base0 + 8);
            out[base1 + 8] = r3 + __ldg(addsrc + base1 + 8);
        }
    }
}

// =====================================================================
// Fused conv4 (LN + 64->128) -> SimpleGate -> conv5 (64->64).
// Gate pairs (o, o+64) live in the same thread (tiles nt, nt+8).
// =====================================================================
__global__ __launch_bounds__(256, 2) void k_tc45(
    const float* __restrict__ in, const float* __restrict__ w4,
    const float* __restrict__ b4, const float* __restrict__ lnw,
    const float* __restrict__ lnb,
    const float* __restrict__ w5, const float* __restrict__ b5,
    float* __restrict__ out)
{
    __shared__ __align__(16) float ABsm[64*APAD];
    __shared__ float sb4[128], sb5[64];

    int tid = threadIdx.x;
    int pix0 = blockIdx.x*128;
    int b = pix0 / HWSZ, hw0 = pix0 - b*HWSZ;
    if (tid < 128) sb4[tid] = __ldg(b4 + tid);
    if (tid < 64)  sb5[tid] = __ldg(b5 + tid);

    // stage A with channel-LN (eps 1e-6)
    {
        int p = tid >> 1, h = tid & 1;
        const float* src = in + (b*64 + h*32)*HWSZ + hw0 + p;
        float v[32];
#pragma unroll
        for (int c = 0; c < 32; c++) v[c] = src[c*HWSZ];
        float s = 0.f;
#pragma unroll
        for (int c = 0; c < 32; c++) s += v[c];
        s += __shfl_xor_sync(0xffffffffu, s, 1);
        float mu = s * (1.f/64.f);
        float q = 0.f;
#pragma unroll
        for (int c = 0; c < 32; c++) { float d = v[c]-mu; q += d*d; }
        q += __shfl_xor_sync(0xffffffffu, q, 1);
        float is = rsqrtf(q*(1.f/64.f) + 1e-6f);
#pragma unroll
        for (int c = 0; c < 32; c++) {
            int ch = h*32 + c;
            float val = (v[c]-mu)*is*__ldg(lnw+ch) + __ldg(lnb+ch);
            ABsm[ch*APAD + p] = __uint_as_float(cvt_tf32(val));
        }
    }
    __syncthreads();

    int warp = tid >> 5, lane = tid & 31, g = lane >> 2, tig = lane & 3;
    int pxA = warp*16 + g;
    unsigned afrag[8][4];
#pragma unroll
    for (int kt = 0; kt < 8; kt++) {
        int ca = kt*8 + tig;
        afrag[kt][0] = __float_as_uint(ABsm[ca*APAD + pxA]);
        afrag[kt][1] = __float_as_uint(ABsm[ca*APAD + pxA + 8]);
        afrag[kt][2] = __float_as_uint(ABsm[(ca+4)*APAD + pxA]);
        afrag[kt][3] = __float_as_uint(ABsm[(ca+4)*APAD + pxA + 8]);
    }
    __syncthreads();

    // stage B4 fragments (NT=16)
    for (int i = tid; i < 8192; i += 256) {
        int k = i & 63, oc = i >> 6;
        int kt = k >> 3, kk = k & 7, nt = oc >> 3, nn = oc & 7;
        unsigned v = cvt_tf32(__ldg(w4 + oc*64 + k));
        int idx = ((kt*8 + (nt>>1))*32 + nn*4 + (kk&3))*4 + ((nt&1)*2 + (kk>>2));
        ABsm[idx] = __uint_as_float(v);
    }
    __syncthreads();

    // MMA 1 (conv4, NT=16)
    float acc[16][4];
#pragma unroll
    for (int nt = 0; nt < 16; nt++)
#pragma unroll
        for (int u = 0; u < 4; u++) acc[nt][u] = 0.f;
#pragma unroll
    for (int kt = 0; kt < 8; kt++) {
#pragma unroll
        for (int np = 0; np < 8; np++) {
            float4 bb = *(const float4*)&ABsm[((kt*8 + np)*32 + lane)*4];
            mma8(acc[2*np],   afrag[kt][0], afrag[kt][1], afrag[kt][2], afrag[kt][3], bb.x, bb.y);
            mma8(acc[2*np+1], afrag[kt][0], afrag[kt][1], afrag[kt][2], afrag[kt][3], bb.z, bb.w);
        }
    }

    // SimpleGate in registers: gated ch o = (y[o]+b4[o]) * (y[o+64]+b4[o+64])
    float gated[8][4];
#pragma unroll
    for (int nt = 0; nt < 8; nt++) {
        int o0 = nt*8 + 2*tig, o1 = o0 + 1;
        gated[nt][0] = (acc[nt][0] + sb4[o0]) * (acc[nt+8][0] + sb4[o0+64]);
        gated[nt][1] = (acc[nt][1] + sb4[o1]) * (acc[nt+8][1] + sb4[o1+64]);
        gated[nt][2] = (acc[nt][2] + sb4[o0]) * (acc[nt+8][2] + sb4[o0+64]);
        gated[nt][3] = (acc[nt][3] + sb4[o1]) * (acc[nt+8][3] + sb4[o1+64]);
    }
    __syncthreads();   // B4 reads complete before overwriting ABsm

    // route gated through smem as new A matrix [ch][px]
#pragma unroll
    for (int nt = 0; nt < 8; nt++) {
        int o0 = nt*8 + 2*tig, o1 = o0 + 1;
        ABsm[o0*APAD + pxA]     = __uint_as_float(cvt_tf32(gated[nt][0]));
        ABsm[o1*APAD + pxA]     = __uint_as_float(cvt_tf32(gated[nt][1]));
        ABsm[o0*APAD + pxA + 8] = __uint_as_float(cvt_tf32(gated[nt][2]));
        ABsm[o1*APAD + pxA + 8] = __uint_as_float(cvt_tf32(gated[nt][3]));
    }
    __syncthreads();

    unsigned af2[8][4];
#pragma unroll
    for (int kt = 0; kt < 8; kt++) {
        int ca = kt*8 + tig;
        af2[kt][0] = __float_as_uint(ABsm[ca*APAD + pxA]);
        af2[kt][1] = __float_as_uint(ABsm[ca*APAD + pxA + 8]);
        af2[kt][2] = __float_as_uint(ABsm[(ca+4)*APAD + pxA]);
        af2[kt][3] = __float_as_uint(ABsm[(ca+4)*APAD + pxA + 8]);
    }
    __syncthreads();

    // stage B5 fragments (NT=8)
    for (int i = tid; i < 4096; i += 256) {
        int k = i & 63, oc = i >> 6;
        int kt = k >> 3, kk = k & 7, nt = oc >> 3, nn = oc & 7;
        unsigned v = cvt_tf32(__ldg(w5 + oc*64 + k));
        int idx = ((kt*4 + (nt>>1))*32 + nn*4 + (kk&3))*4 + ((nt&1)*2 + (kk>>2));
        ABsm[idx] = __uint_as_float(v);
    }
    __syncthreads();

    // MMA 2 (conv5, NT=8)
    float a5[8][4];
#pragma unroll
    for (int nt = 0; nt < 8; nt++)
#pragma unroll
        for (int u = 0; u < 4; u++) a5[nt][u] = 0.f;
#pragma unroll
    for (int kt = 0; kt < 8; kt++) {
#pragma unroll
        for (int np = 0; np < 4; np++) {
            float4 bb = *(const float4*)&ABsm[((kt*4 + np)*32 + lane)*4];
            mma8(a5[2*np],   af2[kt][0], af2[kt][1], af2[kt][2], af2[kt][3], bb.x, bb.y);
            mma8(a5[2*np+1], af2[kt][0], af2[kt][1], af2[kt][2], af2[kt][3], bb.z, bb.w);
        }
    }

    int pxg = hw0 + warp*16 + g;
#pragma unroll
    for (int nt = 0; nt < 8; nt++) {
        int o0 = nt*8 + 2*tig, o1 = o0 + 1;
        int base0 = (b*64 + o0)*HWSZ + pxg;
        int base1 = (b*64 + o1)*HWSZ + pxg;
        out[base0]     = a5[nt][0] + sb5[o0];
        out[base1]     = a5[nt][1] + sb5[o1];
        out[base0 + 8] = a5[nt][2] + sb5[o0];
        out[base1 + 8] = a5[nt][3] + sb5[o1];
    }
}

// ---------------- depthwise 3x3 (+bias) with InstanceNorm stats ----------------
__global__ __launch_bounds__(256) void k_dw_stats(
    const float* __restrict__ in, const float* __restrict__ w,
    const float* __restrict__ bias, float* __restrict__ out)
{
    int bc = blockIdx.z;
    int c = bc & 127, b = bc >> 7;
    __shared__ float tile[10][34];
    __shared__ float redS[256], redQ[256];
    int tx0 = blockIdx.x*32, ty0 = blockIdx.y*8;
    int tid = threadIdx.y*32 + threadIdx.x;
    const float* src = in + bc*HWSZ;
    for (int i = tid; i < 340; i += 256) {
        int r = i/34, cc = i - r*34;
        int gy = ty0 + r - 1, gx = tx0 + cc - 1;
        tile[r][cc] = (gy >= 0 && gy < HH && gx >= 0 && gx < WWID) ? src[gy*WWID+gx] : 0.f;
    }
    __syncthreads();
    float acc = bias[c];
#pragma unroll
    for (int di = 0; di < 3; di++)
#pragma unroll
        for (int dj = 0; dj < 3; dj++)
            acc += w[c*9 + di*3 + dj] * tile[threadIdx.y+di][threadIdx.x+dj];
    out[bc*HWSZ + (ty0+threadIdx.y)*WWID + tx0 + threadIdx.x] = acc;

    if (c < 64) {
        redS[tid] = acc; redQ[tid] = acc*acc;
        __syncthreads();
        for (int s = 128; s > 0; s >>= 1) {
            if (tid < s) { redS[tid] += redS[tid+s]; redQ[tid] += redQ[tid+s]; }
            __syncthreads();
        }
        if (tid == 0) {
            atomicAdd(&g_instS[b*64 + c], redS[0]);
            atomicAdd(&g_instQ[b*64 + c], redQ[0]);
        }
    }
}

__global__ void k_instfin() {
    int t = blockIdx.x*blockDim.x + threadIdx.x;
    if (t < BB*CCH) {
        float m = g_instS[t] * (1.f/HWSZ);
        float v = g_instQ[t] * (1.f/HWSZ) - m*m;
        g_instMean[t] = m;
        g_instInv[t]  = rsqrtf(v + 1e-5f);
    }
}

// ---------------- instnorm(a)*g -> t3 (float4), DCT-weighted SCA pool ----------------
__global__ __launch_bounds__(256) void k_gate_sca4(
    const float* __restrict__ inw, const float* __restrict__ inb)
{
    int bc = blockIdx.y;
    int c = bc & 63, b = bc >> 6;
    int i4 = blockIdx.x*256 + threadIdx.x;
    const float4* A = (const float4*)(g_buf2b + (b*128 + c)*HWSZ);
    const float4* G = (const float4*)(g_buf2b + (b*128 + 64 + c)*HWSZ);
    float m = g_instMean[bc], iv = g_instInv[bc];
    float sw = inw[c], sb = inb[c];
    float4 a = A[i4], g = G[i4];
    float4 t;
    t.x = ((a.x - m)*iv*sw + sb) * g.x;
    t.y = ((a.y - m)*iv*sw + sb) * g.y;
    t.z = ((a.z - m)*iv*sw + sb) * g.z;
    t.w = ((a.w - m)*iv*sw + sb) * g.w;
    ((float4*)(g_bufc + bc*HWSZ))[i4] = t;
    int gy = i4 / 56, gx4 = i4 - gy*56;
    float ws = (t.x + t.y + t.z + t.w) * g_dctR[c*56 + (gy >> 2)] * g_dctC[c*56 + gx4];
    __shared__ float red[256];
    red[threadIdx.x] = ws; __syncthreads();
    for (int s = 128; s > 0; s >>= 1) {
        if (threadIdx.x < s) red[threadIdx.x] += red[threadIdx.x+s];
        __syncthreads();
    }
    if (threadIdx.x == 0) atomicAdd(&g_scay[bc], red[0]);
}

__global__ void k_se(const float* __restrict__ fc1, const float* __restrict__ fc2) {
    int b = blockIdx.x, c = threadIdx.x;
    __shared__ float ys[64];
    ys[c] = g_scay[b*64 + c] * (1.f/16.f);
    __syncthreads();
    float h[4];
#pragma unroll
    for (int j = 0; j < 4; j++) {
        float s = 0.f;
#pragma unroll
        for (int k = 0; k < 64; k++) s += fc1[j*64 + k] * ys[k];
        h[j] = fmaxf(s, 0.f);
    }
    float z = 0.f;
#pragma unroll
    for (int j = 0; j < 4; j++) z += fc2[c*4 + j] * h[j];
    g_z[b*64 + c] = 1.f / (1.f + expf(-z));
}

// ---------------- per-patch spectral transform, in-place on g_buf2a ----------------
// Early-exits when the fft weights reduce to the identity map (g_fftNonId==0).
__global__ __launch_bounds__(128) void k_fftapply_rb() {
    if (g_fftNonId == 0) return;
    int bc = blockIdx.x;
    int c  = bc & 127;
    __shared__ __align__(16) float Ms[4096];
    __shared__ __align__(16) float pat[64*60];
    int tid = threadIdx.x;
    const float* msrc = g_M + c*4096;
    for (int i = tid; i < 4096; i += 128) Ms[i] = msrc[i];
    float* plane = g_buf2a + bc*HWSZ;
    int og = tid & 15, pg = tid >> 4;
    for (int bp = 0; bp < 14; bp++) {
        for (int i = tid; i < 3584; i += 128) {
            int r = i / 224, wcol = i - r*224;
            int p = r & 7, band = r >> 3, pc = wcol >> 3, q = wcol & 7;
            pat[(p*8+q)*60 + band*28 + pc] = plane[(bp*16 + r)*224 + wcol];
        }
        __syncthreads();
        ull acc[4][4];
#pragma unroll
        for (int j = 0; j < 4; j++)
#pragma unroll
            for (int u = 0; u < 4; u++) acc[j][u] = 0ULL;
        if (pg < 7) {
            const float* pI = pat + pg*8;
            for (int k = 0; k < 64; k++) {
                ulonglong2 va = *(const ulonglong2*)(pI + k*60);
                ulonglong2 vb = *(const ulonglong2*)(pI + k*60 + 4);
                float4 wv = *(const float4*)(Ms + k*64 + og*4);
                float wav[4] = {wv.x, wv.y, wv.z, wv.w};
#pragma unroll
                for (int j = 0; j < 4; j++) {
                    ull wp = pack2(wav[j]);
                    acc[j][0] = fma2(va.x, wp, acc[j][0]);
                    acc[j][1] = fma2(va.y, wp, acc[j][1]);
                    acc[j][2] = fma2(vb.x, wp, acc[j][2]);
                    acc[j][3] = fma2(vb.y, wp, acc[j][3]);
                }
            }
        }
        __syncthreads();
        if (pg < 7) {
#pragma unroll
            for (int j = 0; j < 4; j++) {
                int o = og*4 + j;
                ulonglong2 s0, s1;
                s0.x = acc[j][0]; s0.y = acc[j][1];
                s1.x = acc[j][2]; s1.y = acc[j][3];
                *(ulonglong2*)(pat + o*60 + pg*8) = s0;
                *(ulonglong2*)(pat + o*60 + pg*8 + 4) = s1;
            }
        }
        __syncthreads();
        for (int i = tid; i < 3584; i += 128) {
            int r = i / 224, wcol = i - r*224;
            int p = r & 7, band = r >> 3, pc = wcol >> 3, q = wcol & 7;
            plane[(bp*16 + r)*224 + wcol] = pat[(p*8+q)*60 + band*28 + pc];
        }
        __syncthreads();
    }
}

// ---------------- DFFN depthwise 3x3 pair + gelu gate ----------------
__global__ __launch_bounds__(256) void k_dw_gelu(const float* __restrict__ w) {
    int bc = blockIdx.z;
    int c = bc & 63, b = bc >> 6;
    __shared__ float t1[10][34], t2[10][34];
    int tx0 = blockIdx.x*32, ty0 = blockIdx.y*8;
    int tid = threadIdx.y*32 + threadIdx.x;
    const float* s1 = g_buf2a + (b*128 + c)*HWSZ;
    const float* s2 = g_buf2a + (b*128 + 64 + c)*HWSZ;
    for (int i = tid; i < 340; i += 256) {
        int r = i/34, cc = i - r*34;
        int gy = ty0 + r - 1, gx = tx0 + cc - 1;
        bool ok = (gy >= 0 && gy < HH && gx >= 0 && gx < WWID);
        t1[r][cc] = ok ? s1[gy*WWID+gx] : 0.f;
        t2[r][cc] = ok ? s2[gy*WWID+gx] : 0.f;
    }
    __syncthreads();
    float d1 = 0.f, d2 = 0.f;
#pragma unroll
    for (int di = 0; di < 3; di++)
#pragma unroll
        for (int dj = 0; dj < 3; dj++) {
            d1 += w[c*9 + di*3 + dj]      * t1[threadIdx.y+di][threadIdx.x+dj];
            d2 += w[(64+c)*9 + di*3 + dj] * t2[threadIdx.y+di][threadIdx.x+dj];
        }
    float gel = 0.5f * d1 * (1.f + erff(d1 * 0.70710678118f));
    g_bufc[bc*HWSZ + (ty0+threadIdx.y)*WWID + tx0 + threadIdx.x] = gel * d2;
}

// ---------------- launch ----------------
extern "C" void kernel_launch(void* const* d_in, const int* in_sizes, int n_in,
                              void* d_out, int out_size)
{
    (void)in_sizes; (void)n_in; (void)out_size;
    const float* x       = (const float*)d_in[0];
    const float* n1_w    = (const float*)d_in[1];
    const float* n1_b    = (const float*)d_in[2];
    const float* conv1_w = (const float*)d_in[3];
    const float* conv1_b = (const float*)d_in[4];
    const float* conv2_w = (const float*)d_in[5];
    const float* conv2_b = (const float*)d_in[6];
    const float* in_w    = (const float*)d_in[7];
    const float* in_b    = (const float*)d_in[8];
    const float* fc1_w   = (const float*)d_in[9];
    const float* fc2_w   = (const float*)d_in[10];
    const float* conv3_w = (const float*)d_in[11];
    const float* conv3_b = (const float*)d_in[12];
    const float* beta    = (const float*)d_in[13];
    const float* n2n_w   = (const float*)d_in[14];
    const float* n2n_b   = (const float*)d_in[15];
    const float* conv4_w = (const float*)d_in[16];
    const float* conv4_b = (const float*)d_in[17];
    const float* conv5_w = (const float*)d_in[18];
    const float* conv5_b = (const float*)d_in[19];
    const float* ln_w    = (const float*)d_in[20];
    const float* ln_b    = (const float*)d_in[21];
    const float* pin_w   = (const float*)d_in[22];
    const float* dw_w    = (const float*)d_in[23];
    const float* fft_w   = (const float*)d_in[24];
    const float* pout_w  = (const float*)d_in[25];

    float *t2a, *t2b, *tc, *ty;
    cudaGetSymbolAddress((void**)&t2a, g_buf2a);
    cudaGetSymbolAddress((void**)&t2b, g_buf2b);
    cudaGetSymbolAddress((void**)&tc,  g_bufc);
    cudaGetSymbolAddress((void**)&ty,  g_y);

    const int GB = NPIX / 128;     // 3136 blocks (128 px each)

    k_zero<<<1, 512>>>();
    k_tables<<<28, 128>>>();
    k_fftmat<<<64, 128>>>(fft_w);

    // conv1: LN(n1) + 64->128 + bias  -> g_buf2a
    k_tc<16,1,0><<<GB, 256>>>(x, conv1_w, conv1_b, n1_w, n1_b, 1e-6f,
                              nullptr, nullptr, nullptr, t2a, 128);

    // depthwise 3x3 + conv2 bias, InstanceNorm stats -> g_buf2b
    {
        dim3 g(7, 28, BB*C2), blk(32, 8);
        k_dw_stats<<<g, blk>>>(t2a, conv2_w, conv2_b, t2b);
    }
    k_instfin<<<4, 128>>>();

    // instnorm(a)*g -> t3 (g_bufc), DCT-weighted SCA pooling
    {
        dim3 g(HWSZ/(4*256), BB*CCH);
        k_gate_sca4<<<g, 256>>>(in_w, in_b);
    }
    k_se<<<BB, 64>>>(fc1_w, fc2_w);

    // conv3 on z-scaled t3 + residual -> g_buf2a
    k_tc<8,2,1><<<GB, 256>>>(tc, conv3_w, conv3_b, nullptr, nullptr, 0.f,
                             x, beta, nullptr, t2a, 64);
    // fused conv4 + SimpleGate + conv5 -> y
    k_tc45<<<GB, 256>>>(t2a, conv4_w, conv4_b, n2n_w, n2n_b,
                        conv5_w, conv5_b, ty);

    // DFFN: LN + pin (64->128) -> g_buf2a (in-place fft target)
    k_tc<16,1,0><<<GB, 256>>>(ty, pin_w, nullptr, ln_w, ln_b, 1e-5f,
                              nullptr, nullptr, nullptr, t2a, 128);
    // patch spectral transform in-place (skips when identity)
    k_fftapply_rb<<<BB*C2, 128>>>();
    // depthwise pair + gelu gate -> g_bufc
    {
        dim3 g(7, 28, BB*CCH), blk(32, 8);
        k_dw_gelu<<<g, blk>>>(dw_w);
    }
    // pout + y -> d_out
    k_tc<8,0,2><<<GB, 256>>>(tc, pout_w, nullptr, nullptr, nullptr, 0.f,
                             nullptr, nullptr, ty, (float*)d_out, 64);
}

// round 12
// speedup vs baseline: 1.3031x; 1.0182x over previous
#include <cuda_runtime.h>
#include <cuda_bf16.h>
#include <math.h>

#define BB    8
#define CCH   64
#define C2    128
#define HH    224
#define WWID  224
#define HWSZ  (HH*WWID)          // 50176
#define NPIX  (BB*HWSZ)          // 401408

typedef unsigned long long ull;
typedef __nv_bfloat16 bf16;

// ---------------- packed f32x2 helpers (used by fftapply) ----------------
__device__ __forceinline__ ull pack2(float x) {
    ull r; asm("mov.b64 %0, {%1, %1};" : "=l"(r) : "f"(x)); return r;
}
__device__ __forceinline__ ull fma2(ull a, ull b, ull c) {
    ull d; asm("fma.rn.f32x2 %0, %1, %2, %3;" : "=l"(d) : "l"(a), "l"(b), "l"(c)); return d;
}

// ---------------- tf32 mma helpers ----------------
__device__ __forceinline__ unsigned cvt_tf32(float f) {
    unsigned u; asm("cvt.rna.tf32.f32 %0, %1;" : "=r"(u) : "f"(f)); return u;
}
__device__ __forceinline__ void mma8(float* c, unsigned a0, unsigned a1,
                                     unsigned a2, unsigned a3, float bx, float by) {
    unsigned b0 = __float_as_uint(bx), b1 = __float_as_uint(by);
    asm("mma.sync.aligned.m16n8k8.row.col.f32.tf32.tf32.f32 "
        "{%0,%1,%2,%3}, {%4,%5,%6,%7}, {%8,%9}, {%0,%1,%2,%3};"
        : "+f"(c[0]), "+f"(c[1]), "+f"(c[2]), "+f"(c[3])
        : "r"(a0), "r"(a1), "r"(a2), "r"(a3), "r"(b0), "r"(b1));
}

// ---------------- scratch (device globals; no allocation allowed) ----------------
static __device__ float g_buf2a[BB*C2*HWSZ];   // fp32: residual / pin-out / fft
static __device__ float g_buf2b[BB*C2*HWSZ];   // carved: 2 bf16 buffers (conv1out, dwout)
static __device__ float g_bufc [BB*CCH*HWSZ];  // fp32: dffn gelu-gated
static __device__ float g_y    [BB*CCH*HWSZ];  // fp32: NAF output y
static __device__ float g_M    [C2*64*64];     // [c][in][out]
static __device__ float g_dctR [CCH*56];
static __device__ float g_dctC [CCH*56];
static __device__ float g_instS[BB*CCH], g_instQ[BB*CCH];
static __device__ float g_instMean[BB*CCH], g_instInv[BB*CCH];
static __device__ float g_scay[BB*CCH], g_z[BB*CCH];
static __device__ int   g_fftNonId;

// ---------------- tiny init kernels ----------------
__global__ void k_zero() {
    int t = threadIdx.x;
    if (t < BB*CCH) { g_instS[t] = 0.f; g_instQ[t] = 0.f; g_scay[t] = 0.f; }
    if (t == 0) g_fftNonId = 0;
}

__global__ void k_tables() {
    int t = blockIdx.x * blockDim.x + threadIdx.x;
    if (t >= CCH*56) return;
    int c = t / 56, i = t - c*56;
    const int mx[16] = {0,0,6,0,0,1,1,4,5,1,3,0,0,0,3,2};
    const int my[16] = {0,1,0,5,2,0,2,0,0,6,0,4,6,3,2,5};
    int g = c >> 2;
    int ux = mx[g]*8, uy = my[g]*8;
    float inv = rsqrtf(56.f);
    float rv = cosf((float)M_PI * ux * (i + 0.5f) / 56.f) * inv;
    if (ux) rv *= 1.41421356237f;
    float cv = cosf((float)M_PI * uy * (i + 0.5f) / 56.f) * inv;
    if (uy) cv *= 1.41421356237f;
    g_dctR[t] = rv; g_dctC[t] = cv;
}

__global__ void k_fftmat(const float* __restrict__ fw) {
    int t = blockIdx.x * blockDim.x + threadIdx.x;
    if (t >= C2*64) return;
    int c = t >> 6, in = t & 63, i0 = in >> 3, j0 = in & 7;
    const float c8[8] = {1.f, 0.70710678118f, 0.f, -0.70710678118f,
                         -1.f, -0.70710678118f, 0.f, 0.70710678118f};
    const float s8[8] = {0.f, 0.70710678118f, 1.f, 0.70710678118f,
                         0.f, -0.70710678118f, -1.f, -0.70710678118f};
    int dev = 0;
    for (int p = 0; p < 8; p++) {
        float Gr[5], Gi[5];
        for (int v = 0; v < 5; v++) {
            float gr = 0.f, gi = 0.f;
            for (int u = 0; u < 8; u++) {
                int idx = ((u*(p - i0) - v*j0) % 8 + 8) % 8;
                float w = fw[c*40 + u*5 + v];
                gr += w * c8[idx]; gi += w * s8[idx];
            }
            Gr[v] = gr; Gi[v] = gi;
        }
        for (int q = 0; q < 8; q++) {
            float val = Gr[0] + ((q & 1) ? -Gr[4] : Gr[4]);
            for (int v = 1; v < 4; v++) {
                int k = (v*q) & 7;
                val += 2.f * (Gr[v]*c8[k] - Gi[v]*s8[k]);
            }
            val *= (1.f/64.f);
            int outp = p*8 + q;
            g_M[c*4096 + in*64 + outp] = val;
            float expect = (outp == in) ? 1.f : 0.f;
            if (fabsf(val - expect) > 1e-5f) dev = 1;
        }
    }
    if (dev) g_fftNonId = 1;
}

// =====================================================================
// Tensor-core conv1x1 GEMM.  128 px x (NT*8) oc per block, K=64, tf32 mma.
// IMODE: 0 plain f32, 1 channel-LN f32, 4 inline instnorm-gate from bf16
// OMODE: 0 acc+bias, 1 x + beta*(acc+bias), 2 acc+add     OBF: bf16 out (OMODE0)
// =====================================================================
#define APAD 136

template<int NT, int IMODE, int OMODE, int OBF>
__global__ __launch_bounds__(256, 2) void k_tc(
    const float* __restrict__ in, const float* __restrict__ w,
    const float* __restrict__ bias, const float* __restrict__ lnw,
    const float* __restrict__ lnb, float eps,
    const float* __restrict__ xres, const float* __restrict__ beta,
    const float* __restrict__ addsrc, float* __restrict__ out, int ocStride)
{
    constexpr int NOC = NT*8;
    __shared__ __align__(16) float ABsm[64*APAD];
    __shared__ float sbias[128];
    __shared__ float sAZ[64], sBZ[64];

    int tid = threadIdx.x;
    int pix0 = blockIdx.x*128;
    int b = pix0 / HWSZ, hw0 = pix0 - b*HWSZ;

    if (tid < NOC) sbias[tid] = bias ? __ldg(bias + tid) : 0.f;

    // ---- phase 1: stage A ----
    if (IMODE == 1) {
        int p = tid >> 1, h = tid & 1;
        const float* src = in + (b*64 + h*32)*HWSZ + hw0 + p;
        float v[32];
#pragma unroll
        for (int c = 0; c < 32; c++) v[c] = src[c*HWSZ];
        float s = 0.f;
#pragma unroll
        for (int c = 0; c < 32; c++) s += v[c];
        s += __shfl_xor_sync(0xffffffffu, s, 1);
        float mu = s * (1.f/64.f);
        float q = 0.f;
#pragma unroll
        for (int c = 0; c < 32; c++) { float d = v[c]-mu; q += d*d; }
        q += __shfl_xor_sync(0xffffffffu, q, 1);
        float is = rsqrtf(q*(1.f/64.f) + eps);
#pragma unroll
        for (int c = 0; c < 32; c++) {
            int ch = h*32 + c;
            float val = (v[c]-mu)*is*__ldg(lnw+ch) + __ldg(lnb+ch);
            ABsm[ch*APAD + p] = __uint_as_float(cvt_tf32(val));
        }
    } else if (IMODE == 4) {
        // t3*z = (a*AZ + BZ)*g  from bf16 dw-output planes
        if (tid < 64) {
            int bc = b*64 + tid;
            float iv = g_instInv[bc];
            float A  = iv*__ldg(lnw + tid);
            float z  = g_z[bc];
            sAZ[tid] = A*z;
            sBZ[tid] = (__ldg(lnb + tid) - g_instMean[bc]*A)*z;
        }
        __syncthreads();
        const bf16* inb16 = (const bf16*)in;
        for (int i = tid; i < 8192; i += 256) {
            int px = i & 127, c = i >> 7;
            float a  = __bfloat162float(inb16[(b*128 + c)*HWSZ + hw0 + px]);
            float gg = __bfloat162float(inb16[(b*128 + 64 + c)*HWSZ + hw0 + px]);
            float val = (a*sAZ[c] + sBZ[c])*gg;
            ABsm[c*APAD + px] = __uint_as_float(cvt_tf32(val));
        }
    } else {
        for (int i = tid; i < 8192; i += 256) {
            int px = i & 127, c = i >> 7;
            float val = in[(b*64 + c)*HWSZ + hw0 + px];
            ABsm[c*APAD + px] = __uint_as_float(cvt_tf32(val));
        }
    }
    __syncthreads();

    // ---- phase 2: A fragments to regs ----
    int warp = tid >> 5, lane = tid & 31, g = lane >> 2, tig = lane & 3;
    int pxA = warp*16 + g;
    unsigned afrag[8][4];
#pragma unroll
    for (int kt = 0; kt < 8; kt++) {
        int ca = kt*8 + tig;
        afrag[kt][0] = __float_as_uint(ABsm[ca*APAD + pxA]);
        afrag[kt][1] = __float_as_uint(ABsm[ca*APAD + pxA + 8]);
        afrag[kt][2] = __float_as_uint(ABsm[(ca+4)*APAD + pxA]);
        afrag[kt][3] = __float_as_uint(ABsm[(ca+4)*APAD + pxA + 8]);
    }
    __syncthreads();

    // ---- phase 3: stage B fragments ----
    for (int i = tid; i < NOC*64; i += 256) {
        int k = i & 63, oc = i >> 6;
        int kt = k >> 3, kk = k & 7, nt = oc >> 3, nn = oc & 7;
        unsigned v = cvt_tf32(__ldg(w + oc*64 + k));
        int idx = ((kt*(NT/2) + (nt>>1))*32 + nn*4 + (kk&3))*4 + ((nt&1)*2 + (kk>>2));
        ABsm[idx] = __uint_as_float(v);
    }
    __syncthreads();

    // ---- phase 4: MMA mainloop ----
    float acc[NT][4];
#pragma unroll
    for (int nt = 0; nt < NT; nt++)
#pragma unroll
        for (int u = 0; u < 4; u++) acc[nt][u] = 0.f;

#pragma unroll
    for (int kt = 0; kt < 8; kt++) {
#pragma unroll
        for (int np = 0; np < NT/2; np++) {
            float4 bb = *(const float4*)&ABsm[((kt*(NT/2) + np)*32 + lane)*4];
            mma8(acc[2*np],   afrag[kt][0], afrag[kt][1], afrag[kt][2], afrag[kt][3], bb.x, bb.y);
            mma8(acc[2*np+1], afrag[kt][0], afrag[kt][1], afrag[kt][2], afrag[kt][3], bb.z, bb.w);
        }
    }

    // ---- epilogue (scattered) ----
    int pxg = hw0 + warp*16 + g;
#pragma unroll
    for (int nt = 0; nt < NT; nt++) {
        int o0 = nt*8 + 2*tig, o1 = o0 + 1;
        int base0 = (b*ocStride + o0)*HWSZ + pxg;
        int base1 = (b*ocStride + o1)*HWSZ + pxg;
        float r0 = acc[nt][0], r1 = acc[nt][1], r2 = acc[nt][2], r3 = acc[nt][3];
        if (OMODE == 0) {
            float b0v = sbias[o0], b1v = sbias[o1];
            if (OBF) {
                bf16* ob = (bf16*)out;
                ob[base0]     = __float2bfloat16(r0 + b0v);
                ob[base1]     = __float2bfloat16(r1 + b1v);
                ob[base0 + 8] = __float2bfloat16(r2 + b0v);
                ob[base1 + 8] = __float2bfloat16(r3 + b1v);
            } else {
                out[base0]     = r0 + b0v;
                out[base1]     = r1 + b1v;
                out[base0 + 8] = r2 + b0v;
                out[base1 + 8] = r3 + b1v;
            }
        } else if (OMODE == 1) {
            float b0v = sbias[o0], b1v = sbias[o1];
            float bt0 = __ldg(beta + o0), bt1 = __ldg(beta + o1);
            out[base0]     = fmaf(r0 + b0v, bt0, __ldg(xres + base0));
            out[base1]     = fmaf(r1 + b1v, bt1, __ldg(xres + base1));
            out[base0 + 8] = fmaf(r2 + b0v, bt0, __ldg(xres + base0 + 8));
            out[base1 + 8] = fmaf(r3 + b1v, bt1, __ldg(xres + base1 + 8));
        } else {
            out[base0]     = r0 + __ldg(addsrc + base0);
            out[base1]     = r1 + __ldg(addsrc + base1);
            out[base0 + 8] = r2 + __ldg(addsrc + base0 + 8);
            out[base1 + 8] = r3 + __ldg(addsrc + base1 + 8);
        }
    }
}

// =====================================================================
// Fused conv4 (LN + 64->128) -> SimpleGate -> conv5 (64->64).
// =====================================================================
__global__ __launch_bounds__(256, 2) void k_tc45(
    const float* __restrict__ in, const float* __restrict__ w4,
    const float* __restrict__ b4, const float* __restrict__ lnw,
    const float* __restrict__ lnb,
    const float* __restrict__ w5, const float* __restrict__ b5,
    float* __restrict__ out)
{
    __shared__ __align__(16) float ABsm[64*APAD];
    __shared__ float sb4[128], sb5[64];

    int tid = threadIdx.x;
    int pix0 = blockIdx.x*128;
    int b = pix0 / HWSZ, hw0 = pix0 - b*HWSZ;
    if (tid < 128) sb4[tid] = __ldg(b4 + tid);
    if (tid < 64)  sb5[tid] = __ldg(b5 + tid);

    // stage A with channel-LN (eps 1e-6)
    {
        int p = tid >> 1, h = tid & 1;
        const float* src = in + (b*64 + h*32)*HWSZ + hw0 + p;
        float v[32];
#pragma unroll
        for (int c = 0; c < 32; c++) v[c] = src[c*HWSZ];
        float s = 0.f;
#pragma unroll
        for (int c = 0; c < 32; c++) s += v[c];
        s += __shfl_xor_sync(0xffffffffu, s, 1);
        float mu = s * (1.f/64.f);
        float q = 0.f;
#pragma unroll
        for (int c = 0; c < 32; c++) { float d = v[c]-mu; q += d*d; }
        q += __shfl_xor_sync(0xffffffffu, q, 1);
        float is = rsqrtf(q*(1.f/64.f) + 1e-6f);
#pragma unroll
        for (int c = 0; c < 32; c++) {
            int ch = h*32 + c;
            float val = (v[c]-mu)*is*__ldg(lnw+ch) + __ldg(lnb+ch);
            ABsm[ch*APAD + p] = __uint_as_float(cvt_tf32(val));
        }
    }
    __syncthreads();

    int warp = tid >> 5, lane = tid & 31, g = lane >> 2, tig = lane & 3;
    int pxA = warp*16 + g;
    unsigned afrag[8][4];
#pragma unroll
    for (int kt = 0; kt < 8; kt++) {
        int ca = kt*8 + tig;
        afrag[kt][0] = __float_as_uint(ABsm[ca*APAD + pxA]);
        afrag[kt][1] = __float_as_uint(ABsm[ca*APAD + pxA + 8]);
        afrag[kt][2] = __float_as_uint(ABsm[(ca+4)*APAD + pxA]);
        afrag[kt][3] = __float_as_uint(ABsm[(ca+4)*APAD + pxA + 8]);
    }
    __syncthreads();

    // stage B4 fragments (NT=16)
    for (int i = tid; i < 8192; i += 256) {
        int k = i & 63, oc = i >> 6;
        int kt = k >> 3, kk = k & 7, nt = oc >> 3, nn = oc & 7;
        unsigned v = cvt_tf32(__ldg(w4 + oc*64 + k));
        int idx = ((kt*8 + (nt>>1))*32 + nn*4 + (kk&3))*4 + ((nt&1)*2 + (kk>>2));
        ABsm[idx] = __uint_as_float(v);
    }
    __syncthreads();

    // MMA 1 (conv4, NT=16)
    float acc[16][4];
#pragma unroll
    for (int nt = 0; nt < 16; nt++)
#pragma unroll
        for (int u = 0; u < 4; u++) acc[nt][u] = 0.f;
#pragma unroll
    for (int kt = 0; kt < 8; kt++) {
#pragma unroll
        for (int np = 0; np < 8; np++) {
            float4 bb = *(const float4*)&ABsm[((kt*8 + np)*32 + lane)*4];
            mma8(acc[2*np],   afrag[kt][0], afrag[kt][1], afrag[kt][2], afrag[kt][3], bb.x, bb.y);
            mma8(acc[2*np+1], afrag[kt][0], afrag[kt][1], afrag[kt][2], afrag[kt][3], bb.z, bb.w);
        }
    }

    // SimpleGate in registers
    float gated[8][4];
#pragma unroll
    for (int nt = 0; nt < 8; nt++) {
        int o0 = nt*8 + 2*tig, o1 = o0 + 1;
        gated[nt][0] = (acc[nt][0] + sb4[o0]) * (acc[nt+8][0] + sb4[o0+64]);
        gated[nt][1] = (acc[nt][1] + sb4[o1]) * (acc[nt+8][1] + sb4[o1+64]);
        gated[nt][2] = (acc[nt][2] + sb4[o0]) * (acc[nt+8][2] + sb4[o0+64]);
        gated[nt][3] = (acc[nt][3] + sb4[o1]) * (acc[nt+8][3] + sb4[o1+64]);
    }
    __syncthreads();

    // route gated through smem as new A matrix [ch][px]
#pragma unroll
    for (int nt = 0; nt < 8; nt++) {
        int o0 = nt*8 + 2*tig, o1 = o0 + 1;
        ABsm[o0*APAD + pxA]     = __uint_as_float(cvt_tf32(gated[nt][0]));
        ABsm[o1*APAD + pxA]     = __uint_as_float(cvt_tf32(gated[nt][1]));
        ABsm[o0*APAD + pxA + 8] = __uint_as_float(cvt_tf32(gated[nt][2]));
        ABsm[o1*APAD + pxA + 8] = __uint_as_float(cvt_tf32(gated[nt][3]));
    }
    __syncthreads();

    unsigned af2[8][4];
#pragma unroll
    for (int kt = 0; kt < 8; kt++) {
        int ca = kt*8 + tig;
        af2[kt][0] = __float_as_uint(ABsm[ca*APAD + pxA]);
        af2[kt][1] = __float_as_uint(ABsm[ca*APAD + pxA + 8]);
        af2[kt][2] = __float_as_uint(ABsm[(ca+4)*APAD + pxA]);
        af2[kt][3] = __float_as_uint(ABsm[(ca+4)*APAD + pxA + 8]);
    }
    __syncthreads();

    // stage B5 fragments (NT=8)
    for (int i = tid; i < 4096; i += 256) {
        int k = i & 63, oc = i >> 6;
        int kt = k >> 3, kk = k & 7, nt = oc >> 3, nn = oc & 7;
        unsigned v = cvt_tf32(__ldg(w5 + oc*64 + k));
        int idx = ((kt*4 + (nt>>1))*32 + nn*4 + (kk&3))*4 + ((nt&1)*2 + (kk>>2));
        ABsm[idx] = __uint_as_float(v);
    }
    __syncthreads();

    // MMA 2 (conv5, NT=8)
    float a5[8][4];
#pragma unroll
    for (int nt = 0; nt < 8; nt++)
#pragma unroll
        for (int u = 0; u < 4; u++) a5[nt][u] = 0.f;
#pragma unroll
    for (int kt = 0; kt < 8; kt++) {
#pragma unroll
        for (int np = 0; np < 4; np++) {
            float4 bb = *(const float4*)&ABsm[((kt*4 + np)*32 + lane)*4];
            mma8(a5[2*np],   af2[kt][0], af2[kt][1], af2[kt][2], af2[kt][3], bb.x, bb.y);
            mma8(a5[2*np+1], af2[kt][0], af2[kt][1], af2[kt][2], af2[kt][3], bb.z, bb.w);
        }
    }

    int pxg = hw0 + warp*16 + g;
#pragma unroll
    for (int nt = 0; nt < 8; nt++) {
        int o0 = nt*8 + 2*tig, o1 = o0 + 1;
        int base0 = (b*64 + o0)*HWSZ + pxg;
        int base1 = (b*64 + o1)*HWSZ + pxg;
        out[base0]     = a5[nt][0] + sb5[o0];
        out[base1]     = a5[nt][1] + sb5[o1];
        out[base0 + 8] = a5[nt][2] + sb5[o0];
        out[base1 + 8] = a5[nt][3] + sb5[o1];
    }
}

// ---------------- depthwise 3x3 (+bias) bf16 in/out, InstanceNorm stats ----------------
__global__ __launch_bounds__(256) void k_dw_stats(
    const bf16* __restrict__ in, const float* __restrict__ w,
    const float* __restrict__ bias, bf16* __restrict__ out)
{
    int bc = blockIdx.z;
    int c = bc & 127, b = bc >> 7;
    __shared__ float tile[10][34];
    __shared__ float redS[256], redQ[256];
    int tx0 = blockIdx.x*32, ty0 = blockIdx.y*8;
    int tid = threadIdx.y*32 + threadIdx.x;
    const bf16* src = in + (size_t)bc*HWSZ;
    for (int i = tid; i < 340; i += 256) {
        int r = i/34, cc = i - r*34;
        int gy = ty0 + r - 1, gx = tx0 + cc - 1;
        tile[r][cc] = (gy >= 0 && gy < HH && gx >= 0 && gx < WWID)
                      ? __bfloat162float(src[gy*WWID+gx]) : 0.f;
    }
    __syncthreads();
    float acc = bias[c];
#pragma unroll
    for (int di = 0; di < 3; di++)
#pragma unroll
        for (int dj = 0; dj < 3; dj++)
            acc += w[c*9 + di*3 + dj] * tile[threadIdx.y+di][threadIdx.x+dj];
    out[(size_t)bc*HWSZ + (ty0+threadIdx.y)*WWID + tx0 + threadIdx.x] = __float2bfloat16(acc);

    if (c < 64) {
        redS[tid] = acc; redQ[tid] = acc*acc;
        __syncthreads();
        for (int s = 128; s > 0; s >>= 1) {
            if (tid < s) { redS[tid] += redS[tid+s]; redQ[tid] += redQ[tid+s]; }
            __syncthreads();
        }
        if (tid == 0) {
            atomicAdd(&g_instS[b*64 + c], redS[0]);
            atomicAdd(&g_instQ[b*64 + c], redQ[0]);
        }
    }
}

__global__ void k_instfin() {
    int t = blockIdx.x*blockDim.x + threadIdx.x;
    if (t < BB*CCH) {
        float m = g_instS[t] * (1.f/HWSZ);
        float v = g_instQ[t] * (1.f/HWSZ) - m*m;
        g_instMean[t] = m;
        g_instInv[t]  = rsqrtf(v + 1e-5f);
    }
}

// ---------------- SCA pooling only (no t3 store), bf16 input ----------------
__global__ __launch_bounds__(256) void k_sca_pool(
    const bf16* __restrict__ buf, const float* __restrict__ inw,
    const float* __restrict__ inb)
{
    int bc = blockIdx.y;
    int c = bc & 63, b = bc >> 6;
    int i4 = blockIdx.x*256 + threadIdx.x;          // quad index < 12544
    const __nv_bfloat162* A2 = (const __nv_bfloat162*)(buf + (size_t)(b*128 + c)*HWSZ);
    const __nv_bfloat162* G2 = (const __nv_bfloat162*)(buf + (size_t)(b*128 + 64 + c)*HWSZ);
    float m = g_instMean[bc], iv = g_instInv[bc];
    float sw = inw[c], sb = inb[c];
    float2 a0 = __bfloat1622float2(A2[i4*2]);
    float2 a1 = __bfloat1622float2(A2[i4*2+1]);
    float2 g0 = __bfloat1622float2(G2[i4*2]);
    float2 g1 = __bfloat1622float2(G2[i4*2+1]);
    float t0 = ((a0.x - m)*iv*sw + sb) * g0.x;
    float t1 = ((a0.y - m)*iv*sw + sb) * g0.y;
    float t2 = ((a1.x - m)*iv*sw + sb) * g1.x;
    float t3 = ((a1.y - m)*iv*sw + sb) * g1.y;
    int gy = i4 / 56, gx4 = i4 - gy*56;
    float ws = (t0 + t1 + t2 + t3) * g_dctR[c*56 + (gy >> 2)] * g_dctC[c*56 + gx4];
    __shared__ float red[256];
    red[threadIdx.x] = ws; __syncthreads();
    for (int s = 128; s > 0; s >>= 1) {
        if (threadIdx.x < s) red[threadIdx.x] += red[threadIdx.x+s];
        __syncthreads();
    }
    if (threadIdx.x == 0) atomicAdd(&g_scay[bc], red[0]);
}

__global__ void k_se(const float* __restrict__ fc1, const float* __restrict__ fc2) {
    int b = blockIdx.x, c = threadIdx.x;
    __shared__ float ys[64];
    ys[c] = g_scay[b*64 + c] * (1.f/16.f);
    __syncthreads();
    float h[4];
#pragma unroll
    for (int j = 0; j < 4; j++) {
        float s = 0.f;
#pragma unroll
        for (int k = 0; k < 64; k++) s += fc1[j*64 + k] * ys[k];
        h[j] = fmaxf(s, 0.f);
    }
    float z = 0.f;
#pragma unroll
    for (int j = 0; j < 4; j++) z += fc2[c*4 + j] * h[j];
    g_z[b*64 + c] = 1.f / (1.f + expf(-z));
}

// ---------------- per-patch spectral transform, in-place on g_buf2a ----------------
__global__ __launch_bounds__(128) void k_fftapply_rb() {
    if (g_fftNonId == 0) return;
    int bc = blockIdx.x;
    int c  = bc & 127;
    __shared__ __align__(16) float Ms[4096];
    __shared__ __align__(16) float pat[64*60];
    int tid = threadIdx.x;
    const float* msrc = g_M + c*4096;
    for (int i = tid; i < 4096; i += 128) Ms[i] = msrc[i];
    float* plane = g_buf2a + (size_t)bc*HWSZ;
    int og = tid & 15, pg = tid >> 4;
    for (int bp = 0; bp < 14; bp++) {
        for (int i = tid; i < 3584; i += 128) {
            int r = i / 224, wcol = i - r*224;
            int p = r & 7, band = r >> 3, pc = wcol >> 3, q = wcol & 7;
            pat[(p*8+q)*60 + band*28 + pc] = plane[(bp*16 + r)*224 + wcol];
        }
        __syncthreads();
        ull acc[4][4];
#pragma unroll
        for (int j = 0; j < 4; j++)
#pragma unroll
            for (int u = 0; u < 4; u++) acc[j][u] = 0ULL;
        if (pg < 7) {
            const float* pI = pat + pg*8;
            for (int k = 0; k < 64; k++) {
                ulonglong2 va = *(const ulonglong2*)(pI + k*60);
                ulonglong2 vb = *(const ulonglong2*)(pI + k*60 + 4);
                float4 wv = *(const float4*)(Ms + k*64 + og*4);
                float wav[4] = {wv.x, wv.y, wv.z, wv.w};
#pragma unroll
                for (int j = 0; j < 4; j++) {
                    ull wp = pack2(wav[j]);
                    acc[j][0] = fma2(va.x, wp, acc[j][0]);
                    acc[j][1] = fma2(va.y, wp, acc[j][1]);
                    acc[j][2] = fma2(vb.x, wp, acc[j][2]);
                    acc[j][3] = fma2(vb.y, wp, acc[j][3]);
                }
            }
        }
        __syncthreads();
        if (pg < 7) {
#pragma unroll
            for (int j = 0; j < 4; j++) {
                int o = og*4 + j;
                ulonglong2 s0, s1;
                s0.x = acc[j][0]; s0.y = acc[j][1];
                s1.x = acc[j][2]; s1.y = acc[j][3];
                *(ulonglong2*)(pat + o*60 + pg*8) = s0;
                *(ulonglong2*)(pat + o*60 + pg*8 + 4) = s1;
            }
        }
        __syncthreads();
        for (int i = tid; i < 3584; i += 128) {
            int r = i / 224, wcol = i - r*224;
            int p = r & 7, band = r >> 3, pc = wcol >> 3, q = wcol & 7;
            plane[(bp*16 + r)*224 + wcol] = pat[(p*8+q)*60 + band*28 + pc];
        }
        __syncthreads();
    }
}

// ---------------- DFFN depthwise 3x3 pair + gelu gate ----------------
__global__ __launch_bounds__(256) void k_dw_gelu(const float* __restrict__ w) {
    int bc = blockIdx.z;
    int c = bc & 63, b = bc >> 6;
    __shared__ float t1[10][34], t2[10][34];
    int tx0 = blockIdx.x*32, ty0 = blockIdx.y*8;
    int tid = threadIdx.y*32 + threadIdx.x;
    const float* s1 = g_buf2a + (size_t)(b*128 + c)*HWSZ;
    const float* s2 = g_buf2a + (size_t)(b*128 + 64 + c)*HWSZ;
    for (int i = tid; i < 340; i += 256) {
        int r = i/34, cc = i - r*34;
        int gy = ty0 + r - 1, gx = tx0 + cc - 1;
        bool ok = (gy >= 0 && gy < HH && gx >= 0 && gx < WWID);
        t1[r][cc] = ok ? s1[gy*WWID+gx] : 0.f;
        t2[r][cc] = ok ? s2[gy*WWID+gx] : 0.f;
    }
    __syncthreads();
    float d1 = 0.f, d2 = 0.f;
#pragma unroll
    for (int di = 0; di < 3; di++)
#pragma unroll
        for (int dj = 0; dj < 3; dj++) {
            d1 += w[c*9 + di*3 + dj]      * t1[threadIdx.y+di][threadIdx.x+dj];
            d2 += w[(64+c)*9 + di*3 + dj] * t2[threadIdx.y+di][threadIdx.x+dj];
        }
    float gel = 0.5f * d1 * (1.f + erff(d1 * 0.70710678118f));
    g_bufc[(size_t)bc*HWSZ + (ty0+threadIdx.y)*WWID + tx0 + threadIdx.x] = gel * d2;
}

// ---------------- launch ----------------
extern "C" void kernel_launch(void* const* d_in, const int* in_sizes, int n_in,
                              void* d_out, int out_size)
{
    (void)in_sizes; (void)n_in; (void)out_size;
    const float* x       = (const float*)d_in[0];
    const float* n1_w    = (const float*)d_in[1];
    const float* n1_b    = (const float*)d_in[2];
    const float* conv1_w = (const float*)d_in[3];
    const float* conv1_b = (const float*)d_in[4];
    const float* conv2_w = (const float*)d_in[5];
    const float* conv2_b = (const float*)d_in[6];
    const float* in_w    = (const float*)d_in[7];
    const float* in_b    = (const float*)d_in[8];
    const float* fc1_w   = (const float*)d_in[9];
    const float* fc2_w   = (const float*)d_in[10];
    const float* conv3_w = (const float*)d_in[11];
    const float* conv3_b = (const float*)d_in[12];
    const float* beta    = (const float*)d_in[13];
    const float* n2n_w   = (const float*)d_in[14];
    const float* n2n_b   = (const float*)d_in[15];
    const float* conv4_w = (const float*)d_in[16];
    const float* conv4_b = (const float*)d_in[17];
    const float* conv5_w = (const float*)d_in[18];
    const float* conv5_b = (const float*)d_in[19];
    const float* ln_w    = (const float*)d_in[20];
    const float* ln_b    = (const float*)d_in[21];
    const float* pin_w   = (const float*)d_in[22];
    const float* dw_w    = (const float*)d_in[23];
    const float* fft_w   = (const float*)d_in[24];
    const float* pout_w  = (const float*)d_in[25];

    float *t2a, *t2b, *tc, *ty;
    cudaGetSymbolAddress((void**)&t2a, g_buf2a);
    cudaGetSymbolAddress((void**)&t2b, g_buf2b);
    cudaGetSymbolAddress((void**)&tc,  g_bufc);
    cudaGetSymbolAddress((void**)&ty,  g_y);

    // carve two bf16 buffers out of g_buf2b (205.5MB >= 2 x 102.8MB)
    bf16* c1bf = (bf16*)t2b;                          // conv1 output [b,128,HW]
    bf16* dwbf = c1bf + (size_t)BB*C2*HWSZ;           // dw output    [b,128,HW]

    const int GB = NPIX / 128;     // 3136 blocks (128 px each)

    k_zero<<<1, 512>>>();
    k_tables<<<28, 128>>>();
    k_fftmat<<<64, 128>>>(fft_w);

    // conv1: LN(n1) + 64->128 + bias  -> bf16
    k_tc<16,1,0,1><<<GB, 256>>>(x, conv1_w, conv1_b, n1_w, n1_b, 1e-6f,
                                nullptr, nullptr, nullptr, (float*)c1bf, 128);

    // depthwise 3x3 + conv2 bias (bf16 in/out), InstanceNorm stats
    {
        dim3 g(7, 28, BB*C2), blk(32, 8);
        k_dw_stats<<<g, blk>>>(c1bf, conv2_w, conv2_b, dwbf);
    }
    k_instfin<<<4, 128>>>();

    // DCT-weighted SCA pooling (reduce only)
    {
        dim3 g(HWSZ/(4*256), BB*CCH);
        k_sca_pool<<<g, 256>>>(dwbf, in_w, in_b);
    }
    k_se<<<BB, 64>>>(fc1_w, fc2_w);

    // conv3 with inline instnorm-gate-z staging + residual -> g_buf2a (fp32)
    k_tc<8,4,1,0><<<GB, 256>>>((const float*)dwbf, conv3_w, conv3_b, in_w, in_b, 0.f,
                               x, beta, nullptr, t2a, 64);
    // fused conv4 + SimpleGate + conv5 -> y
    k_tc45<<<GB, 256>>>(t2a, conv4_w, conv4_b, n2n_w, n2n_b,
                        conv5_w, conv5_b, ty);

    // DFFN: LN + pin (64->128) -> g_buf2a (in-place fft target)
    k_tc<16,1,0,0><<<GB, 256>>>(ty, pin_w, nullptr, ln_w, ln_b, 1e-5f,
                                nullptr, nullptr, nullptr, t2a, 128);
    // patch spectral transform in-place (skips when identity)
    k_fftapply_rb<<<BB*C2, 128>>>();
    // depthwise pair + gelu gate -> g_bufc
    {
        dim3 g(7, 28, BB*CCH), blk(32, 8);
        k_dw_gelu<<<g, blk>>>(dw_w);
    }
    // pout + y -> d_out
    k_tc<8,0,2,0><<<GB, 256>>>(tc, pout_w, nullptr, nullptr, nullptr, 0.f,
                               nullptr, nullptr, ty, (float*)d_out, 64);
}

// round 13
// speedup vs baseline: 1.4278x; 1.0957x over previous
#include <cuda_runtime.h>
#include <cuda_bf16.h>
#include <cuda_fp16.h>
#include <math.h>

#define BB    8
#define CCH   64
#define C2    128
#define HH    224
#define WWID  224
#define HWSZ  (HH*WWID)          // 50176
#define NPIX  (BB*HWSZ)          // 401408

typedef unsigned long long ull;
typedef __nv_bfloat16 bf16;
typedef __half fp16;

// ---------------- packed f32x2 helpers (used by fftapply) ----------------
__device__ __forceinline__ ull pack2(float x) {
    ull r; asm("mov.b64 %0, {%1, %1};" : "=l"(r) : "f"(x)); return r;
}
__device__ __forceinline__ ull fma2(ull a, ull b, ull c) {
    ull d; asm("fma.rn.f32x2 %0, %1, %2, %3;" : "=l"(d) : "l"(a), "l"(b), "l"(c)); return d;
}

// ---------------- tf32 mma helpers ----------------
__device__ __forceinline__ unsigned cvt_tf32(float f) {
    unsigned u; asm("cvt.rna.tf32.f32 %0, %1;" : "=r"(u) : "f"(f)); return u;
}
__device__ __forceinline__ void mma8(float* c, unsigned a0, unsigned a1,
                                     unsigned a2, unsigned a3, float bx, float by) {
    unsigned b0 = __float_as_uint(bx), b1 = __float_as_uint(by);
    asm("mma.sync.aligned.m16n8k8.row.col.f32.tf32.tf32.f32 "
        "{%0,%1,%2,%3}, {%4,%5,%6,%7}, {%8,%9}, {%0,%1,%2,%3};"
        : "+f"(c[0]), "+f"(c[1]), "+f"(c[2]), "+f"(c[3])
        : "r"(a0), "r"(a1), "r"(a2), "r"(a3), "r"(b0), "r"(b1));
}

// ---------------- scratch (device globals; no allocation allowed) ----------------
static __device__ float g_buf2a[BB*C2*HWSZ];   // fp32 residual / fp16 pin-out+fft
static __device__ float g_buf2b[BB*C2*HWSZ];   // carved: 2 bf16 buffers (conv1out, dwout)
static __device__ float g_bufc [BB*CCH*HWSZ];  // carved: fp16 dffn gelu-gated
static __device__ float g_y    [BB*CCH*HWSZ];  // fp32: NAF output y
static __device__ float g_M    [C2*64*64];     // [c][in][out]
static __device__ float g_dctR [CCH*56];
static __device__ float g_dctC [CCH*56];
static __device__ float g_instS[BB*CCH], g_instQ[BB*CCH];
static __device__ float g_instMean[BB*CCH], g_instInv[BB*CCH];
static __device__ float g_scay[BB*CCH], g_scay2[BB*CCH], g_z[BB*CCH];
static __device__ int   g_fftNonId;

// ---------------- tiny init kernels ----------------
__global__ void k_zero() {
    int t = threadIdx.x;
    if (t < BB*CCH) {
        g_instS[t] = 0.f; g_instQ[t] = 0.f;
        g_scay[t] = 0.f;  g_scay2[t] = 0.f;
    }
    if (t == 0) g_fftNonId = 0;
}

__global__ void k_tables() {
    int t = blockIdx.x * blockDim.x + threadIdx.x;
    if (t >= CCH*56) return;
    int c = t / 56, i = t - c*56;
    const int mx[16] = {0,0,6,0,0,1,1,4,5,1,3,0,0,0,3,2};
    const int my[16] = {0,1,0,5,2,0,2,0,0,6,0,4,6,3,2,5};
    int g = c >> 2;
    int ux = mx[g]*8, uy = my[g]*8;
    float inv = rsqrtf(56.f);
    float rv = cosf((float)M_PI * ux * (i + 0.5f) / 56.f) * inv;
    if (ux) rv *= 1.41421356237f;
    float cv = cosf((float)M_PI * uy * (i + 0.5f) / 56.f) * inv;
    if (uy) cv *= 1.41421356237f;
    g_dctR[t] = rv; g_dctC[t] = cv;
}

__global__ void k_fftmat(const float* __restrict__ fw) {
    int t = blockIdx.x * blockDim.x + threadIdx.x;
    if (t >= C2*64) return;
    int c = t >> 6, in = t & 63, i0 = in >> 3, j0 = in & 7;
    const float c8[8] = {1.f, 0.70710678118f, 0.f, -0.70710678118f,
                         -1.f, -0.70710678118f, 0.f, 0.70710678118f};
    const float s8[8] = {0.f, 0.70710678118f, 1.f, 0.70710678118f,
                         0.f, -0.70710678118f, -1.f, -0.70710678118f};
    int dev = 0;
    for (int p = 0; p < 8; p++) {
        float Gr[5], Gi[5];
        for (int v = 0; v < 5; v++) {
            float gr = 0.f, gi = 0.f;
            for (int u = 0; u < 8; u++) {
                int idx = ((u*(p - i0) - v*j0) % 8 + 8) % 8;
                float w = fw[c*40 + u*5 + v];
                gr += w * c8[idx]; gi += w * s8[idx];
            }
            Gr[v] = gr; Gi[v] = gi;
        }
        for (int q = 0; q < 8; q++) {
            float val = Gr[0] + ((q & 1) ? -Gr[4] : Gr[4]);
            for (int v = 1; v < 4; v++) {
                int k = (v*q) & 7;
                val += 2.f * (Gr[v]*c8[k] - Gi[v]*s8[k]);
            }
            val *= (1.f/64.f);
            int outp = p*8 + q;
            g_M[c*4096 + in*64 + outp] = val;
            float expect = (outp == in) ? 1.f : 0.f;
            if (fabsf(val - expect) > 1e-5f) dev = 1;
        }
    }
    if (dev) g_fftNonId = 1;
}

// =====================================================================
// Tensor-core conv1x1 GEMM.  128 px x (NT*8) oc per block, K=64, tf32 mma.
// IMODE: 0 plain f32, 1 channel-LN f32, 4 instnorm-gate bf16, 5 plain fp16
// OMODE: 0 acc+bias, 1 x + beta*(acc+bias), 2 acc+add
// OBF:   0 f32 out, 1 bf16 out, 2 fp16 out   (OMODE 0 only)
// =====================================================================
#define APAD 136

template<int NT, int IMODE, int OMODE, int OBF>
__global__ __launch_bounds__(256, 2) void k_tc(
    const float* __restrict__ in, const float* __restrict__ w,
    const float* __restrict__ bias, const float* __restrict__ lnw,
    const float* __restrict__ lnb, float eps,
    const float* __restrict__ xres, const float* __restrict__ beta,
    const float* __restrict__ addsrc, float* __restrict__ out, int ocStride)
{
    constexpr int NOC = NT*8;
    __shared__ __align__(16) float ABsm[64*APAD];
    __shared__ float sbias[128];
    __shared__ float sAZ[64], sBZ[64];

    int tid = threadIdx.x;
    int pix0 = blockIdx.x*128;
    int b = pix0 / HWSZ, hw0 = pix0 - b*HWSZ;

    if (tid < NOC) sbias[tid] = bias ? __ldg(bias + tid) : 0.f;

    // ---- phase 1: stage A ----
    if (IMODE == 1) {
        int p = tid >> 1, h = tid & 1;
        const float* src = in + (b*64 + h*32)*HWSZ + hw0 + p;
        float v[32];
#pragma unroll
        for (int c = 0; c < 32; c++) v[c] = src[c*HWSZ];
        float s = 0.f;
#pragma unroll
        for (int c = 0; c < 32; c++) s += v[c];
        s += __shfl_xor_sync(0xffffffffu, s, 1);
        float mu = s * (1.f/64.f);
        float q = 0.f;
#pragma unroll
        for (int c = 0; c < 32; c++) { float d = v[c]-mu; q += d*d; }
        q += __shfl_xor_sync(0xffffffffu, q, 1);
        float is = rsqrtf(q*(1.f/64.f) + eps);
#pragma unroll
        for (int c = 0; c < 32; c++) {
            int ch = h*32 + c;
            float val = (v[c]-mu)*is*__ldg(lnw+ch) + __ldg(lnb+ch);
            ABsm[ch*APAD + p] = __uint_as_float(cvt_tf32(val));
        }
    } else if (IMODE == 4) {
        // t3*z = (a*AZ + BZ)*g  from bf16 dw-output planes
        if (tid < 64) {
            int bc = b*64 + tid;
            float iv = g_instInv[bc];
            float A  = iv*__ldg(lnw + tid);
            float z  = g_z[bc];
            sAZ[tid] = A*z;
            sBZ[tid] = (__ldg(lnb + tid) - g_instMean[bc]*A)*z;
        }
        __syncthreads();
        const bf16* inb16 = (const bf16*)in;
        for (int i = tid; i < 8192; i += 256) {
            int px = i & 127, c = i >> 7;
            float a  = __bfloat162float(inb16[(size_t)(b*128 + c)*HWSZ + hw0 + px]);
            float gg = __bfloat162float(inb16[(size_t)(b*128 + 64 + c)*HWSZ + hw0 + px]);
            float val = (a*sAZ[c] + sBZ[c])*gg;
            ABsm[c*APAD + px] = __uint_as_float(cvt_tf32(val));
        }
    } else if (IMODE == 5) {
        const fp16* inh = (const fp16*)in;
        for (int i = tid; i < 8192; i += 256) {
            int px = i & 127, c = i >> 7;
            float val = __half2float(inh[(size_t)(b*64 + c)*HWSZ + hw0 + px]);
            ABsm[c*APAD + px] = __uint_as_float(cvt_tf32(val));
        }
    } else {
        for (int i = tid; i < 8192; i += 256) {
            int px = i & 127, c = i >> 7;
            float val = in[(b*64 + c)*HWSZ + hw0 + px];
            ABsm[c*APAD + px] = __uint_as_float(cvt_tf32(val));
        }
    }
    __syncthreads();

    // ---- phase 2: A fragments to regs ----
    int warp = tid >> 5, lane = tid & 31, g = lane >> 2, tig = lane & 3;
    int pxA = warp*16 + g;
    unsigned afrag[8][4];
#pragma unroll
    for (int kt = 0; kt < 8; kt++) {
        int ca = kt*8 + tig;
        afrag[kt][0] = __float_as_uint(ABsm[ca*APAD + pxA]);
        afrag[kt][1] = __float_as_uint(ABsm[ca*APAD + pxA + 8]);
        afrag[kt][2] = __float_as_uint(ABsm[(ca+4)*APAD + pxA]);
        afrag[kt][3] = __float_as_uint(ABsm[(ca+4)*APAD + pxA + 8]);
    }
    __syncthreads();

    // ---- phase 3: stage B fragments ----
    for (int i = tid; i < NOC*64; i += 256) {
        int k = i & 63, oc = i >> 6;
        int kt = k >> 3, kk = k & 7, nt = oc >> 3, nn = oc & 7;
        unsigned v = cvt_tf32(__ldg(w + oc*64 + k));
        int idx = ((kt*(NT/2) + (nt>>1))*32 + nn*4 + (kk&3))*4 + ((nt&1)*2 + (kk>>2));
        ABsm[idx] = __uint_as_float(v);
    }
    __syncthreads();

    // ---- phase 4: MMA mainloop ----
    float acc[NT][4];
#pragma unroll
    for (int nt = 0; nt < NT; nt++)
#pragma unroll
        for (int u = 0; u < 4; u++) acc[nt][u] = 0.f;

#pragma unroll
    for (int kt = 0; kt < 8; kt++) {
#pragma unroll
        for (int np = 0; np < NT/2; np++) {
            float4 bb = *(const float4*)&ABsm[((kt*(NT/2) + np)*32 + lane)*4];
            mma8(acc[2*np],   afrag[kt][0], afrag[kt][1], afrag[kt][2], afrag[kt][3], bb.x, bb.y);
            mma8(acc[2*np+1], afrag[kt][0], afrag[kt][1], afrag[kt][2], afrag[kt][3], bb.z, bb.w);
        }
    }

    // ---- epilogue (scattered) ----
    int pxg = hw0 + warp*16 + g;
#pragma unroll
    for (int nt = 0; nt < NT; nt++) {
        int o0 = nt*8 + 2*tig, o1 = o0 + 1;
        size_t base0 = (size_t)(b*ocStride + o0)*HWSZ + pxg;
        size_t base1 = (size_t)(b*ocStride + o1)*HWSZ + pxg;
        float r0 = acc[nt][0], r1 = acc[nt][1], r2 = acc[nt][2], r3 = acc[nt][3];
        if (OMODE == 0) {
            float b0v = sbias[o0], b1v = sbias[o1];
            if (OBF == 1) {
                bf16* ob = (bf16*)out;
                ob[base0]     = __float2bfloat16(r0 + b0v);
                ob[base1]     = __float2bfloat16(r1 + b1v);
                ob[base0 + 8] = __float2bfloat16(r2 + b0v);
                ob[base1 + 8] = __float2bfloat16(r3 + b1v);
            } else if (OBF == 2) {
                fp16* oh = (fp16*)out;
                oh[base0]     = __float2half(r0 + b0v);
                oh[base1]     = __float2half(r1 + b1v);
                oh[base0 + 8] = __float2half(r2 + b0v);
                oh[base1 + 8] = __float2half(r3 + b1v);
            } else {
                out[base0]     = r0 + b0v;
                out[base1]     = r1 + b1v;
                out[base0 + 8] = r2 + b0v;
                out[base1 + 8] = r3 + b1v;
            }
        } else if (OMODE == 1) {
            float b0v = sbias[o0], b1v = sbias[o1];
            float bt0 = __ldg(beta + o0), bt1 = __ldg(beta + o1);
            out[base0]     = fmaf(r0 + b0v, bt0, __ldg(xres + base0));
            out[base1]     = fmaf(r1 + b1v, bt1, __ldg(xres + base1));
            out[base0 + 8] = fmaf(r2 + b0v, bt0, __ldg(xres + base0 + 8));
            out[base1 + 8] = fmaf(r3 + b1v, bt1, __ldg(xres + base1 + 8));
        } else {
            out[base0]     = r0 + __ldg(addsrc + base0);
            out[base1]     = r1 + __ldg(addsrc + base1);
            out[base0 + 8] = r2 + __ldg(addsrc + base0 + 8);
            out[base1 + 8] = r3 + __ldg(addsrc + base1 + 8);
        }
    }
}

// =====================================================================
// Fused conv4 (LN + 64->128) -> SimpleGate -> conv5 (64->64).
// =====================================================================
__global__ __launch_bounds__(256, 2) void k_tc45(
    const float* __restrict__ in, const float* __restrict__ w4,
    const float* __restrict__ b4, const float* __restrict__ lnw,
    const float* __restrict__ lnb,
    const float* __restrict__ w5, const float* __restrict__ b5,
    float* __restrict__ out)
{
    __shared__ __align__(16) float ABsm[64*APAD];
    __shared__ float sb4[128], sb5[64];

    int tid = threadIdx.x;
    int pix0 = blockIdx.x*128;
    int b = pix0 / HWSZ, hw0 = pix0 - b*HWSZ;
    if (tid < 128) sb4[tid] = __ldg(b4 + tid);
    if (tid < 64)  sb5[tid] = __ldg(b5 + tid);

    // stage A with channel-LN (eps 1e-6)
    {
        int p = tid >> 1, h = tid & 1;
        const float* src = in + (b*64 + h*32)*HWSZ + hw0 + p;
        float v[32];
#pragma unroll
        for (int c = 0; c < 32; c++) v[c] = src[c*HWSZ];
        float s = 0.f;
#pragma unroll
        for (int c = 0; c < 32; c++) s += v[c];
        s += __shfl_xor_sync(0xffffffffu, s, 1);
        float mu = s * (1.f/64.f);
        float q = 0.f;
#pragma unroll
        for (int c = 0; c < 32; c++) { float d = v[c]-mu; q += d*d; }
        q += __shfl_xor_sync(0xffffffffu, q, 1);
        float is = rsqrtf(q*(1.f/64.f) + 1e-6f);
#pragma unroll
        for (int c = 0; c < 32; c++) {
            int ch = h*32 + c;
            float val = (v[c]-mu)*is*__ldg(lnw+ch) + __ldg(lnb+ch);
            ABsm[ch*APAD + p] = __uint_as_float(cvt_tf32(val));
        }
    }
    __syncthreads();

    int warp = tid >> 5, lane = tid & 31, g = lane >> 2, tig = lane & 3;
    int pxA = warp*16 + g;
    unsigned afrag[8][4];
#pragma unroll
    for (int kt = 0; kt < 8; kt++) {
        int ca = kt*8 + tig;
        afrag[kt][0] = __float_as_uint(ABsm[ca*APAD + pxA]);
        afrag[kt][1] = __float_as_uint(ABsm[ca*APAD + pxA + 8]);
        afrag[kt][2] = __float_as_uint(ABsm[(ca+4)*APAD + pxA]);
        afrag[kt][3] = __float_as_uint(ABsm[(ca+4)*APAD + pxA + 8]);
    }
    __syncthreads();

    // stage B4 fragments (NT=16)
    for (int i = tid; i < 8192; i += 256) {
        int k = i & 63, oc = i >> 6;
        int kt = k >> 3, kk = k & 7, nt = oc >> 3, nn = oc & 7;
        unsigned v = cvt_tf32(__ldg(w4 + oc*64 + k));
        int idx = ((kt*8 + (nt>>1))*32 + nn*4 + (kk&3))*4 + ((nt&1)*2 + (kk>>2));
        ABsm[idx] = __uint_as_float(v);
    }
    __syncthreads();

    // MMA 1 (conv4, NT=16)
    float acc[16][4];
#pragma unroll
    for (int nt = 0; nt < 16; nt++)
#pragma unroll
        for (int u = 0; u < 4; u++) acc[nt][u] = 0.f;
#pragma unroll
    for (int kt = 0; kt < 8; kt++) {
#pragma unroll
        for (int np = 0; np < 8; np++) {
            float4 bb = *(const float4*)&ABsm[((kt*8 + np)*32 + lane)*4];
            mma8(acc[2*np],   afrag[kt][0], afrag[kt][1], afrag[kt][2], afrag[kt][3], bb.x, bb.y);
            mma8(acc[2*np+1], afrag[kt][0], afrag[kt][1], afrag[kt][2], afrag[kt][3], bb.z, bb.w);
        }
    }

    // SimpleGate in registers
    float gated[8][4];
#pragma unroll
    for (int nt = 0; nt < 8; nt++) {
        int o0 = nt*8 + 2*tig, o1 = o0 + 1;
        gated[nt][0] = (acc[nt][0] + sb4[o0]) * (acc[nt+8][0] + sb4[o0+64]);
        gated[nt][1] = (acc[nt][1] + sb4[o1]) * (acc[nt+8][1] + sb4[o1+64]);
        gated[nt][2] = (acc[nt][2] + sb4[o0]) * (acc[nt+8][2] + sb4[o0+64]);
        gated[nt][3] = (acc[nt][3] + sb4[o1]) * (acc[nt+8][3] + sb4[o1+64]);
    }
    __syncthreads();

    // route gated through smem as new A matrix [ch][px]
#pragma unroll
    for (int nt = 0; nt < 8; nt++) {
        int o0 = nt*8 + 2*tig, o1 = o0 + 1;
        ABsm[o0*APAD + pxA]     = __uint_as_float(cvt_tf32(gated[nt][0]));
        ABsm[o1*APAD + pxA]     = __uint_as_float(cvt_tf32(gated[nt][1]));
        ABsm[o0*APAD + pxA + 8] = __uint_as_float(cvt_tf32(gated[nt][2]));
        ABsm[o1*APAD + pxA + 8] = __uint_as_float(cvt_tf32(gated[nt][3]));
    }
    __syncthreads();

    unsigned af2[8][4];
#pragma unroll
    for (int kt = 0; kt < 8; kt++) {
        int ca = kt*8 + tig;
        af2[kt][0] = __float_as_uint(ABsm[ca*APAD + pxA]);
        af2[kt][1] = __float_as_uint(ABsm[ca*APAD + pxA + 8]);
        af2[kt][2] = __float_as_uint(ABsm[(ca+4)*APAD + pxA]);
        af2[kt][3] = __float_as_uint(ABsm[(ca+4)*APAD + pxA + 8]);
    }
    __syncthreads();

    // stage B5 fragments (NT=8)
    for (int i = tid; i < 4096; i += 256) {
        int k = i & 63, oc = i >> 6;
        int kt = k >> 3, kk = k & 7, nt = oc >> 3, nn = oc & 7;
        unsigned v = cvt_tf32(__ldg(w5 + oc*64 + k));
        int idx = ((kt*4 + (nt>>1))*32 + nn*4 + (kk&3))*4 + ((nt&1)*2 + (kk>>2));
        ABsm[idx] = __uint_as_float(v);
    }
    __syncthreads();

    // MMA 2 (conv5, NT=8)
    float a5[8][4];
#pragma unroll
    for (int nt = 0; nt < 8; nt++)
#pragma unroll
        for (int u = 0; u < 4; u++) a5[nt][u] = 0.f;
#pragma unroll
    for (int kt = 0; kt < 8; kt++) {
#pragma unroll
        for (int np = 0; np < 4; np++) {
            float4 bb = *(const float4*)&ABsm[((kt*4 + np)*32 + lane)*4];
            mma8(a5[2*np],   af2[kt][0], af2[kt][1], af2[kt][2], af2[kt][3], bb.x, bb.y);
            mma8(a5[2*np+1], af2[kt][0], af2[kt][1], af2[kt][2], af2[kt][3], bb.z, bb.w);
        }
    }

    int pxg = hw0 + warp*16 + g;
#pragma unroll
    for (int nt = 0; nt < 8; nt++) {
        int o0 = nt*8 + 2*tig, o1 = o0 + 1;
        int base0 = (b*64 + o0)*HWSZ + pxg;
        int base1 = (b*64 + o1)*HWSZ + pxg;
        out[base0]     = a5[nt][0] + sb5[o0];
        out[base1]     = a5[nt][1] + sb5[o1];
        out[base0 + 8] = a5[nt][2] + sb5[o0];
        out[base1 + 8] = a5[nt][3] + sb5[o1];
    }
}

// ---------------- depthwise 3x3 pair (c, c+64), bf16 io ----------------
// Accumulates InstanceNorm stats (S, Q) on the 'a' half AND the two
// DCT-weighted pool partials P1 = sum w*a*g, P2 = sum w*g.
__global__ __launch_bounds__(256) void k_dw_stats2(
    const bf16* __restrict__ in, const float* __restrict__ w,
    const float* __restrict__ bias, bf16* __restrict__ out)
{
    int bc = blockIdx.z;                 // b*64 + c
    int c = bc & 63, b = bc >> 6;
    int ca = b*128 + c, cg = ca + 64;
    __shared__ float ta[10][34], tg[10][34];
    __shared__ float rA[256], rB[256], rC[256], rD[256];
    int tx0 = blockIdx.x*32, ty0 = blockIdx.y*8;
    int tid = threadIdx.y*32 + threadIdx.x;
    const bf16* sa = in + (size_t)ca*HWSZ;
    const bf16* sg = in + (size_t)cg*HWSZ;
    for (int i = tid; i < 340; i += 256) {
        int r = i/34, cc = i - r*34;
        int gy = ty0 + r - 1, gx = tx0 + cc - 1;
        bool ok = (gy >= 0 && gy < HH && gx >= 0 && gx < WWID);
        ta[r][cc] = ok ? __bfloat162float(sa[gy*WWID+gx]) : 0.f;
        tg[r][cc] = ok ? __bfloat162float(sg[gy*WWID+gx]) : 0.f;
    }
    __syncthreads();
    float da = bias[c], dg = bias[c+64];
#pragma unroll
    for (int di = 0; di < 3; di++)
#pragma unroll
        for (int dj = 0; dj < 3; dj++) {
            da += w[c*9 + di*3 + dj]      * ta[threadIdx.y+di][threadIdx.x+dj];
            dg += w[(64+c)*9 + di*3 + dj] * tg[threadIdx.y+di][threadIdx.x+dj];
        }
    int gy = ty0 + threadIdx.y, gx = tx0 + threadIdx.x;
    out[(size_t)ca*HWSZ + gy*WWID + gx] = __float2bfloat16(da);
    out[(size_t)cg*HWSZ + gy*WWID + gx] = __float2bfloat16(dg);

    float wd = g_dctR[c*56 + (gy >> 2)] * g_dctC[c*56 + (gx >> 2)];
    rA[tid] = da; rB[tid] = da*da; rC[tid] = wd*da*dg; rD[tid] = wd*dg;
    __syncthreads();
    for (int s = 128; s > 0; s >>= 1) {
        if (tid < s) {
            rA[tid] += rA[tid+s]; rB[tid] += rB[tid+s];
            rC[tid] += rC[tid+s]; rD[tid] += rD[tid+s];
        }
        __syncthreads();
    }
    if (tid == 0) {
        atomicAdd(&g_instS[bc], rA[0]);
        atomicAdd(&g_instQ[bc], rB[0]);
        atomicAdd(&g_scay[bc],  rC[0]);
        atomicAdd(&g_scay2[bc], rD[0]);
    }
}

// ---------------- instnorm finish + SCA pool finish + SE ----------------
__global__ void k_se(const float* __restrict__ fc1, const float* __restrict__ fc2,
                     const float* __restrict__ inw, const float* __restrict__ inb) {
    int b = blockIdx.x, c = threadIdx.x;
    int bc = b*64 + c;
    float m = g_instS[bc] * (1.f/HWSZ);
    float var = g_instQ[bc] * (1.f/HWSZ) - m*m;
    float iv = rsqrtf(var + 1e-5f);
    g_instMean[bc] = m; g_instInv[bc] = iv;
    float A = iv*inw[c];
    __shared__ float ys[64];
    ys[c] = (A*g_scay[bc] + (inb[c] - m*A)*g_scay2[bc]) * (1.f/16.f);
    __syncthreads();
    float h[4];
#pragma unroll
    for (int j = 0; j < 4; j++) {
        float s = 0.f;
#pragma unroll
        for (int k = 0; k < 64; k++) s += fc1[j*64 + k] * ys[k];
        h[j] = fmaxf(s, 0.f);
    }
    float z = 0.f;
#pragma unroll
    for (int j = 0; j < 4; j++) z += fc2[c*4 + j] * h[j];
    g_z[bc] = 1.f / (1.f + expf(-z));
}

// ---------------- per-patch spectral transform, in-place fp16 ----------------
__global__ __launch_bounds__(128) void k_fftapply_rb() {
    if (g_fftNonId == 0) return;
    int bc = blockIdx.x;
    int c  = bc & 127;
    __shared__ __align__(16) float Ms[4096];
    __shared__ __align__(16) float pat[64*60];
    int tid = threadIdx.x;
    const float* msrc = g_M + c*4096;
    for (int i = tid; i < 4096; i += 128) Ms[i] = msrc[i];
    fp16* plane = (fp16*)g_buf2a + (size_t)bc*HWSZ;
    int og = tid & 15, pg = tid >> 4;
    for (int bp = 0; bp < 14; bp++) {
        for (int i = tid; i < 3584; i += 128) {
            int r = i / 224, wcol = i - r*224;
            int p = r & 7, band = r >> 3, pc = wcol >> 3, q = wcol & 7;
            pat[(p*8+q)*60 + band*28 + pc] = __half2float(plane[(bp*16 + r)*224 + wcol]);
        }
        __syncthreads();
        ull acc[4][4];
#pragma unroll
        for (int j = 0; j < 4; j++)
#pragma unroll
            for (int u = 0; u < 4; u++) acc[j][u] = 0ULL;
        if (pg < 7) {
            const float* pI = pat + pg*8;
            for (int k = 0; k < 64; k++) {
                ulonglong2 va = *(const ulonglong2*)(pI + k*60);
                ulonglong2 vb = *(const ulonglong2*)(pI + k*60 + 4);
                float4 wv = *(const float4*)(Ms + k*64 + og*4);
                float wav[4] = {wv.x, wv.y, wv.z, wv.w};
#pragma unroll
                for (int j = 0; j < 4; j++) {
                    ull wp = pack2(wav[j]);
                    acc[j][0] = fma2(va.x, wp, acc[j][0]);
                    acc[j][1] = fma2(va.y, wp, acc[j][1]);
                    acc[j][2] = fma2(vb.x, wp, acc[j][2]);
                    acc[j][3] = fma2(vb.y, wp, acc[j][3]);
                }
            }
        }
        __syncthreads();
        if (pg < 7) {
#pragma unroll
            for (int j = 0; j < 4; j++) {
                int o = og*4 + j;
                ulonglong2 s0, s1;
                s0.x = acc[j][0]; s0.y = acc[j][1];
                s1.x = acc[j][2]; s1.y = acc[j][3];
                *(ulonglong2*)(pat + o*60 + pg*8) = s0;
                *(ulonglong2*)(pat + o*60 + pg*8 + 4) = s1;
            }
        }
        __syncthreads();
        for (int i = tid; i < 3584; i += 128) {
            int r = i / 224, wcol = i - r*224;
            int p = r & 7, band = r >> 3, pc = wcol >> 3, q = wcol & 7;
            plane[(bp*16 + r)*224 + wcol] = __float2half(pat[(p*8+q)*60 + band*28 + pc]);
        }
        __syncthreads();
    }
}

// ---------------- DFFN depthwise 3x3 pair + gelu gate (fp16 io) ----------------
__global__ __launch_bounds__(256) void k_dw_gelu(const float* __restrict__ w) {
    int bc = blockIdx.z;
    int c = bc & 63, b = bc >> 6;
    __shared__ float t1[10][34], t2[10][34];
    int tx0 = blockIdx.x*32, ty0 = blockIdx.y*8;
    int tid = threadIdx.y*32 + threadIdx.x;
    const fp16* s1 = (const fp16*)g_buf2a + (size_t)(b*128 + c)*HWSZ;
    const fp16* s2 = (const fp16*)g_buf2a + (size_t)(b*128 + 64 + c)*HWSZ;
    for (int i = tid; i < 340; i += 256) {
        int r = i/34, cc = i - r*34;
        int gy = ty0 + r - 1, gx = tx0 + cc - 1;
        bool ok = (gy >= 0 && gy < HH && gx >= 0 && gx < WWID);
        t1[r][cc] = ok ? __half2float(s1[gy*WWID+gx]) : 0.f;
        t2[r][cc] = ok ? __half2float(s2[gy*WWID+gx]) : 0.f;
    }
    __syncthreads();
    float d1 = 0.f, d2 = 0.f;
#pragma unroll
    for (int di = 0; di < 3; di++)
#pragma unroll
        for (int dj = 0; dj < 3; dj++) {
            d1 += w[c*9 + di*3 + dj]      * t1[threadIdx.y+di][threadIdx.x+dj];
            d2 += w[(64+c)*9 + di*3 + dj] * t2[threadIdx.y+di][threadIdx.x+dj];
        }
    float gel = 0.5f * d1 * (1.f + erff(d1 * 0.70710678118f));
    ((fp16*)g_bufc)[(size_t)bc*HWSZ + (ty0+threadIdx.y)*WWID + tx0 + threadIdx.x]
        = __float2half(gel * d2);
}

// ---------------- launch ----------------
extern "C" void kernel_launch(void* const* d_in, const int* in_sizes, int n_in,
                              void* d_out, int out_size)
{
    (void)in_sizes; (void)n_in; (void)out_size;
    const float* x       = (const float*)d_in[0];
    const float* n1_w    = (const float*)d_in[1];
    const float* n1_b    = (const float*)d_in[2];
    const float* conv1_w = (const float*)d_in[3];
    const float* conv1_b = (const float*)d_in[4];
    const float* conv2_w = (const float*)d_in[5];
    const float* conv2_b = (const float*)d_in[6];
    const float* in_w    = (const float*)d_in[7];
    const float* in_b    = (const float*)d_in[8];
    const float* fc1_w   = (const float*)d_in[9];
    const float* fc2_w   = (const float*)d_in[10];
    const float* conv3_w = (const float*)d_in[11];
    const float* conv3_b = (const float*)d_in[12];
    const float* beta    = (const float*)d_in[13];
    const float* n2n_w   = (const float*)d_in[14];
    const float* n2n_b   = (const float*)d_in[15];
    const float* conv4_w = (const float*)d_in[16];
    const float* conv4_b = (const float*)d_in[17];
    const float* conv5_w = (const float*)d_in[18];
    const float* conv5_b = (const float*)d_in[19];
    const float* ln_w    = (const float*)d_in[20];
    const float* ln_b    = (const float*)d_in[21];
    const float* pin_w   = (const float*)d_in[22];
    const float* dw_w    = (const float*)d_in[23];
    const float* fft_w   = (const float*)d_in[24];
    const float* pout_w  = (const float*)d_in[25];

    float *t2a, *t2b, *tc, *ty;
    cudaGetSymbolAddress((void**)&t2a, g_buf2a);
    cudaGetSymbolAddress((void**)&t2b, g_buf2b);
    cudaGetSymbolAddress((void**)&tc,  g_bufc);
    cudaGetSymbolAddress((void**)&ty,  g_y);

    // carve two bf16 buffers out of g_buf2b
    bf16* c1bf = (bf16*)t2b;                          // conv1 output [b,128,HW]
    bf16* dwbf = c1bf + (size_t)BB*C2*HWSZ;           // dw output    [b,128,HW]
    // fp16 views: pin-out in g_buf2a, gelu-gated in g_bufc
    fp16* pinh = (fp16*)t2a;
    fp16* gmh  = (fp16*)tc;

    const int GB = NPIX / 128;     // 3136 blocks (128 px each)

    k_zero<<<1, 512>>>();
    k_tables<<<28, 128>>>();
    k_fftmat<<<64, 128>>>(fft_w);

    // conv1: LN(n1) + 64->128 + bias  -> bf16
    k_tc<16,1,0,1><<<GB, 256>>>(x, conv1_w, conv1_b, n1_w, n1_b, 1e-6f,
                                nullptr, nullptr, nullptr, (float*)c1bf, 128);

    // depthwise pair + conv2 bias (bf16 io) + IN stats + SCA pool partials
    {
        dim3 g(7, 28, BB*CCH), blk(32, 8);
        k_dw_stats2<<<g, blk>>>(c1bf, conv2_w, conv2_b, dwbf);
    }
    // instnorm finish + pool finish + SE
    k_se<<<BB, 64>>>(fc1_w, fc2_w, in_w, in_b);

    // conv3 with inline instnorm-gate-z staging + residual -> g_buf2a... careful:
    // residual written fp32 into g_y? No: residual -> we need it for k_tc45 input and xres.
    // Keep residual fp32 in g_buf2b? c1bf/dwbf no longer needed after conv3 reads dwbf.
    // Residual goes to the second half region of g_buf2b (dwbf space is still in use
    // during conv3). Use g_y for residual, then y to... Simplest: residual -> g_buf2b
    // reinterpreted fp32 (c1bf region, 102.8MB = exactly 64ch fp32) AFTER dw reads done.
    // c1bf region is free once dw_stats2 completed. 64ch fp32 = 102.8MB fits c1bf's 128ch bf16.
    k_tc<8,4,1,0><<<GB, 256>>>((const float*)dwbf, conv3_w, conv3_b, in_w, in_b, 0.f,
                               x, beta, nullptr, (float*)t2b, 64);
    // fused conv4 + SimpleGate + conv5 -> y
    k_tc45<<<GB, 256>>>((const float*)t2b, conv4_w, conv4_b, n2n_w, n2n_b,
                        conv5_w, conv5_b, ty);

    // DFFN: LN + pin (64->128) -> fp16 in g_buf2a
    k_tc<16,1,0,2><<<GB, 256>>>(ty, pin_w, nullptr, ln_w, ln_b, 1e-5f,
                                nullptr, nullptr, nullptr, (float*)pinh, 128);
    // patch spectral transform in-place fp16 (skips when identity)
    k_fftapply_rb<<<BB*C2, 128>>>();
    // depthwise pair + gelu gate -> fp16 g_bufc
    {
        dim3 g(7, 28, BB*CCH), blk(32, 8);
        k_dw_gelu<<<g, blk>>>(dw_w);
    }
    // pout (fp16 in) + y -> d_out
    k_tc<8,5,2,0><<<GB, 256>>>((const float*)gmh, pout_w, nullptr, nullptr, nullptr, 0.f,
                               nullptr, nullptr, ty, (float*)d_out, 64);
}

// round 14
// speedup vs baseline: 1.6006x; 1.1211x over previous
#include <cuda_runtime.h>
#include <cuda_bf16.h>
#include <cuda_fp16.h>
#include <math.h>

#define BB    8
#define CCH   64
#define C2    128
#define HH    224
#define WWID  224
#define HWSZ  (HH*WWID)          // 50176
#define NPIX  (BB*HWSZ)          // 401408

typedef unsigned long long ull;
typedef __nv_bfloat16 bf16;
typedef __half fp16;

// ---------------- packed f32x2 helpers (used by fftapply) ----------------
__device__ __forceinline__ ull pack2(float x) {
    ull r; asm("mov.b64 %0, {%1, %1};" : "=l"(r) : "f"(x)); return r;
}
__device__ __forceinline__ ull fma2(ull a, ull b, ull c) {
    ull d; asm("fma.rn.f32x2 %0, %1, %2, %3;" : "=l"(d) : "l"(a), "l"(b), "l"(c)); return d;
}

// ---------------- tf32 mma helpers ----------------
__device__ __forceinline__ unsigned cvt_tf32(float f) {
    unsigned u; asm("cvt.rna.tf32.f32 %0, %1;" : "=r"(u) : "f"(f)); return u;
}
__device__ __forceinline__ void mma8(float* c, unsigned a0, unsigned a1,
                                     unsigned a2, unsigned a3, float bx, float by) {
    unsigned b0 = __float_as_uint(bx), b1 = __float_as_uint(by);
    asm("mma.sync.aligned.m16n8k8.row.col.f32.tf32.tf32.f32 "
        "{%0,%1,%2,%3}, {%4,%5,%6,%7}, {%8,%9}, {%0,%1,%2,%3};"
        : "+f"(c[0]), "+f"(c[1]), "+f"(c[2]), "+f"(c[3])
        : "r"(a0), "r"(a1), "r"(a2), "r"(a3), "r"(b0), "r"(b1));
}

// ---------------- scratch (device globals; no allocation allowed) ----------------
static __device__ float g_buf2a[BB*C2*HWSZ];   // fp32 residual / fp16 pin-out+fft
static __device__ float g_buf2b[BB*C2*HWSZ];   // carved: bf16 conv1out/dwout, then fp32 residual
static __device__ float g_bufc [BB*CCH*HWSZ];  // carved: fp16 dffn gelu-gated
static __device__ float g_y    [BB*CCH*HWSZ];  // fp32: NAF output y
static __device__ float g_M    [C2*64*64];     // [c][in][out]
static __device__ __align__(16) float g_wfrag[36864];  // precomputed tf32 B-fragments
static __device__ float g_dctR [CCH*56];
static __device__ float g_dctC [CCH*56];
static __device__ float g_instS[BB*CCH], g_instQ[BB*CCH];
static __device__ float g_instMean[BB*CCH], g_instInv[BB*CCH];
static __device__ float g_scay[BB*CCH], g_scay2[BB*CCH], g_z[BB*CCH];
static __device__ int   g_fftNonId;

// fragment buffer offsets (floats)
#define WF_CONV1 0
#define WF_CONV3 8192
#define WF_CONV4 12288
#define WF_CONV5 20480
#define WF_PIN   24576
#define WF_POUT  32768

// ---------------- tiny init kernels ----------------
__global__ void k_zero() {
    int t = threadIdx.x;
    if (t < BB*CCH) {
        g_instS[t] = 0.f; g_instQ[t] = 0.f;
        g_scay[t] = 0.f;  g_scay2[t] = 0.f;
    }
    if (t == 0) g_fftNonId = 0;
}

// precompute tf32 weight fragments: w[OC][64] -> fragment order for NT=OC/8
__global__ void k_wprep(const float* __restrict__ w, int OC, int wfoff) {
    int i = blockIdx.x*256 + threadIdx.x;
    if (i >= OC*64) return;
    int k = i & 63, oc = i >> 6;
    int NT = OC >> 3;
    int kt = k >> 3, kk = k & 7, nt = oc >> 3, nn = oc & 7;
    unsigned v = cvt_tf32(__ldg(w + oc*64 + k));
    int idx = ((kt*(NT/2) + (nt>>1))*32 + nn*4 + (kk&3))*4 + ((nt&1)*2 + (kk>>2));
    g_wfrag[wfoff + idx] = __uint_as_float(v);
}

__global__ void k_tables() {
    int t = blockIdx.x * blockDim.x + threadIdx.x;
    if (t >= CCH*56) return;
    int c = t / 56, i = t - c*56;
    const int mx[16] = {0,0,6,0,0,1,1,4,5,1,3,0,0,0,3,2};
    const int my[16] = {0,1,0,5,2,0,2,0,0,6,0,4,6,3,2,5};
    int g = c >> 2;
    int ux = mx[g]*8, uy = my[g]*8;
    float inv = rsqrtf(56.f);
    float rv = cosf((float)M_PI * ux * (i + 0.5f) / 56.f) * inv;
    if (ux) rv *= 1.41421356237f;
    float cv = cosf((float)M_PI * uy * (i + 0.5f) / 56.f) * inv;
    if (uy) cv *= 1.41421356237f;
    g_dctR[t] = rv; g_dctC[t] = cv;
}

__global__ void k_fftmat(const float* __restrict__ fw) {
    int t = blockIdx.x * blockDim.x + threadIdx.x;
    if (t >= C2*64) return;
    int c = t >> 6, in = t & 63, i0 = in >> 3, j0 = in & 7;
    const float c8[8] = {1.f, 0.70710678118f, 0.f, -0.70710678118f,
                         -1.f, -0.70710678118f, 0.f, 0.70710678118f};
    const float s8[8] = {0.f, 0.70710678118f, 1.f, 0.70710678118f,
                         0.f, -0.70710678118f, -1.f, -0.70710678118f};
    int dev = 0;
    for (int p = 0; p < 8; p++) {
        float Gr[5], Gi[5];
        for (int v = 0; v < 5; v++) {
            float gr = 0.f, gi = 0.f;
            for (int u = 0; u < 8; u++) {
                int idx = ((u*(p - i0) - v*j0) % 8 + 8) % 8;
                float w = fw[c*40 + u*5 + v];
                gr += w * c8[idx]; gi += w * s8[idx];
            }
            Gr[v] = gr; Gi[v] = gi;
        }
        for (int q = 0; q < 8; q++) {
            float val = Gr[0] + ((q & 1) ? -Gr[4] : Gr[4]);
            for (int v = 1; v < 4; v++) {
                int k = (v*q) & 7;
                val += 2.f * (Gr[v]*c8[k] - Gi[v]*s8[k]);
            }
            val *= (1.f/64.f);
            int outp = p*8 + q;
            g_M[c*4096 + in*64 + outp] = val;
            float expect = (outp == in) ? 1.f : 0.f;
            if (fabsf(val - expect) > 1e-5f) dev = 1;
        }
    }
    if (dev) g_fftNonId = 1;
}

// =====================================================================
// Tensor-core conv1x1 GEMM.  128 px x (NT*8) oc per block, K=64, tf32 mma.
// B fragments precomputed in g_wfrag (L2-resident, coalesced float4 reads).
// IMODE: 0 plain f32, 1 channel-LN f32, 4 instnorm-gate bf16, 5 plain fp16
// OMODE: 0 acc+bias, 1 x + beta*(acc+bias), 2 acc+add
// OBF:   0 f32 out, 1 bf16 out, 2 fp16 out   (OMODE 0 only)
// =====================================================================
#define APAD 136

template<int NT, int IMODE, int OMODE, int OBF>
__global__ __launch_bounds__(256, 2) void k_tc(
    const float* __restrict__ in, int wfoff,
    const float* __restrict__ bias, const float* __restrict__ lnw,
    const float* __restrict__ lnb, float eps,
    const float* __restrict__ xres, const float* __restrict__ beta,
    const float* __restrict__ addsrc, float* __restrict__ out, int ocStride)
{
    constexpr int NOC = NT*8;
    __shared__ __align__(16) float ABsm[64*APAD];
    __shared__ float sbias[128];
    __shared__ float sAZ[64], sBZ[64];

    int tid = threadIdx.x;
    int pix0 = blockIdx.x*128;
    int b = pix0 / HWSZ, hw0 = pix0 - b*HWSZ;

    if (tid < NOC) sbias[tid] = bias ? __ldg(bias + tid) : 0.f;

    // ---- phase 1: stage A ----
    if (IMODE == 1) {
        int p = tid >> 1, h = tid & 1;
        const float* src = in + (b*64 + h*32)*HWSZ + hw0 + p;
        float v[32];
#pragma unroll
        for (int c = 0; c < 32; c++) v[c] = src[c*HWSZ];
        float s = 0.f;
#pragma unroll
        for (int c = 0; c < 32; c++) s += v[c];
        s += __shfl_xor_sync(0xffffffffu, s, 1);
        float mu = s * (1.f/64.f);
        float q = 0.f;
#pragma unroll
        for (int c = 0; c < 32; c++) { float d = v[c]-mu; q += d*d; }
        q += __shfl_xor_sync(0xffffffffu, q, 1);
        float is = rsqrtf(q*(1.f/64.f) + eps);
#pragma unroll
        for (int c = 0; c < 32; c++) {
            int ch = h*32 + c;
            float val = (v[c]-mu)*is*__ldg(lnw+ch) + __ldg(lnb+ch);
            ABsm[ch*APAD + p] = __uint_as_float(cvt_tf32(val));
        }
    } else if (IMODE == 4) {
        if (tid < 64) {
            int bc = b*64 + tid;
            float iv = g_instInv[bc];
            float A  = iv*__ldg(lnw + tid);
            float z  = g_z[bc];
            sAZ[tid] = A*z;
            sBZ[tid] = (__ldg(lnb + tid) - g_instMean[bc]*A)*z;
        }
        __syncthreads();
        const bf16* inb16 = (const bf16*)in;
        for (int i = tid; i < 8192; i += 256) {
            int px = i & 127, c = i >> 7;
            float a  = __bfloat162float(inb16[(size_t)(b*128 + c)*HWSZ + hw0 + px]);
            float gg = __bfloat162float(inb16[(size_t)(b*128 + 64 + c)*HWSZ + hw0 + px]);
            float val = (a*sAZ[c] + sBZ[c])*gg;
            ABsm[c*APAD + px] = __uint_as_float(cvt_tf32(val));
        }
    } else if (IMODE == 5) {
        const fp16* inh = (const fp16*)in;
        for (int i = tid; i < 8192; i += 256) {
            int px = i & 127, c = i >> 7;
            float val = __half2float(inh[(size_t)(b*64 + c)*HWSZ + hw0 + px]);
            ABsm[c*APAD + px] = __uint_as_float(cvt_tf32(val));
        }
    } else {
        for (int i = tid; i < 8192; i += 256) {
            int px = i & 127, c = i >> 7;
            float val = in[(b*64 + c)*HWSZ + hw0 + px];
            ABsm[c*APAD + px] = __uint_as_float(cvt_tf32(val));
        }
    }
    __syncthreads();

    // ---- phase 2: A fragments to regs ----
    int warp = tid >> 5, lane = tid & 31, g = lane >> 2, tig = lane & 3;
    int pxA = warp*16 + g;
    unsigned afrag[8][4];
#pragma unroll
    for (int kt = 0; kt < 8; kt++) {
        int ca = kt*8 + tig;
        afrag[kt][0] = __float_as_uint(ABsm[ca*APAD + pxA]);
        afrag[kt][1] = __float_as_uint(ABsm[ca*APAD + pxA + 8]);
        afrag[kt][2] = __float_as_uint(ABsm[(ca+4)*APAD + pxA]);
        afrag[kt][3] = __float_as_uint(ABsm[(ca+4)*APAD + pxA + 8]);
    }

    // ---- phase 3: MMA mainloop, B fragments streamed from gmem (L2-hot) ----
    const float4* Bg = (const float4*)(g_wfrag + wfoff);
    float acc[NT][4];
#pragma unroll
    for (int nt = 0; nt < NT; nt++)
#pragma unroll
        for (int u = 0; u < 4; u++) acc[nt][u] = 0.f;

#pragma unroll
    for (int kt = 0; kt < 8; kt++) {
#pragma unroll
        for (int np = 0; np < NT/2; np++) {
            float4 bb = __ldg(&Bg[(kt*(NT/2) + np)*32 + lane]);
            mma8(acc[2*np],   afrag[kt][0], afrag[kt][1], afrag[kt][2], afrag[kt][3], bb.x, bb.y);
            mma8(acc[2*np+1], afrag[kt][0], afrag[kt][1], afrag[kt][2], afrag[kt][3], bb.z, bb.w);
        }
    }

    // ---- epilogue (scattered) ----
    int pxg = hw0 + warp*16 + g;
#pragma unroll
    for (int nt = 0; nt < NT; nt++) {
        int o0 = nt*8 + 2*tig, o1 = o0 + 1;
        size_t base0 = (size_t)(b*ocStride + o0)*HWSZ + pxg;
        size_t base1 = (size_t)(b*ocStride + o1)*HWSZ + pxg;
        float r0 = acc[nt][0], r1 = acc[nt][1], r2 = acc[nt][2], r3 = acc[nt][3];
        if (OMODE == 0) {
            float b0v = sbias[o0], b1v = sbias[o1];
            if (OBF == 1) {
                bf16* ob = (bf16*)out;
                ob[base0]     = __float2bfloat16(r0 + b0v);
                ob[base1]     = __float2bfloat16(r1 + b1v);
                ob[base0 + 8] = __float2bfloat16(r2 + b0v);
                ob[base1 + 8] = __float2bfloat16(r3 + b1v);
            } else if (OBF == 2) {
                fp16* oh = (fp16*)out;
                oh[base0]     = __float2half(r0 + b0v);
                oh[base1]     = __float2half(r1 + b1v);
                oh[base0 + 8] = __float2half(r2 + b0v);
                oh[base1 + 8] = __float2half(r3 + b1v);
            } else {
                out[base0]     = r0 + b0v;
                out[base1]     = r1 + b1v;
                out[base0 + 8] = r2 + b0v;
                out[base1 + 8] = r3 + b1v;
            }
        } else if (OMODE == 1) {
            float b0v = sbias[o0], b1v = sbias[o1];
            float bt0 = __ldg(beta + o0), bt1 = __ldg(beta + o1);
            out[base0]     = fmaf(r0 + b0v, bt0, __ldg(xres + base0));
            out[base1]     = fmaf(r1 + b1v, bt1, __ldg(xres + base1));
            out[base0 + 8] = fmaf(r2 + b0v, bt0, __ldg(xres + base0 + 8));
            out[base1 + 8] = fmaf(r3 + b1v, bt1, __ldg(xres + base1 + 8));
        } else {
            out[base0]     = r0 + __ldg(addsrc + base0);
            out[base1]     = r1 + __ldg(addsrc + base1);
            out[base0 + 8] = r2 + __ldg(addsrc + base0 + 8);
            out[base1 + 8] = r3 + __ldg(addsrc + base1 + 8);
        }
    }
}

// =====================================================================
// Fused conv4 (LN + 64->128) -> SimpleGate -> conv5 (64->64).
// B4/B5 fragments from g_wfrag.
// =====================================================================
__global__ __launch_bounds__(256, 2) void k_tc45(
    const float* __restrict__ in,
    const float* __restrict__ b4, const float* __restrict__ lnw,
    const float* __restrict__ lnb,
    const float* __restrict__ b5, float* __restrict__ out)
{
    __shared__ __align__(16) float ABsm[64*APAD];
    __shared__ float sb4[128], sb5[64];

    int tid = threadIdx.x;
    int pix0 = blockIdx.x*128;
    int b = pix0 / HWSZ, hw0 = pix0 - b*HWSZ;
    if (tid < 128) sb4[tid] = __ldg(b4 + tid);
    if (tid < 64)  sb5[tid] = __ldg(b5 + tid);

    // stage A with channel-LN (eps 1e-6)
    {
        int p = tid >> 1, h = tid & 1;
        const float* src = in + (b*64 + h*32)*HWSZ + hw0 + p;
        float v[32];
#pragma unroll
        for (int c = 0; c < 32; c++) v[c] = src[c*HWSZ];
        float s = 0.f;
#pragma unroll
        for (int c = 0; c < 32; c++) s += v[c];
        s += __shfl_xor_sync(0xffffffffu, s, 1);
        float mu = s * (1.f/64.f);
        float q = 0.f;
#pragma unroll
        for (int c = 0; c < 32; c++) { float d = v[c]-mu; q += d*d; }
        q += __shfl_xor_sync(0xffffffffu, q, 1);
        float is = rsqrtf(q*(1.f/64.f) + 1e-6f);
#pragma unroll
        for (int c = 0; c < 32; c++) {
            int ch = h*32 + c;
            float val = (v[c]-mu)*is*__ldg(lnw+ch) + __ldg(lnb+ch);
            ABsm[ch*APAD + p] = __uint_as_float(cvt_tf32(val));
        }
    }
    __syncthreads();

    int warp = tid >> 5, lane = tid & 31, g = lane >> 2, tig = lane & 3;
    int pxA = warp*16 + g;
    unsigned afrag[8][4];
#pragma unroll
    for (int kt = 0; kt < 8; kt++) {
        int ca = kt*8 + tig;
        afrag[kt][0] = __float_as_uint(ABsm[ca*APAD + pxA]);
        afrag[kt][1] = __float_as_uint(ABsm[ca*APAD + pxA + 8]);
        afrag[kt][2] = __float_as_uint(ABsm[(ca+4)*APAD + pxA]);
        afrag[kt][3] = __float_as_uint(ABsm[(ca+4)*APAD + pxA + 8]);
    }

    // MMA 1 (conv4, NT=16) — B from gmem fragments
    const float4* B4g = (const float4*)(g_wfrag + WF_CONV4);
    float acc[16][4];
#pragma unroll
    for (int nt = 0; nt < 16; nt++)
#pragma unroll
        for (int u = 0; u < 4; u++) acc[nt][u] = 0.f;
#pragma unroll
    for (int kt = 0; kt < 8; kt++) {
#pragma unroll
        for (int np = 0; np < 8; np++) {
            float4 bb = __ldg(&B4g[(kt*8 + np)*32 + lane]);
            mma8(acc[2*np],   afrag[kt][0], afrag[kt][1], afrag[kt][2], afrag[kt][3], bb.x, bb.y);
            mma8(acc[2*np+1], afrag[kt][0], afrag[kt][1], afrag[kt][2], afrag[kt][3], bb.z, bb.w);
        }
    }

    // SimpleGate in registers
    float gated[8][4];
#pragma unroll
    for (int nt = 0; nt < 8; nt++) {
        int o0 = nt*8 + 2*tig, o1 = o0 + 1;
        gated[nt][0] = (acc[nt][0] + sb4[o0]) * (acc[nt+8][0] + sb4[o0+64]);
        gated[nt][1] = (acc[nt][1] + sb4[o1]) * (acc[nt+8][1] + sb4[o1+64]);
        gated[nt][2] = (acc[nt][2] + sb4[o0]) * (acc[nt+8][2] + sb4[o0+64]);
        gated[nt][3] = (acc[nt][3] + sb4[o1]) * (acc[nt+8][3] + sb4[o1+64]);
    }
    __syncthreads();   // A reads complete before overwriting ABsm

    // route gated through smem as new A matrix [ch][px]
#pragma unroll
    for (int nt = 0; nt < 8; nt++) {
        int o0 = nt*8 + 2*tig, o1 = o0 + 1;
        ABsm[o0*APAD + pxA]     = __uint_as_float(cvt_tf32(gated[nt][0]));
        ABsm[o1*APAD + pxA]     = __uint_as_float(cvt_tf32(gated[nt][1]));
        ABsm[o0*APAD + pxA + 8] = __uint_as_float(cvt_tf32(gated[nt][2]));
        ABsm[o1*APAD + pxA + 8] = __uint_as_float(cvt_tf32(gated[nt][3]));
    }
    __syncthreads();

    unsigned af2[8][4];
#pragma unroll
    for (int kt = 0; kt < 8; kt++) {
        int ca = kt*8 + tig;
        af2[kt][0] = __float_as_uint(ABsm[ca*APAD + pxA]);
        af2[kt][1] = __float_as_uint(ABsm[ca*APAD + pxA + 8]);
        af2[kt][2] = __float_as_uint(ABsm[(ca+4)*APAD + pxA]);
        af2[kt][3] = __float_as_uint(ABsm[(ca+4)*APAD + pxA + 8]);
    }

    // MMA 2 (conv5, NT=8) — B from gmem fragments
    const float4* B5g = (const float4*)(g_wfrag + WF_CONV5);
    float a5[8][4];
#pragma unroll
    for (int nt = 0; nt < 8; nt++)
#pragma unroll
        for (int u = 0; u < 4; u++) a5[nt][u] = 0.f;
#pragma unroll
    for (int kt = 0; kt < 8; kt++) {
#pragma unroll
        for (int np = 0; np < 4; np++) {
            float4 bb = __ldg(&B5g[(kt*4 + np)*32 + lane]);
            mma8(a5[2*np],   af2[kt][0], af2[kt][1], af2[kt][2], af2[kt][3], bb.x, bb.y);
            mma8(a5[2*np+1], af2[kt][0], af2[kt][1], af2[kt][2], af2[kt][3], bb.z, bb.w);
        }
    }

    int pxg = hw0 + warp*16 + g;
#pragma unroll
    for (int nt = 0; nt < 8; nt++) {
        int o0 = nt*8 + 2*tig, o1 = o0 + 1;
        int base0 = (b*64 + o0)*HWSZ + pxg;
        int base1 = (b*64 + o1)*HWSZ + pxg;
        out[base0]     = a5[nt][0] + sb5[o0];
        out[base1]     = a5[nt][1] + sb5[o1];
        out[base0 + 8] = a5[nt][2] + sb5[o0];
        out[base1 + 8] = a5[nt][3] + sb5[o1];
    }
}

// ---------------- depthwise 3x3 pair (c, c+64), bf16 io ----------------
__global__ __launch_bounds__(256) void k_dw_stats2(
    const bf16* __restrict__ in, const float* __restrict__ w,
    const float* __restrict__ bias, bf16* __restrict__ out)
{
    int bc = blockIdx.z;                 // b*64 + c
    int c = bc & 63, b = bc >> 6;
    int ca = b*128 + c, cg = ca + 64;
    __shared__ float ta[10][34], tg[10][34];
    __shared__ float rA[256], rB[256], rC[256], rD[256];
    int tx0 = blockIdx.x*32, ty0 = blockIdx.y*8;
    int tid = threadIdx.y*32 + threadIdx.x;
    const bf16* sa = in + (size_t)ca*HWSZ;
    const bf16* sg = in + (size_t)cg*HWSZ;
    for (int i = tid; i < 340; i += 256) {
        int r = i/34, cc = i - r*34;
        int gy = ty0 + r - 1, gx = tx0 + cc - 1;
        bool ok = (gy >= 0 && gy < HH && gx >= 0 && gx < WWID);
        ta[r][cc] = ok ? __bfloat162float(sa[gy*WWID+gx]) : 0.f;
        tg[r][cc] = ok ? __bfloat162float(sg[gy*WWID+gx]) : 0.f;
    }
    __syncthreads();
    float da = bias[c], dg = bias[c+64];
#pragma unroll
    for (int di = 0; di < 3; di++)
#pragma unroll
        for (int dj = 0; dj < 3; dj++) {
            da += w[c*9 + di*3 + dj]      * ta[threadIdx.y+di][threadIdx.x+dj];
            dg += w[(64+c)*9 + di*3 + dj] * tg[threadIdx.y+di][threadIdx.x+dj];
        }
    int gy = ty0 + threadIdx.y, gx = tx0 + threadIdx.x;
    out[(size_t)ca*HWSZ + gy*WWID + gx] = __float2bfloat16(da);
    out[(size_t)cg*HWSZ + gy*WWID + gx] = __float2bfloat16(dg);

    float wd = g_dctR[c*56 + (gy >> 2)] * g_dctC[c*56 + (gx >> 2)];
    rA[tid] = da; rB[tid] = da*da; rC[tid] = wd*da*dg; rD[tid] = wd*dg;
    __syncthreads();
    for (int s = 128; s > 0; s >>= 1) {
        if (tid < s) {
            rA[tid] += rA[tid+s]; rB[tid] += rB[tid+s];
            rC[tid] += rC[tid+s]; rD[tid] += rD[tid+s];
        }
        __syncthreads();
    }
    if (tid == 0) {
        atomicAdd(&g_instS[bc], rA[0]);
        atomicAdd(&g_instQ[bc], rB[0]);
        atomicAdd(&g_scay[bc],  rC[0]);
        atomicAdd(&g_scay2[bc], rD[0]);
    }
}

// ---------------- instnorm finish + SCA pool finish + SE ----------------
__global__ void k_se(const float* __restrict__ fc1, const float* __restrict__ fc2,
                     const float* __restrict__ inw, const float* __restrict__ inb) {
    int b = blockIdx.x, c = threadIdx.x;
    int bc = b*64 + c;
    float m = g_instS[bc] * (1.f/HWSZ);
    float var = g_instQ[bc] * (1.f/HWSZ) - m*m;
    float iv = rsqrtf(var + 1e-5f);
    g_instMean[bc] = m; g_instInv[bc] = iv;
    float A = iv*inw[c];
    __shared__ float ys[64];
    ys[c] = (A*g_scay[bc] + (inb[c] - m*A)*g_scay2[bc]) * (1.f/16.f);
    __syncthreads();
    float h[4];
#pragma unroll
    for (int j = 0; j < 4; j++) {
        float s = 0.f;
#pragma unroll
        for (int k = 0; k < 64; k++) s += fc1[j*64 + k] * ys[k];
        h[j] = fmaxf(s, 0.f);
    }
    float z = 0.f;
#pragma unroll
    for (int j = 0; j < 4; j++) z += fc2[c*4 + j] * h[j];
    g_z[bc] = 1.f / (1.f + expf(-z));
}

// ---------------- per-patch spectral transform, in-place fp16 ----------------
__global__ __launch_bounds__(128) void k_fftapply_rb() {
    if (g_fftNonId == 0) return;
    int bc = blockIdx.x;
    int c  = bc & 127;
    __shared__ __align__(16) float Ms[4096];
    __shared__ __align__(16) float pat[64*60];
    int tid = threadIdx.x;
    const float* msrc = g_M + c*4096;
    for (int i = tid; i < 4096; i += 128) Ms[i] = msrc[i];
    fp16* plane = (fp16*)g_buf2a + (size_t)bc*HWSZ;
    int og = tid & 15, pg = tid >> 4;
    for (int bp = 0; bp < 14; bp++) {
        for (int i = tid; i < 3584; i += 128) {
            int r = i / 224, wcol = i - r*224;
            int p = r & 7, band = r >> 3, pc = wcol >> 3, q = wcol & 7;
            pat[(p*8+q)*60 + band*28 + pc] = __half2float(plane[(bp*16 + r)*224 + wcol]);
        }
        __syncthreads();
        ull acc[4][4];
#pragma unroll
        for (int j = 0; j < 4; j++)
#pragma unroll
            for (int u = 0; u < 4; u++) acc[j][u] = 0ULL;
        if (pg < 7) {
            const float* pI = pat + pg*8;
            for (int k = 0; k < 64; k++) {
                ulonglong2 va = *(const ulonglong2*)(pI + k*60);
                ulonglong2 vb = *(const ulonglong2*)(pI + k*60 + 4);
                float4 wv = *(const float4*)(Ms + k*64 + og*4);
                float wav[4] = {wv.x, wv.y, wv.z, wv.w};
#pragma unroll
                for (int j = 0; j < 4; j++) {
                    ull wp = pack2(wav[j]);
                    acc[j][0] = fma2(va.x, wp, acc[j][0]);
                    acc[j][1] = fma2(va.y, wp, acc[j][1]);
                    acc[j][2] = fma2(vb.x, wp, acc[j][2]);
                    acc[j][3] = fma2(vb.y, wp, acc[j][3]);
                }
            }
        }
        __syncthreads();
        if (pg < 7) {
#pragma unroll
            for (int j = 0; j < 4; j++) {
                int o = og*4 + j;
                ulonglong2 s0, s1;
                s0.x = acc[j][0]; s0.y = acc[j][1];
                s1.x = acc[j][2]; s1.y = acc[j][3];
                *(ulonglong2*)(pat + o*60 + pg*8) = s0;
                *(ulonglong2*)(pat + o*60 + pg*8 + 4) = s1;
            }
        }
        __syncthreads();
        for (int i = tid; i < 3584; i += 128) {
            int r = i / 224, wcol = i - r*224;
            int p = r & 7, band = r >> 3, pc = wcol >> 3, q = wcol & 7;
            plane[(bp*16 + r)*224 + wcol] = __float2half(pat[(p*8+q)*60 + band*28 + pc]);
        }
        __syncthreads();
    }
}

// ---------------- DFFN depthwise 3x3 pair + gelu gate (fp16 io) ----------------
__global__ __launch_bounds__(256) void k_dw_gelu(const float* __restrict__ w) {
    int bc = blockIdx.z;
    int c = bc & 63, b = bc >> 6;
    __shared__ float t1[10][34], t2[10][34];
    int tx0 = blockIdx.x*32, ty0 = blockIdx.y*8;
    int tid = threadIdx.y*32 + threadIdx.x;
    const fp16* s1 = (const fp16*)g_buf2a + (size_t)(b*128 + c)*HWSZ;
    const fp16* s2 = (const fp16*)g_buf2a + (size_t)(b*128 + 64 + c)*HWSZ;
    for (int i = tid; i < 340; i += 256) {
        int r = i/34, cc = i - r*34;
        int gy = ty0 + r - 1, gx = tx0 + cc - 1;
        bool ok = (gy >= 0 && gy < HH && gx >= 0 && gx < WWID);
        t1[r][cc] = ok ? __half2float(s1[gy*WWID+gx]) : 0.f;
        t2[r][cc] = ok ? __half2float(s2[gy*WWID+gx]) : 0.f;
    }
    __syncthreads();
    float d1 = 0.f, d2 = 0.f;
#pragma unroll
    for (int di = 0; di < 3; di++)
#pragma unroll
        for (int dj = 0; dj < 3; dj++) {
            d1 += w[c*9 + di*3 + dj]      * t1[threadIdx.y+di][threadIdx.x+dj];
            d2 += w[(64+c)*9 + di*3 + dj] * t2[threadIdx.y+di][threadIdx.x+dj];
        }
    float gel = 0.5f * d1 * (1.f + erff(d1 * 0.70710678118f));
    ((fp16*)g_bufc)[(size_t)bc*HWSZ + (ty0+threadIdx.y)*WWID + tx0 + threadIdx.x]
        = __float2half(gel * d2);
}

// ---------------- launch ----------------
extern "C" void kernel_launch(void* const* d_in, const int* in_sizes, int n_in,
                              void* d_out, int out_size)
{
    (void)in_sizes; (void)n_in; (void)out_size;
    const float* x       = (const float*)d_in[0];
    const float* n1_w    = (const float*)d_in[1];
    const float* n1_b    = (const float*)d_in[2];
    const float* conv1_w = (const float*)d_in[3];
    const float* conv1_b = (const float*)d_in[4];
    const float* conv2_w = (const float*)d_in[5];
    const float* conv2_b = (const float*)d_in[6];
    const float* in_w    = (const float*)d_in[7];
    const float* in_b    = (const float*)d_in[8];
    const float* fc1_w   = (const float*)d_in[9];
    const float* fc2_w   = (const float*)d_in[10];
    const float* conv3_w = (const float*)d_in[11];
    const float* conv3_b = (const float*)d_in[12];
    const float* beta    = (const float*)d_in[13];
    const float* n2n_w   = (const float*)d_in[14];
    const float* n2n_b   = (const float*)d_in[15];
    const float* conv4_w = (const float*)d_in[16];
    const float* conv4_b = (const float*)d_in[17];
    const float* conv5_w = (const float*)d_in[18];
    const float* conv5_b = (const float*)d_in[19];
    const float* ln_w    = (const float*)d_in[20];
    const float* ln_b    = (const float*)d_in[21];
    const float* pin_w   = (const float*)d_in[22];
    const float* dw_w    = (const float*)d_in[23];
    const float* fft_w   = (const float*)d_in[24];
    const float* pout_w  = (const float*)d_in[25];

    float *t2a, *t2b, *tc, *ty;
    cudaGetSymbolAddress((void**)&t2a, g_buf2a);
    cudaGetSymbolAddress((void**)&t2b, g_buf2b);
    cudaGetSymbolAddress((void**)&tc,  g_bufc);
    cudaGetSymbolAddress((void**)&ty,  g_y);

    bf16* c1bf = (bf16*)t2b;                          // conv1 output [b,128,HW]
    bf16* dwbf = c1bf + (size_t)BB*C2*HWSZ;           // dw output    [b,128,HW]
    fp16* pinh = (fp16*)t2a;
    fp16* gmh  = (fp16*)tc;

    const int GB = NPIX / 128;     // 3136 blocks (128 px each)

    k_zero<<<1, 512>>>();
    k_tables<<<28, 128>>>();
    k_fftmat<<<64, 128>>>(fft_w);
    k_wprep<<<32, 256>>>(conv1_w, 128, WF_CONV1);
    k_wprep<<<16, 256>>>(conv3_w, 64,  WF_CONV3);
    k_wprep<<<32, 256>>>(conv4_w, 128, WF_CONV4);
    k_wprep<<<16, 256>>>(conv5_w, 64,  WF_CONV5);
    k_wprep<<<32, 256>>>(pin_w,   128, WF_PIN);
    k_wprep<<<16, 256>>>(pout_w,  64,  WF_POUT);

    // conv1: LN(n1) + 64->128 + bias  -> bf16
    k_tc<16,1,0,1><<<GB, 256>>>(x, WF_CONV1, conv1_b, n1_w, n1_b, 1e-6f,
                                nullptr, nullptr, nullptr, (float*)c1bf, 128);

    // depthwise pair + conv2 bias (bf16 io) + IN stats + SCA pool partials
    {
        dim3 g(7, 28, BB*CCH), blk(32, 8);
        k_dw_stats2<<<g, blk>>>(c1bf, conv2_w, conv2_b, dwbf);
    }
    // instnorm finish + pool finish + SE
    k_se<<<BB, 64>>>(fc1_w, fc2_w, in_w, in_b);

    // conv3 with inline instnorm-gate-z staging + residual -> fp32 (c1bf region free)
    k_tc<8,4,1,0><<<GB, 256>>>((const float*)dwbf, WF_CONV3, conv3_b, in_w, in_b, 0.f,
                               x, beta, nullptr, (float*)t2b, 64);
    // fused conv4 + SimpleGate + conv5 -> y
    k_tc45<<<GB, 256>>>((const float*)t2b, conv4_b, n2n_w, n2n_b, conv5_b, ty);

    // DFFN: LN + pin (64->128) -> fp16 in g_buf2a
    k_tc<16,1,0,2><<<GB, 256>>>(ty, WF_PIN, nullptr, ln_w, ln_b, 1e-5f,
                                nullptr, nullptr, nullptr, (float*)pinh, 128);
    // patch spectral transform in-place fp16 (skips when identity)
    k_fftapply_rb<<<BB*C2, 128>>>();
    // depthwise pair + gelu gate -> fp16 g_bufc
    {
        dim3 g(7, 28, BB*CCH), blk(32, 8);
        k_dw_gelu<<<g, blk>>>(dw_w);
    }
    // pout (fp16 in) + y -> d_out
    k_tc<8,5,2,0><<<GB, 256>>>((const float*)gmh, WF_POUT, nullptr, nullptr, nullptr, 0.f,
                               nullptr, nullptr, ty, (float*)d_out, 64);
}

// round 15
// speedup vs baseline: 1.6364x; 1.0224x over previous
#include <cuda_runtime.h>
#include <cuda_bf16.h>
#include <cuda_fp16.h>
#include <math.h>

#define BB    8
#define CCH   64
#define C2    128
#define HH    224
#define WWID  224
#define HWSZ  (HH*WWID)          // 50176
#define NPIX  (BB*HWSZ)          // 401408

typedef unsigned long long ull;
typedef __nv_bfloat16 bf16;
typedef __half fp16;

// ---------------- packed f32x2 helpers (used by fftapply) ----------------
__device__ __forceinline__ ull pack2(float x) {
    ull r; asm("mov.b64 %0, {%1, %1};" : "=l"(r) : "f"(x)); return r;
}
__device__ __forceinline__ ull fma2(ull a, ull b, ull c) {
    ull d; asm("fma.rn.f32x2 %0, %1, %2, %3;" : "=l"(d) : "l"(a), "l"(b), "l"(c)); return d;
}

// ---------------- tf32 mma helpers ----------------
__device__ __forceinline__ unsigned cvt_tf32(float f) {
    unsigned u; asm("cvt.rna.tf32.f32 %0, %1;" : "=r"(u) : "f"(f)); return u;
}
__device__ __forceinline__ void mma8(float* c, unsigned a0, unsigned a1,
                                     unsigned a2, unsigned a3, float bx, float by) {
    unsigned b0 = __float_as_uint(bx), b1 = __float_as_uint(by);
    asm("mma.sync.aligned.m16n8k8.row.col.f32.tf32.tf32.f32 "
        "{%0,%1,%2,%3}, {%4,%5,%6,%7}, {%8,%9}, {%0,%1,%2,%3};"
        : "+f"(c[0]), "+f"(c[1]), "+f"(c[2]), "+f"(c[3])
        : "r"(a0), "r"(a1), "r"(a2), "r"(a3), "r"(b0), "r"(b1));
}

// ---------------- scratch (device globals; no allocation allowed) ----------------
static __device__ float g_buf2a[BB*C2*HWSZ];   // fp32 residual / fp16 pin-out+fft
static __device__ float g_buf2b[BB*C2*HWSZ];   // carved: bf16 conv1out/dwout, then fp32 residual
static __device__ float g_bufc [BB*CCH*HWSZ];  // carved: fp16 dffn gelu-gated
static __device__ float g_y    [BB*CCH*HWSZ];  // fp32: NAF output y
static __device__ float g_M    [C2*64*64];     // [c][in][out]
static __device__ __align__(16) float g_wfrag[36864];  // precomputed tf32 B-fragments
static __device__ float g_dctR [CCH*56];
static __device__ float g_dctC [CCH*56];
static __device__ float g_instS[BB*CCH], g_instQ[BB*CCH];
static __device__ float g_instMean[BB*CCH], g_instInv[BB*CCH];
static __device__ float g_scay[BB*CCH], g_scay2[BB*CCH], g_z[BB*CCH];
static __device__ int   g_fftNonId;

// fragment buffer offsets (floats); 64-oc half = 4096 floats
#define WF_CONV1 0
#define WF_CONV3 8192
#define WF_CONV4 12288
#define WF_CONV5 20480
#define WF_PIN   24576
#define WF_POUT  32768

// ---------------- tiny init kernels ----------------
__global__ void k_zero() {
    int t = threadIdx.x;
    if (t < BB*CCH) {
        g_instS[t] = 0.f; g_instQ[t] = 0.f;
        g_scay[t] = 0.f;  g_scay2[t] = 0.f;
    }
    if (t == 0) g_fftNonId = 0;
}

// precompute tf32 weight fragments: w[OC][64] -> fragment order for NT=OC/8
__global__ void k_wprep(const float* __restrict__ w, int OC, int wfoff) {
    int i = blockIdx.x*256 + threadIdx.x;
    if (i >= OC*64) return;
    int k = i & 63, oc = i >> 6;
    int NT = OC >> 3;
    int kt = k >> 3, kk = k & 7, nt = oc >> 3, nn = oc & 7;
    unsigned v = cvt_tf32(__ldg(w + oc*64 + k));
    int idx = ((kt*(NT/2) + (nt>>1))*32 + nn*4 + (kk&3))*4 + ((nt&1)*2 + (kk>>2));
    g_wfrag[wfoff + idx] = __uint_as_float(v);
}

__global__ void k_tables() {
    int t = blockIdx.x * blockDim.x + threadIdx.x;
    if (t >= CCH*56) return;
    int c = t / 56, i = t - c*56;
    const int mx[16] = {0,0,6,0,0,1,1,4,5,1,3,0,0,0,3,2};
    const int my[16] = {0,1,0,5,2,0,2,0,0,6,0,4,6,3,2,5};
    int g = c >> 2;
    int ux = mx[g]*8, uy = my[g]*8;
    float inv = rsqrtf(56.f);
    float rv = cosf((float)M_PI * ux * (i + 0.5f) / 56.f) * inv;
    if (ux) rv *= 1.41421356237f;
    float cv = cosf((float)M_PI * uy * (i + 0.5f) / 56.f) * inv;
    if (uy) cv *= 1.41421356237f;
    g_dctR[t] = rv; g_dctC[t] = cv;
}

__global__ void k_fftmat(const float* __restrict__ fw) {
    int t = blockIdx.x * blockDim.x + threadIdx.x;
    if (t >= C2*64) return;
    int c = t >> 6, in = t & 63, i0 = in >> 3, j0 = in & 7;
    const float c8[8] = {1.f, 0.70710678118f, 0.f, -0.70710678118f,
                         -1.f, -0.70710678118f, 0.f, 0.70710678118f};
    const float s8[8] = {0.f, 0.70710678118f, 1.f, 0.70710678118f,
                         0.f, -0.70710678118f, -1.f, -0.70710678118f};
    int dev = 0;
    for (int p = 0; p < 8; p++) {
        float Gr[5], Gi[5];
        for (int v = 0; v < 5; v++) {
            float gr = 0.f, gi = 0.f;
            for (int u = 0; u < 8; u++) {
                int idx = ((u*(p - i0) - v*j0) % 8 + 8) % 8;
                float w = fw[c*40 + u*5 + v];
                gr += w * c8[idx]; gi += w * s8[idx];
            }
            Gr[v] = gr; Gi[v] = gi;
        }
        for (int q = 0; q < 8; q++) {
            float val = Gr[0] + ((q & 1) ? -Gr[4] : Gr[4]);
            for (int v = 1; v < 4; v++) {
                int k = (v*q) & 7;
                val += 2.f * (Gr[v]*c8[k] - Gi[v]*s8[k]);
            }
            val *= (1.f/64.f);
            int outp = p*8 + q;
            g_M[c*4096 + in*64 + outp] = val;
            float expect = (outp == in) ? 1.f : 0.f;
            if (fabsf(val - expect) > 1e-5f) dev = 1;
        }
    }
    if (dev) g_fftNonId = 1;
}

// =====================================================================
// Tensor-core conv1x1 GEMM.  128 px x 64 oc per block, K=64, tf32 mma.
// HALVES==2: oc-half interleaved in blockIdx.x (A reads L2-dedup'd).
// B fragments precomputed in g_wfrag (L2-resident float4 reads).
// IMODE: 0 plain f32, 1 channel-LN f32, 4 instnorm-gate bf16, 5 plain fp16
// OMODE: 0 acc+bias, 1 x + beta*(acc+bias), 2 acc+add
// OBF:   0 f32 out, 1 bf16 out, 2 fp16 out   (OMODE 0 only)
// =====================================================================
#define APAD 136

template<int HALVES, int IMODE, int OMODE, int OBF>
__global__ __launch_bounds__(256, 3) void k_tc(
    const float* __restrict__ in, int wfoff,
    const float* __restrict__ bias, const float* __restrict__ lnw,
    const float* __restrict__ lnb, float eps,
    const float* __restrict__ xres, const float* __restrict__ beta,
    const float* __restrict__ addsrc, float* __restrict__ out, int ocStride)
{
    __shared__ __align__(16) float ABsm[64*APAD];
    __shared__ float sbias[64];
    __shared__ float sAZ[64], sBZ[64];

    int tid = threadIdx.x;
    int bx = blockIdx.x;
    int tile  = (HALVES == 2) ? (bx >> 1) : bx;
    int obase = (HALVES == 2) ? ((bx & 1) << 6) : 0;
    int pix0 = tile*128;
    int b = pix0 / HWSZ, hw0 = pix0 - b*HWSZ;

    if (tid < 64) sbias[tid] = bias ? __ldg(bias + obase + tid) : 0.f;

    // ---- phase 1: stage A ----
    if (IMODE == 1) {
        int p = tid >> 1, h = tid & 1;
        const float* src = in + (b*64 + h*32)*HWSZ + hw0 + p;
        float v[32];
#pragma unroll
        for (int c = 0; c < 32; c++) v[c] = src[c*HWSZ];
        float s = 0.f;
#pragma unroll
        for (int c = 0; c < 32; c++) s += v[c];
        s += __shfl_xor_sync(0xffffffffu, s, 1);
        float mu = s * (1.f/64.f);
        float q = 0.f;
#pragma unroll
        for (int c = 0; c < 32; c++) { float d = v[c]-mu; q += d*d; }
        q += __shfl_xor_sync(0xffffffffu, q, 1);
        float is = rsqrtf(q*(1.f/64.f) + eps);
#pragma unroll
        for (int c = 0; c < 32; c++) {
            int ch = h*32 + c;
            float val = (v[c]-mu)*is*__ldg(lnw+ch) + __ldg(lnb+ch);
            ABsm[ch*APAD + p] = __uint_as_float(cvt_tf32(val));
        }
    } else if (IMODE == 4) {
        if (tid < 64) {
            int bc = b*64 + tid;
            float iv = g_instInv[bc];
            float A  = iv*__ldg(lnw + tid);
            float z  = g_z[bc];
            sAZ[tid] = A*z;
            sBZ[tid] = (__ldg(lnb + tid) - g_instMean[bc]*A)*z;
        }
        __syncthreads();
        const bf16* inb16 = (const bf16*)in;
        for (int i = tid; i < 8192; i += 256) {
            int px = i & 127, c = i >> 7;
            float a  = __bfloat162float(inb16[(size_t)(b*128 + c)*HWSZ + hw0 + px]);
            float gg = __bfloat162float(inb16[(size_t)(b*128 + 64 + c)*HWSZ + hw0 + px]);
            float val = (a*sAZ[c] + sBZ[c])*gg;
            ABsm[c*APAD + px] = __uint_as_float(cvt_tf32(val));
        }
    } else if (IMODE == 5) {
        const fp16* inh = (const fp16*)in;
        for (int i = tid; i < 8192; i += 256) {
            int px = i & 127, c = i >> 7;
            float val = __half2float(inh[(size_t)(b*64 + c)*HWSZ + hw0 + px]);
            ABsm[c*APAD + px] = __uint_as_float(cvt_tf32(val));
        }
    } else {
        for (int i = tid; i < 8192; i += 256) {
            int px = i & 127, c = i >> 7;
            float val = in[(b*64 + c)*HWSZ + hw0 + px];
            ABsm[c*APAD + px] = __uint_as_float(cvt_tf32(val));
        }
    }
    __syncthreads();

    // ---- phase 2: A fragments to regs ----
    int warp = tid >> 5, lane = tid & 31, g = lane >> 2, tig = lane & 3;
    int pxA = warp*16 + g;
    unsigned afrag[8][4];
#pragma unroll
    for (int kt = 0; kt < 8; kt++) {
        int ca = kt*8 + tig;
        afrag[kt][0] = __float_as_uint(ABsm[ca*APAD + pxA]);
        afrag[kt][1] = __float_as_uint(ABsm[ca*APAD + pxA + 8]);
        afrag[kt][2] = __float_as_uint(ABsm[(ca+4)*APAD + pxA]);
        afrag[kt][3] = __float_as_uint(ABsm[(ca+4)*APAD + pxA + 8]);
    }

    // ---- phase 3: MMA mainloop (NT=8), B fragments from gmem (L2-hot) ----
    const float4* Bg = (const float4*)(g_wfrag + wfoff + obase*64);
    float acc[8][4];
#pragma unroll
    for (int nt = 0; nt < 8; nt++)
#pragma unroll
        for (int u = 0; u < 4; u++) acc[nt][u] = 0.f;

#pragma unroll
    for (int kt = 0; kt < 8; kt++) {
#pragma unroll
        for (int np = 0; np < 4; np++) {
            float4 bb = __ldg(&Bg[(kt*4 + np)*32 + lane]);
            mma8(acc[2*np],   afrag[kt][0], afrag[kt][1], afrag[kt][2], afrag[kt][3], bb.x, bb.y);
            mma8(acc[2*np+1], afrag[kt][0], afrag[kt][1], afrag[kt][2], afrag[kt][3], bb.z, bb.w);
        }
    }

    // ---- epilogue (scattered) ----
    int pxg = hw0 + warp*16 + g;
#pragma unroll
    for (int nt = 0; nt < 8; nt++) {
        int o0 = nt*8 + 2*tig, o1 = o0 + 1;                 // local oc
        size_t base0 = (size_t)(b*ocStride + obase + o0)*HWSZ + pxg;
        size_t base1 = (size_t)(b*ocStride + obase + o1)*HWSZ + pxg;
        float r0 = acc[nt][0], r1 = acc[nt][1], r2 = acc[nt][2], r3 = acc[nt][3];
        if (OMODE == 0) {
            float b0v = sbias[o0], b1v = sbias[o1];
            if (OBF == 1) {
                bf16* ob = (bf16*)out;
                ob[base0]     = __float2bfloat16(r0 + b0v);
                ob[base1]     = __float2bfloat16(r1 + b1v);
                ob[base0 + 8] = __float2bfloat16(r2 + b0v);
                ob[base1 + 8] = __float2bfloat16(r3 + b1v);
            } else if (OBF == 2) {
                fp16* oh = (fp16*)out;
                oh[base0]     = __float2half(r0 + b0v);
                oh[base1]     = __float2half(r1 + b1v);
                oh[base0 + 8] = __float2half(r2 + b0v);
                oh[base1 + 8] = __float2half(r3 + b1v);
            } else {
                out[base0]     = r0 + b0v;
                out[base1]     = r1 + b1v;
                out[base0 + 8] = r2 + b0v;
                out[base1 + 8] = r3 + b1v;
            }
        } else if (OMODE == 1) {
            float b0v = sbias[o0], b1v = sbias[o1];
            float bt0 = __ldg(beta + obase + o0), bt1 = __ldg(beta + obase + o1);
            out[base0]     = fmaf(r0 + b0v, bt0, __ldg(xres + base0));
            out[base1]     = fmaf(r1 + b1v, bt1, __ldg(xres + base1));
            out[base0 + 8] = fmaf(r2 + b0v, bt0, __ldg(xres + base0 + 8));
            out[base1 + 8] = fmaf(r3 + b1v, bt1, __ldg(xres + base1 + 8));
        } else {
            out[base0]     = r0 + __ldg(addsrc + base0);
            out[base1]     = r1 + __ldg(addsrc + base1);
            out[base0 + 8] = r2 + __ldg(addsrc + base0 + 8);
            out[base1 + 8] = r3 + __ldg(addsrc + base1 + 8);
        }
    }
}

// =====================================================================
// Fused conv4 (LN + 64->128) -> SimpleGate -> conv5 (64->64).  NT16 kept.
// =====================================================================
__global__ __launch_bounds__(256, 2) void k_tc45(
    const float* __restrict__ in,
    const float* __restrict__ b4, const float* __restrict__ lnw,
    const float* __restrict__ lnb,
    const float* __restrict__ b5, float* __restrict__ out)
{
    __shared__ __align__(16) float ABsm[64*APAD];
    __shared__ float sb4[128], sb5[64];

    int tid = threadIdx.x;
    int pix0 = blockIdx.x*128;
    int b = pix0 / HWSZ, hw0 = pix0 - b*HWSZ;
    if (tid < 128) sb4[tid] = __ldg(b4 + tid);
    if (tid < 64)  sb5[tid] = __ldg(b5 + tid);

    // stage A with channel-LN (eps 1e-6)
    {
        int p = tid >> 1, h = tid & 1;
        const float* src = in + (b*64 + h*32)*HWSZ + hw0 + p;
        float v[32];
#pragma unroll
        for (int c = 0; c < 32; c++) v[c] = src[c*HWSZ];
        float s = 0.f;
#pragma unroll
        for (int c = 0; c < 32; c++) s += v[c];
        s += __shfl_xor_sync(0xffffffffu, s, 1);
        float mu = s * (1.f/64.f);
        float q = 0.f;
#pragma unroll
        for (int c = 0; c < 32; c++) { float d = v[c]-mu; q += d*d; }
        q += __shfl_xor_sync(0xffffffffu, q, 1);
        float is = rsqrtf(q*(1.f/64.f) + 1e-6f);
#pragma unroll
        for (int c = 0; c < 32; c++) {
            int ch = h*32 + c;
            float val = (v[c]-mu)*is*__ldg(lnw+ch) + __ldg(lnb+ch);
            ABsm[ch*APAD + p] = __uint_as_float(cvt_tf32(val));
        }
    }
    __syncthreads();

    int warp = tid >> 5, lane = tid & 31, g = lane >> 2, tig = lane & 3;
    int pxA = warp*16 + g;
    unsigned afrag[8][4];
#pragma unroll
    for (int kt = 0; kt < 8; kt++) {
        int ca = kt*8 + tig;
        afrag[kt][0] = __float_as_uint(ABsm[ca*APAD + pxA]);
        afrag[kt][1] = __float_as_uint(ABsm[ca*APAD + pxA + 8]);
        afrag[kt][2] = __float_as_uint(ABsm[(ca+4)*APAD + pxA]);
        afrag[kt][3] = __float_as_uint(ABsm[(ca+4)*APAD + pxA + 8]);
    }

    // MMA 1 (conv4, NT=16) — B from gmem fragments
    const float4* B4g = (const float4*)(g_wfrag + WF_CONV4);
    float acc[16][4];
#pragma unroll
    for (int nt = 0; nt < 16; nt++)
#pragma unroll
        for (int u = 0; u < 4; u++) acc[nt][u] = 0.f;
#pragma unroll
    for (int kt = 0; kt < 8; kt++) {
#pragma unroll
        for (int np = 0; np < 8; np++) {
            float4 bb = __ldg(&B4g[(kt*8 + np)*32 + lane]);
            mma8(acc[2*np],   afrag[kt][0], afrag[kt][1], afrag[kt][2], afrag[kt][3], bb.x, bb.y);
            mma8(acc[2*np+1], afrag[kt][0], afrag[kt][1], afrag[kt][2], afrag[kt][3], bb.z, bb.w);
        }
    }

    // SimpleGate in registers
    float gated[8][4];
#pragma unroll
    for (int nt = 0; nt < 8; nt++) {
        int o0 = nt*8 + 2*tig, o1 = o0 + 1;
        gated[nt][0] = (acc[nt][0] + sb4[o0]) * (acc[nt+8][0] + sb4[o0+64]);
        gated[nt][1] = (acc[nt][1] + sb4[o1]) * (acc[nt+8][1] + sb4[o1+64]);
        gated[nt][2] = (acc[nt][2] + sb4[o0]) * (acc[nt+8][2] + sb4[o0+64]);
        gated[nt][3] = (acc[nt][3] + sb4[o1]) * (acc[nt+8][3] + sb4[o1+64]);
    }
    __syncthreads();

    // route gated through smem as new A matrix [ch][px]
#pragma unroll
    for (int nt = 0; nt < 8; nt++) {
        int o0 = nt*8 + 2*tig, o1 = o0 + 1;
        ABsm[o0*APAD + pxA]     = __uint_as_float(cvt_tf32(gated[nt][0]));
        ABsm[o1*APAD + pxA]     = __uint_as_float(cvt_tf32(gated[nt][1]));
        ABsm[o0*APAD + pxA + 8] = __uint_as_float(cvt_tf32(gated[nt][2]));
        ABsm[o1*APAD + pxA + 8] = __uint_as_float(cvt_tf32(gated[nt][3]));
    }
    __syncthreads();

    unsigned af2[8][4];
#pragma unroll
    for (int kt = 0; kt < 8; kt++) {
        int ca = kt*8 + tig;
        af2[kt][0] = __float_as_uint(ABsm[ca*APAD + pxA]);
        af2[kt][1] = __float_as_uint(ABsm[ca*APAD + pxA + 8]);
        af2[kt][2] = __float_as_uint(ABsm[(ca+4)*APAD + pxA]);
        af2[kt][3] = __float_as_uint(ABsm[(ca+4)*APAD + pxA + 8]);
    }

    // MMA 2 (conv5, NT=8) — B from gmem fragments
    const float4* B5g = (const float4*)(g_wfrag + WF_CONV5);
    float a5[8][4];
#pragma unroll
    for (int nt = 0; nt < 8; nt++)
#pragma unroll
        for (int u = 0; u < 4; u++) a5[nt][u] = 0.f;
#pragma unroll
    for (int kt = 0; kt < 8; kt++) {
#pragma unroll
        for (int np = 0; np < 4; np++) {
            float4 bb = __ldg(&B5g[(kt*4 + np)*32 + lane]);
            mma8(a5[2*np],   af2[kt][0], af2[kt][1], af2[kt][2], af2[kt][3], bb.x, bb.y);
            mma8(a5[2*np+1], af2[kt][0], af2[kt][1], af2[kt][2], af2[kt][3], bb.z, bb.w);
        }
    }

    int pxg = hw0 + warp*16 + g;
#pragma unroll
    for (int nt = 0; nt < 8; nt++) {
        int o0 = nt*8 + 2*tig, o1 = o0 + 1;
        int base0 = (b*64 + o0)*HWSZ + pxg;
        int base1 = (b*64 + o1)*HWSZ + pxg;
        out[base0]     = a5[nt][0] + sb5[o0];
        out[base1]     = a5[nt][1] + sb5[o1];
        out[base0 + 8] = a5[nt][2] + sb5[o0];
        out[base1 + 8] = a5[nt][3] + sb5[o1];
    }
}

// ---------------- depthwise 3x3 pair (c, c+64), bf16 io ----------------
__global__ __launch_bounds__(256) void k_dw_stats2(
    const bf16* __restrict__ in, const float* __restrict__ w,
    const float* __restrict__ bias, bf16* __restrict__ out)
{
    int bc = blockIdx.z;                 // b*64 + c
    int c = bc & 63, b = bc >> 6;
    int ca = b*128 + c, cg = ca + 64;
    __shared__ float ta[10][34], tg[10][34];
    __shared__ float rA[256], rB[256], rC[256], rD[256];
    int tx0 = blockIdx.x*32, ty0 = blockIdx.y*8;
    int tid = threadIdx.y*32 + threadIdx.x;
    const bf16* sa = in + (size_t)ca*HWSZ;
    const bf16* sg = in + (size_t)cg*HWSZ;
    for (int i = tid; i < 340; i += 256) {
        int r = i/34, cc = i - r*34;
        int gy = ty0 + r - 1, gx = tx0 + cc - 1;
        bool ok = (gy >= 0 && gy < HH && gx >= 0 && gx < WWID);
        ta[r][cc] = ok ? __bfloat162float(sa[gy*WWID+gx]) : 0.f;
        tg[r][cc] = ok ? __bfloat162float(sg[gy*WWID+gx]) : 0.f;
    }
    __syncthreads();
    float da = bias[c], dg = bias[c+64];
#pragma unroll
    for (int di = 0; di < 3; di++)
#pragma unroll
        for (int dj = 0; dj < 3; dj++) {
            da += w[c*9 + di*3 + dj]      * ta[threadIdx.y+di][threadIdx.x+dj];
            dg += w[(64+c)*9 + di*3 + dj] * tg[threadIdx.y+di][threadIdx.x+dj];
        }
    int gy = ty0 + threadIdx.y, gx = tx0 + threadIdx.x;
    out[(size_t)ca*HWSZ + gy*WWID + gx] = __float2bfloat16(da);
    out[(size_t)cg*HWSZ + gy*WWID + gx] = __float2bfloat16(dg);

    float wd = g_dctR[c*56 + (gy >> 2)] * g_dctC[c*56 + (gx >> 2)];
    rA[tid] = da; rB[tid] = da*da; rC[tid] = wd*da*dg; rD[tid] = wd*dg;
    __syncthreads();
    for (int s = 128; s > 0; s >>= 1) {
        if (tid < s) {
            rA[tid] += rA[tid+s]; rB[tid] += rB[tid+s];
            rC[tid] += rC[tid+s]; rD[tid] += rD[tid+s];
        }
        __syncthreads();
    }
    if (tid == 0) {
        atomicAdd(&g_instS[bc], rA[0]);
        atomicAdd(&g_instQ[bc], rB[0]);
        atomicAdd(&g_scay[bc],  rC[0]);
        atomicAdd(&g_scay2[bc], rD[0]);
    }
}

// ---------------- instnorm finish + SCA pool finish + SE ----------------
__global__ void k_se(const float* __restrict__ fc1, const float* __restrict__ fc2,
                     const float* __restrict__ inw, const float* __restrict__ inb) {
    int b = blockIdx.x, c = threadIdx.x;
    int bc = b*64 + c;
    float m = g_instS[bc] * (1.f/HWSZ);
    float var = g_instQ[bc] * (1.f/HWSZ) - m*m;
    float iv = rsqrtf(var + 1e-5f);
    g_instMean[bc] = m; g_instInv[bc] = iv;
    float A = iv*inw[c];
    __shared__ float ys[64];
    ys[c] = (A*g_scay[bc] + (inb[c] - m*A)*g_scay2[bc]) * (1.f/16.f);
    __syncthreads();
    float h[4];
#pragma unroll
    for (int j = 0; j < 4; j++) {
        float s = 0.f;
#pragma unroll
        for (int k = 0; k < 64; k++) s += fc1[j*64 + k] * ys[k];
        h[j] = fmaxf(s, 0.f);
    }
    float z = 0.f;
#pragma unroll
    for (int j = 0; j < 4; j++) z += fc2[c*4 + j] * h[j];
    g_z[bc] = 1.f / (1.f + expf(-z));
}

// ---------------- per-patch spectral transform, in-place fp16 ----------------
__global__ __launch_bounds__(128) void k_fftapply_rb() {
    if (g_fftNonId == 0) return;
    int bc = blockIdx.x;
    int c  = bc & 127;
    __shared__ __align__(16) float Ms[4096];
    __shared__ __align__(16) float pat[64*60];
    int tid = threadIdx.x;
    const float* msrc = g_M + c*4096;
    for (int i = tid; i < 4096; i += 128) Ms[i] = msrc[i];
    fp16* plane = (fp16*)g_buf2a + (size_t)bc*HWSZ;
    int og = tid & 15, pg = tid >> 4;
    for (int bp = 0; bp < 14; bp++) {
        for (int i = tid; i < 3584; i += 128) {
            int r = i / 224, wcol = i - r*224;
            int p = r & 7, band = r >> 3, pc = wcol >> 3, q = wcol & 7;
            pat[(p*8+q)*60 + band*28 + pc] = __half2float(plane[(bp*16 + r)*224 + wcol]);
        }
        __syncthreads();
        ull acc[4][4];
#pragma unroll
        for (int j = 0; j < 4; j++)
#pragma unroll
            for (int u = 0; u < 4; u++) acc[j][u] = 0ULL;
        if (pg < 7) {
            const float* pI = pat + pg*8;
            for (int k = 0; k < 64; k++) {
                ulonglong2 va = *(const ulonglong2*)(pI + k*60);
                ulonglong2 vb = *(const ulonglong2*)(pI + k*60 + 4);
                float4 wv = *(const float4*)(Ms + k*64 + og*4);
                float wav[4] = {wv.x, wv.y, wv.z, wv.w};
#pragma unroll
                for (int j = 0; j < 4; j++) {
                    ull wp = pack2(wav[j]);
                    acc[j][0] = fma2(va.x, wp, acc[j][0]);
                    acc[j][1] = fma2(va.y, wp, acc[j][1]);
                    acc[j][2] = fma2(vb.x, wp, acc[j][2]);
                    acc[j][3] = fma2(vb.y, wp, acc[j][3]);
                }
            }
        }
        __syncthreads();
        if (pg < 7) {
#pragma unroll
            for (int j = 0; j < 4; j++) {
                int o = og*4 + j;
                ulonglong2 s0, s1;
                s0.x = acc[j][0]; s0.y = acc[j][1];
                s1.x = acc[j][2]; s1.y = acc[j][3];
                *(ulonglong2*)(pat + o*60 + pg*8) = s0;
                *(ulonglong2*)(pat + o*60 + pg*8 + 4) = s1;
            }
        }
        __syncthreads();
        for (int i = tid; i < 3584; i += 128) {
            int r = i / 224, wcol = i - r*224;
            int p = r & 7, band = r >> 3, pc = wcol >> 3, q = wcol & 7;
            plane[(bp*16 + r)*224 + wcol] = __float2half(pat[(p*8+q)*60 + band*28 + pc]);
        }
        __syncthreads();
    }
}

// ---------------- DFFN depthwise 3x3 pair + gelu gate (fp16 io) ----------------
__global__ __launch_bounds__(256) void k_dw_gelu(const float* __restrict__ w) {
    int bc = blockIdx.z;
    int c = bc & 63, b = bc >> 6;
    __shared__ float t1[10][34], t2[10][34];
    int tx0 = blockIdx.x*32, ty0 = blockIdx.y*8;
    int tid = threadIdx.y*32 + threadIdx.x;
    const fp16* s1 = (const fp16*)g_buf2a + (size_t)(b*128 + c)*HWSZ;
    const fp16* s2 = (const fp16*)g_buf2a + (size_t)(b*128 + 64 + c)*HWSZ;
    for (int i = tid; i < 340; i += 256) {
        int r = i/34, cc = i - r*34;
        int gy = ty0 + r - 1, gx = tx0 + cc - 1;
        bool ok = (gy >= 0 && gy < HH && gx >= 0 && gx < WWID);
        t1[r][cc] = ok ? __half2float(s1[gy*WWID+gx]) : 0.f;
        t2[r][cc] = ok ? __half2float(s2[gy*WWID+gx]) : 0.f;
    }
    __syncthreads();
    float d1 = 0.f, d2 = 0.f;
#pragma unroll
    for (int di = 0; di < 3; di++)
#pragma unroll
        for (int dj = 0; dj < 3; dj++) {
            d1 += w[c*9 + di*3 + dj]      * t1[threadIdx.y+di][threadIdx.x+dj];
            d2 += w[(64+c)*9 + di*3 + dj] * t2[threadIdx.y+di][threadIdx.x+dj];
        }
    float gel = 0.5f * d1 * (1.f + erff(d1 * 0.70710678118f));
    ((fp16*)g_bufc)[(size_t)bc*HWSZ + (ty0+threadIdx.y)*WWID + tx0 + threadIdx.x]
        = __float2half(gel * d2);
}

// ---------------- launch ----------------
extern "C" void kernel_launch(void* const* d_in, const int* in_sizes, int n_in,
                              void* d_out, int out_size)
{
    (void)in_sizes; (void)n_in; (void)out_size;
    const float* x       = (const float*)d_in[0];
    const float* n1_w    = (const float*)d_in[1];
    const float* n1_b    = (const float*)d_in[2];
    const float* conv1_w = (const float*)d_in[3];
    const float* conv1_b = (const float*)d_in[4];
    const float* conv2_w = (const float*)d_in[5];
    const float* conv2_b = (const float*)d_in[6];
    const float* in_w    = (const float*)d_in[7];
    const float* in_b    = (const float*)d_in[8];
    const float* fc1_w   = (const float*)d_in[9];
    const float* fc2_w   = (const float*)d_in[10];
    const float* conv3_w = (const float*)d_in[11];
    const float* conv3_b = (const float*)d_in[12];
    const float* beta    = (const float*)d_in[13];
    const float* n2n_w   = (const float*)d_in[14];
    const float* n2n_b   = (const float*)d_in[15];
    const float* conv4_w = (const float*)d_in[16];
    const float* conv4_b = (const float*)d_in[17];
    const float* conv5_w = (const float*)d_in[18];
    const float* conv5_b = (const float*)d_in[19];
    const float* ln_w    = (const float*)d_in[20];
    const float* ln_b    = (const float*)d_in[21];
    const float* pin_w   = (const float*)d_in[22];
    const float* dw_w    = (const float*)d_in[23];
    const float* fft_w   = (const float*)d_in[24];
    const float* pout_w  = (const float*)d_in[25];

    float *t2a, *t2b, *tc, *ty;
    cudaGetSymbolAddress((void**)&t2a, g_buf2a);
    cudaGetSymbolAddress((void**)&t2b, g_buf2b);
    cudaGetSymbolAddress((void**)&tc,  g_bufc);
    cudaGetSymbolAddress((void**)&ty,  g_y);

    bf16* c1bf = (bf16*)t2b;                          // conv1 output [b,128,HW]
    bf16* dwbf = c1bf + (size_t)BB*C2*HWSZ;           // dw output    [b,128,HW]
    fp16* pinh = (fp16*)t2a;
    fp16* gmh  = (fp16*)tc;

    const int GB = NPIX / 128;     // 3136 tiles (128 px each)

    k_zero<<<1, 512>>>();
    k_tables<<<28, 128>>>();
    k_fftmat<<<64, 128>>>(fft_w);
    // 64-oc halves for split GEMMs; conv4 stays NT16 (fused kernel), conv5 NT8
    k_wprep<<<16, 256>>>(conv1_w,        64, WF_CONV1);
    k_wprep<<<16, 256>>>(conv1_w + 4096, 64, WF_CONV1 + 4096);
    k_wprep<<<16, 256>>>(conv3_w,        64, WF_CONV3);
    k_wprep<<<32, 256>>>(conv4_w,       128, WF_CONV4);
    k_wprep<<<16, 256>>>(conv5_w,        64, WF_CONV5);
    k_wprep<<<16, 256>>>(pin_w,          64, WF_PIN);
    k_wprep<<<16, 256>>>(pin_w + 4096,   64, WF_PIN + 4096);
    k_wprep<<<16, 256>>>(pout_w,         64, WF_POUT);

    // conv1: LN(n1) + 64->128 + bias  -> bf16 (oc halves interleaved)
    k_tc<2,1,0,1><<<GB*2, 256>>>(x, WF_CONV1, conv1_b, n1_w, n1_b, 1e-6f,
                                 nullptr, nullptr, nullptr, (float*)c1bf, 128);

    // depthwise pair + conv2 bias (bf16 io) + IN stats + SCA pool partials
    {
        dim3 g(7, 28, BB*CCH), blk(32, 8);
        k_dw_stats2<<<g, blk>>>(c1bf, conv2_w, conv2_b, dwbf);
    }
    // instnorm finish + pool finish + SE
    k_se<<<BB, 64>>>(fc1_w, fc2_w, in_w, in_b);

    // conv3 with inline instnorm-gate-z staging + residual -> fp32 (c1bf region free)
    k_tc<1,4,1,0><<<GB, 256>>>((const float*)dwbf, WF_CONV3, conv3_b, in_w, in_b, 0.f,
                               x, beta, nullptr, (float*)t2b, 64);
    // fused conv4 + SimpleGate + conv5 -> y
    k_tc45<<<GB, 256>>>((const float*)t2b, conv4_b, n2n_w, n2n_b, conv5_b, ty);

    // DFFN: LN + pin (64->128) -> fp16 in g_buf2a (oc halves interleaved)
    k_tc<2,1,0,2><<<GB*2, 256>>>(ty, WF_PIN, nullptr, ln_w, ln_b, 1e-5f,
                                 nullptr, nullptr, nullptr, (float*)pinh, 128);
    // patch spectral transform in-place fp16 (skips when identity)
    k_fftapply_rb<<<BB*C2, 128>>>();
    // depthwise pair + gelu gate -> fp16 g_bufc
    {
        dim3 g(7, 28, BB*CCH), blk(32, 8);
        k_dw_gelu<<<g, blk>>>(dw_w);
    }
    // pout (fp16 in) + y -> d_out
    k_tc<1,5,2,0><<<GB, 256>>>((const float*)gmh, WF_POUT, nullptr, nullptr, nullptr, 0.f,
                               nullptr, nullptr, ty, (float*)d_out, 64);
}

// round 17
// speedup vs baseline: 1.6373x; 1.0005x over previous
#include <cuda_runtime.h>
#include <cuda_bf16.h>
#include <cuda_fp16.h>
#include <math.h>

#define BB    8
#define CCH   64
#define C2    128
#define HH    224
#define WWID  224
#define HWSZ  (HH*WWID)          // 50176
#define NPIX  (BB*HWSZ)          // 401408

typedef unsigned long long ull;
typedef __nv_bfloat16 bf16;
typedef __half fp16;

// ---------------- packed f32x2 helpers (used by fftapply) ----------------
__device__ __forceinline__ ull pack2(float x) {
    ull r; asm("mov.b64 %0, {%1, %1};" : "=l"(r) : "f"(x)); return r;
}
__device__ __forceinline__ ull fma2(ull a, ull b, ull c) {
    ull d; asm("fma.rn.f32x2 %0, %1, %2, %3;" : "=l"(d) : "l"(a), "l"(b), "l"(c)); return d;
}

// ---------------- tf32 mma helpers ----------------
__device__ __forceinline__ unsigned cvt_tf32(float f) {
    unsigned u; asm("cvt.rna.tf32.f32 %0, %1;" : "=r"(u) : "f"(f)); return u;
}
__device__ __forceinline__ void mma8(float* c, unsigned a0, unsigned a1,
                                     unsigned a2, unsigned a3, float bx, float by) {
    unsigned b0 = __float_as_uint(bx), b1 = __float_as_uint(by);
    asm("mma.sync.aligned.m16n8k8.row.col.f32.tf32.tf32.f32 "
        "{%0,%1,%2,%3}, {%4,%5,%6,%7}, {%8,%9}, {%0,%1,%2,%3};"
        : "+f"(c[0]), "+f"(c[1]), "+f"(c[2]), "+f"(c[3])
        : "r"(a0), "r"(a1), "r"(a2), "r"(a3), "r"(b0), "r"(b1));
}

// ---------------- scratch (device globals; no allocation allowed) ----------------
static __device__ float g_buf2a[BB*C2*HWSZ];   // fp16 pin-out+fft
static __device__ float g_buf2b[BB*C2*HWSZ];   // bf16 conv1out/dwout; fp16 residual
static __device__ float g_bufc [BB*CCH*HWSZ];  // fp16 dffn gelu-gated
static __device__ float g_y    [BB*CCH*HWSZ];  // fp16 NAF output y
static __device__ float g_M    [C2*64*64];     // [c][in][out]
static __device__ __align__(16) float g_wfrag[36864];  // precomputed tf32 B-fragments
static __device__ float g_dctR [CCH*56];
static __device__ float g_dctC [CCH*56];
static __device__ float g_instS[BB*CCH], g_instQ[BB*CCH];
static __device__ float g_instMean[BB*CCH], g_instInv[BB*CCH];
static __device__ float g_scay[BB*CCH], g_scay2[BB*CCH], g_z[BB*CCH];
static __device__ int   g_fftNonId;   // zero-initialized; only ever SET (idempotent)

// fragment buffer offsets (floats); 64-oc half = 4096 floats
#define WF_CONV1 0
#define WF_CONV3 8192
#define WF_CONV4 12288
#define WF_CONV5 20480
#define WF_PIN   24576
#define WF_POUT  32768

// ---------------- fused init: zero stats + DCT tables + fft matrix ----------------
__global__ void k_init(const float* __restrict__ fw) {
    int t = blockIdx.x*128 + threadIdx.x;         // 64 blocks x 128 = 8192
    if (t < BB*CCH) {
        g_instS[t] = 0.f; g_instQ[t] = 0.f;
        g_scay[t] = 0.f;  g_scay2[t] = 0.f;
    }
    if (t < CCH*56) {
        int c = t / 56, i = t - c*56;
        const int mx[16] = {0,0,6,0,0,1,1,4,5,1,3,0,0,0,3,2};
        const int my[16] = {0,1,0,5,2,0,2,0,0,6,0,4,6,3,2,5};
        int g = c >> 2;
        int ux = mx[g]*8, uy = my[g]*8;
        float inv = rsqrtf(56.f);
        float rv = cosf((float)M_PI * ux * (i + 0.5f) / 56.f) * inv;
        if (ux) rv *= 1.41421356237f;
        float cv = cosf((float)M_PI * uy * (i + 0.5f) / 56.f) * inv;
        if (uy) cv *= 1.41421356237f;
        g_dctR[t] = rv; g_dctC[t] = cv;
    }
    // fft matrix (all 8192 threads)
    {
        int c = t >> 6, in = t & 63, i0 = in >> 3, j0 = in & 7;
        const float c8[8] = {1.f, 0.70710678118f, 0.f, -0.70710678118f,
                             -1.f, -0.70710678118f, 0.f, 0.70710678118f};
        const float s8[8] = {0.f, 0.70710678118f, 1.f, 0.70710678118f,
                             0.f, -0.70710678118f, -1.f, -0.70710678118f};
        int dev = 0;
        for (int p = 0; p < 8; p++) {
            float Gr[5], Gi[5];
            for (int v = 0; v < 5; v++) {
                float gr = 0.f, gi = 0.f;
                for (int u = 0; u < 8; u++) {
                    int idx = ((u*(p - i0) - v*j0) % 8 + 8) % 8;
                    float w = fw[c*40 + u*5 + v];
                    gr += w * c8[idx]; gi += w * s8[idx];
                }
                Gr[v] = gr; Gi[v] = gi;
            }
            for (int q = 0; q < 8; q++) {
                float val = Gr[0] + ((q & 1) ? -Gr[4] : Gr[4]);
                for (int v = 1; v < 4; v++) {
                    int k = (v*q) & 7;
                    val += 2.f * (Gr[v]*c8[k] - Gi[v]*s8[k]);
                }
                val *= (1.f/64.f);
                int outp = p*8 + q;
                g_M[c*4096 + in*64 + outp] = val;
                float expect = (outp == in) ? 1.f : 0.f;
                if (fabsf(val - expect) > 1e-5f) dev = 1;
            }
        }
        if (dev) g_fftNonId = 1;
    }
}

// ---------------- all weight fragments in one launch ----------------
__global__ void k_wprep_all(
    const float* __restrict__ w1, const float* __restrict__ w3,
    const float* __restrict__ w4, const float* __restrict__ w5,
    const float* __restrict__ wp, const float* __restrict__ wo)
{
    int seg = blockIdx.y;
    const float* w; int OC, wfoff;
    switch (seg) {
        case 0: w = w1;        OC = 64;  wfoff = WF_CONV1;        break;
        case 1: w = w1 + 4096; OC = 64;  wfoff = WF_CONV1 + 4096; break;
        case 2: w = w3;        OC = 64;  wfoff = WF_CONV3;        break;
        case 3: w = w4;        OC = 128; wfoff = WF_CONV4;        break;
        case 4: w = w5;        OC = 64;  wfoff = WF_CONV5;        break;
        case 5: w = wp;        OC = 64;  wfoff = WF_PIN;          break;
        case 6: w = wp + 4096; OC = 64;  wfoff = WF_PIN + 4096;   break;
        default:w = wo;        OC = 64;  wfoff = WF_POUT;         break;
    }
    int i = blockIdx.x*256 + threadIdx.x;
    if (i >= OC*64) return;
    int k = i & 63, oc = i >> 6;
    int NT = OC >> 3;
    int kt = k >> 3, kk = k & 7, nt = oc >> 3, nn = oc & 7;
    unsigned v = cvt_tf32(__ldg(w + oc*64 + k));
    int idx = ((kt*(NT/2) + (nt>>1))*32 + nn*4 + (kk&3))*4 + ((nt&1)*2 + (kk>>2));
    g_wfrag[wfoff + idx] = __uint_as_float(v);
}

// =====================================================================
// Tensor-core conv1x1 GEMM.  128 px x 64 oc per block, K=64, tf32 mma.
// HALVES==2: oc-half interleaved in blockIdx.x.
// IMODE: 0 f32, 1 LN f32, 4 instnorm-gate bf16, 5 plain fp16, 6 LN fp16
// OMODE: 0 acc+bias, 1 x + beta*(acc+bias), 2 acc+add
// OBF:   OMODE0: 0 f32 / 1 bf16 / 2 fp16 out
//        OMODE1: 2 => fp16 out
//        OMODE2: 2 => addsrc fp16 (out f32)
// =====================================================================
#define APAD 136

template<int HALVES, int IMODE, int OMODE, int OBF>
__global__ __launch_bounds__(256, 3) void k_tc(
    const float* __restrict__ in, int wfoff,
    const float* __restrict__ bias, const float* __restrict__ lnw,
    const float* __restrict__ lnb, float eps,
    const float* __restrict__ xres, const float* __restrict__ beta,
    const float* __restrict__ addsrc, float* __restrict__ out, int ocStride)
{
    __shared__ __align__(16) float ABsm[64*APAD];
    __shared__ float sbias[64];
    __shared__ float sAZ[64], sBZ[64];

    int tid = threadIdx.x;
    int bx = blockIdx.x;
    int tile  = (HALVES == 2) ? (bx >> 1) : bx;
    int obase = (HALVES == 2) ? ((bx & 1) << 6) : 0;
    int pix0 = tile*128;
    int b = pix0 / HWSZ, hw0 = pix0 - b*HWSZ;

    if (tid < 64) sbias[tid] = bias ? __ldg(bias + obase + tid) : 0.f;

    // ---- phase 1: stage A ----
    if (IMODE == 1 || IMODE == 6) {
        int p = tid >> 1, h = tid & 1;
        float v[32];
        if (IMODE == 1) {
            const float* src = in + (b*64 + h*32)*HWSZ + hw0 + p;
#pragma unroll
            for (int c = 0; c < 32; c++) v[c] = src[c*HWSZ];
        } else {
            const fp16* src = (const fp16*)in + (size_t)(b*64 + h*32)*HWSZ + hw0 + p;
#pragma unroll
            for (int c = 0; c < 32; c++) v[c] = __half2float(src[c*HWSZ]);
        }
        float s = 0.f;
#pragma unroll
        for (int c = 0; c < 32; c++) s += v[c];
        s += __shfl_xor_sync(0xffffffffu, s, 1);
        float mu = s * (1.f/64.f);
        float q = 0.f;
#pragma unroll
        for (int c = 0; c < 32; c++) { float d = v[c]-mu; q += d*d; }
        q += __shfl_xor_sync(0xffffffffu, q, 1);
        float is = rsqrtf(q*(1.f/64.f) + eps);
#pragma unroll
        for (int c = 0; c < 32; c++) {
            int ch = h*32 + c;
            float val = (v[c]-mu)*is*__ldg(lnw+ch) + __ldg(lnb+ch);
            ABsm[ch*APAD + p] = __uint_as_float(cvt_tf32(val));
        }
    } else if (IMODE == 4) {
        if (tid < 64) {
            int bc = b*64 + tid;
            float iv = g_instInv[bc];
            float A  = iv*__ldg(lnw + tid);
            float z  = g_z[bc];
            sAZ[tid] = A*z;
            sBZ[tid] = (__ldg(lnb + tid) - g_instMean[bc]*A)*z;
        }
        __syncthreads();
        const bf16* inb16 = (const bf16*)in;
        for (int i = tid; i < 8192; i += 256) {
            int px = i & 127, c = i >> 7;
            float a  = __bfloat162float(inb16[(size_t)(b*128 + c)*HWSZ + hw0 + px]);
            float gg = __bfloat162float(inb16[(size_t)(b*128 + 64 + c)*HWSZ + hw0 + px]);
            float val = (a*sAZ[c] + sBZ[c])*gg;
            ABsm[c*APAD + px] = __uint_as_float(cvt_tf32(val));
        }
    } else if (IMODE == 5) {
        const fp16* inh = (const fp16*)in;
        for (int i = tid; i < 8192; i += 256) {
            int px = i & 127, c = i >> 7;
            float val = __half2float(inh[(size_t)(b*64 + c)*HWSZ + hw0 + px]);
            ABsm[c*APAD + px] = __uint_as_float(cvt_tf32(val));
        }
    } else {
        for (int i = tid; i < 8192; i += 256) {
            int px = i & 127, c = i >> 7;
            float val = in[(b*64 + c)*HWSZ + hw0 + px];
            ABsm[c*APAD + px] = __uint_as_float(cvt_tf32(val));
        }
    }
    __syncthreads();

    // ---- phase 2: A fragments to regs ----
    int warp = tid >> 5, lane = tid & 31, g = lane >> 2, tig = lane & 3;
    int pxA = warp*16 + g;
    unsigned afrag[8][4];
#pragma unroll
    for (int kt = 0; kt < 8; kt++) {
        int ca = kt*8 + tig;
        afrag[kt][0] = __float_as_uint(ABsm[ca*APAD + pxA]);
        afrag[kt][1] = __float_as_uint(ABsm[ca*APAD + pxA + 8]);
        afrag[kt][2] = __float_as_uint(ABsm[(ca+4)*APAD + pxA]);
        afrag[kt][3] = __float_as_uint(ABsm[(ca+4)*APAD + pxA + 8]);
    }

    // ---- phase 3: MMA mainloop (NT=8), B fragments from gmem (L2-hot) ----
    const float4* Bg = (const float4*)(g_wfrag + wfoff + obase*64);
    float acc[8][4];
#pragma unroll
    for (int nt = 0; nt < 8; nt++)
#pragma unroll
        for (int u = 0; u < 4; u++) acc[nt][u] = 0.f;

#pragma unroll
    for (int kt = 0; kt < 8; kt++) {
#pragma unroll
        for (int np = 0; np < 4; np++) {
            float4 bb = __ldg(&Bg[(kt*4 + np)*32 + lane]);
            mma8(acc[2*np],   afrag[kt][0], afrag[kt][1], afrag[kt][2], afrag[kt][3], bb.x, bb.y);
            mma8(acc[2*np+1], afrag[kt][0], afrag[kt][1], afrag[kt][2], afrag[kt][3], bb.z, bb.w);
        }
    }

    // ---- epilogue (scattered) ----
    int pxg = hw0 + warp*16 + g;
#pragma unroll
    for (int nt = 0; nt < 8; nt++) {
        int o0 = nt*8 + 2*tig, o1 = o0 + 1;                 // local oc
        size_t base0 = (size_t)(b*ocStride + obase + o0)*HWSZ + pxg;
        size_t base1 = (size_t)(b*ocStride + obase + o1)*HWSZ + pxg;
        float r0 = acc[nt][0], r1 = acc[nt][1], r2 = acc[nt][2], r3 = acc[nt][3];
        if (OMODE == 0) {
            float b0v = sbias[o0], b1v = sbias[o1];
            if (OBF == 1) {
                bf16* ob = (bf16*)out;
                ob[base0]     = __float2bfloat16(r0 + b0v);
                ob[base1]     = __float2bfloat16(r1 + b1v);
                ob[base0 + 8] = __float2bfloat16(r2 + b0v);
                ob[base1 + 8] = __float2bfloat16(r3 + b1v);
            } else if (OBF == 2) {
                fp16* oh = (fp16*)out;
                oh[base0]     = __float2half(r0 + b0v);
                oh[base1]     = __float2half(r1 + b1v);
                oh[base0 + 8] = __float2half(r2 + b0v);
                oh[base1 + 8] = __float2half(r3 + b1v);
            } else {
                out[base0]     = r0 + b0v;
                out[base1]     = r1 + b1v;
                out[base0 + 8] = r2 + b0v;
                out[base1 + 8] = r3 + b1v;
            }
        } else if (OMODE == 1) {
            float b0v = sbias[o0], b1v = sbias[o1];
            float bt0 = __ldg(beta + obase + o0), bt1 = __ldg(beta + obase + o1);
            float s0 = fmaf(r0 + b0v, bt0, __ldg(xres + base0));
            float s1 = fmaf(r1 + b1v, bt1, __ldg(xres + base1));
            float s2 = fmaf(r2 + b0v, bt0, __ldg(xres + base0 + 8));
            float s3 = fmaf(r3 + b1v, bt1, __ldg(xres + base1 + 8));
            if (OBF == 2) {
                fp16* oh = (fp16*)out;
                oh[base0]     = __float2half(s0);
                oh[base1]     = __float2half(s1);
                oh[base0 + 8] = __float2half(s2);
                oh[base1 + 8] = __float2half(s3);
            } else {
                out[base0] = s0; out[base1] = s1;
                out[base0 + 8] = s2; out[base1 + 8] = s3;
            }
        } else {
            if (OBF == 2) {
                const fp16* ah = (const fp16*)addsrc;
                out[base0]     = r0 + __half2float(ah[base0]);
                out[base1]     = r1 + __half2float(ah[base1]);
                out[base0 + 8] = r2 + __half2float(ah[base0 + 8]);
                out[base1 + 8] = r3 + __half2float(ah[base1 + 8]);
            } else {
                out[base0]     = r0 + __ldg(addsrc + base0);
                out[base1]     = r1 + __ldg(addsrc + base1);
                out[base0 + 8] = r2 + __ldg(addsrc + base0 + 8);
                out[base1 + 8] = r3 + __ldg(addsrc + base1 + 8);
            }
        }
    }
}

// =====================================================================
// Fused conv4 (LN + 64->128) -> SimpleGate -> conv5 (64->64).
// Residual input fp16, y output fp16.
// =====================================================================
__global__ __launch_bounds__(256, 2) void k_tc45(
    const fp16* __restrict__ in,
    const float* __restrict__ b4, const float* __restrict__ lnw,
    const float* __restrict__ lnb,
    const float* __restrict__ b5, fp16* __restrict__ out)
{
    __shared__ __align__(16) float ABsm[64*APAD];
    __shared__ float sb4[128], sb5[64];

    int tid = threadIdx.x;
    int pix0 = blockIdx.x*128;
    int b = pix0 / HWSZ, hw0 = pix0 - b*HWSZ;
    if (tid < 128) sb4[tid] = __ldg(b4 + tid);
    if (tid < 64)  sb5[tid] = __ldg(b5 + tid);

    // stage A with channel-LN (eps 1e-6), fp16 input
    {
        int p = tid >> 1, h = tid & 1;
        const fp16* src = in + (size_t)(b*64 + h*32)*HWSZ + hw0 + p;
        float v[32];
#pragma unroll
        for (int c = 0; c < 32; c++) v[c] = __half2float(src[c*HWSZ]);
        float s = 0.f;
#pragma unroll
        for (int c = 0; c < 32; c++) s += v[c];
        s += __shfl_xor_sync(0xffffffffu, s, 1);
        float mu = s * (1.f/64.f);
        float q = 0.f;
#pragma unroll
        for (int c = 0; c < 32; c++) { float d = v[c]-mu; q += d*d; }
        q += __shfl_xor_sync(0xffffffffu, q, 1);
        float is = rsqrtf(q*(1.f/64.f) + 1e-6f);
#pragma unroll
        for (int c = 0; c < 32; c++) {
            int ch = h*32 + c;
            float val = (v[c]-mu)*is*__ldg(lnw+ch) + __ldg(lnb+ch);
            ABsm[ch*APAD + p] = __uint_as_float(cvt_tf32(val));
        }
    }
    __syncthreads();

    int warp = tid >> 5, lane = tid & 31, g = lane >> 2, tig = lane & 3;
    int pxA = warp*16 + g;
    unsigned afrag[8][4];
#pragma unroll
    for (int kt = 0; kt < 8; kt++) {
        int ca = kt*8 + tig;
        afrag[kt][0] = __float_as_uint(ABsm[ca*APAD + pxA]);
        afrag[kt][1] = __float_as_uint(ABsm[ca*APAD + pxA + 8]);
        afrag[kt][2] = __float_as_uint(ABsm[(ca+4)*APAD + pxA]);
        afrag[kt][3] = __float_as_uint(ABsm[(ca+4)*APAD + pxA + 8]);
    }

    // MMA 1 (conv4, NT=16)
    const float4* B4g = (const float4*)(g_wfrag + WF_CONV4);
    float acc[16][4];
#pragma unroll
    for (int nt = 0; nt < 16; nt++)
#pragma unroll
        for (int u = 0; u < 4; u++) acc[nt][u] = 0.f;
#pragma unroll
    for (int kt = 0; kt < 8; kt++) {
#pragma unroll
        for (int np = 0; np < 8; np++) {
            float4 bb = __ldg(&B4g[(kt*8 + np)*32 + lane]);
            mma8(acc[2*np],   afrag[kt][0], afrag[kt][1], afrag[kt][2], afrag[kt][3], bb.x, bb.y);
            mma8(acc[2*np+1], afrag[kt][0], afrag[kt][1], afrag[kt][2], afrag[kt][3], bb.z, bb.w);
        }
    }

    // SimpleGate in registers
    float gated[8][4];
#pragma unroll
    for (int nt = 0; nt < 8; nt++) {
        int o0 = nt*8 + 2*tig, o1 = o0 + 1;
        gated[nt][0] = (acc[nt][0] + sb4[o0]) * (acc[nt+8][0] + sb4[o0+64]);
        gated[nt][1] = (acc[nt][1] + sb4[o1]) * (acc[nt+8][1] + sb4[o1+64]);
        gated[nt][2] = (acc[nt][2] + sb4[o0]) * (acc[nt+8][2] + sb4[o0+64]);
        gated[nt][3] = (acc[nt][3] + sb4[o1]) * (acc[nt+8][3] + sb4[o1+64]);
    }
    __syncthreads();

    // route gated through smem as new A matrix [ch][px]
#pragma unroll
    for (int nt = 0; nt < 8; nt++) {
        int o0 = nt*8 + 2*tig, o1 = o0 + 1;
        ABsm[o0*APAD + pxA]     = __uint_as_float(cvt_tf32(gated[nt][0]));
        ABsm[o1*APAD + pxA]     = __uint_as_float(cvt_tf32(gated[nt][1]));
        ABsm[o0*APAD + pxA + 8] = __uint_as_float(cvt_tf32(gated[nt][2]));
        ABsm[o1*APAD + pxA + 8] = __uint_as_float(cvt_tf32(gated[nt][3]));
    }
    __syncthreads();

    unsigned af2[8][4];
#pragma unroll
    for (int kt = 0; kt < 8; kt++) {
        int ca = kt*8 + tig;
        af2[kt][0] = __float_as_uint(ABsm[ca*APAD + pxA]);
        af2[kt][1] = __float_as_uint(ABsm[ca*APAD + pxA + 8]);
        af2[kt][2] = __float_as_uint(ABsm[(ca+4)*APAD + pxA]);
        af2[kt][3] = __float_as_uint(ABsm[(ca+4)*APAD + pxA + 8]);
    }

    // MMA 2 (conv5, NT=8)
    const float4* B5g = (const float4*)(g_wfrag + WF_CONV5);
    float a5[8][4];
#pragma unroll
    for (int nt = 0; nt < 8; nt++)
#pragma unroll
        for (int u = 0; u < 4; u++) a5[nt][u] = 0.f;
#pragma unroll
    for (int kt = 0; kt < 8; kt++) {
#pragma unroll
        for (int np = 0; np < 4; np++) {
            float4 bb = __ldg(&B5g[(kt*4 + np)*32 + lane]);
            mma8(a5[2*np],   af2[kt][0], af2[kt][1], af2[kt][2], af2[kt][3], bb.x, bb.y);
            mma8(a5[2*np+1], af2[kt][0], af2[kt][1], af2[kt][2], af2[kt][3], bb.z, bb.w);
        }
    }

    int pxg = hw0 + warp*16 + g;
#pragma unroll
    for (int nt = 0; nt < 8; nt++) {
        int o0 = nt*8 + 2*tig, o1 = o0 + 1;
        size_t base0 = (size_t)(b*64 + o0)*HWSZ + pxg;
        size_t base1 = (size_t)(b*64 + o1)*HWSZ + pxg;
        out[base0]     = __float2half(a5[nt][0] + sb5[o0]);
        out[base1]     = __float2half(a5[nt][1] + sb5[o1]);
        out[base0 + 8] = __float2half(a5[nt][2] + sb5[o0]);
        out[base1 + 8] = __float2half(a5[nt][3] + sb5[o1]);
    }
}

// ---------------- depthwise 3x3 pair (c, c+64), bf16 io ----------------
__global__ __launch_bounds__(256) void k_dw_stats2(
    const bf16* __restrict__ in, const float* __restrict__ w,
    const float* __restrict__ bias, bf16* __restrict__ out)
{
    int bc = blockIdx.z;                 // b*64 + c
    int c = bc & 63, b = bc >> 6;
    int ca = b*128 + c, cg = ca + 64;
    __shared__ float ta[10][34], tg[10][34];
    __shared__ float rA[256], rB[256], rC[256], rD[256];
    int tx0 = blockIdx.x*32, ty0 = blockIdx.y*8;
    int tid = threadIdx.y*32 + threadIdx.x;
    const bf16* sa = in + (size_t)ca*HWSZ;
    const bf16* sg = in + (size_t)cg*HWSZ;
    for (int i = tid; i < 340; i += 256) {
        int r = i/34, cc = i - r*34;
        int gy = ty0 + r - 1, gx = tx0 + cc - 1;
        bool ok = (gy >= 0 && gy < HH && gx >= 0 && gx < WWID);
        ta[r][cc] = ok ? __bfloat162float(sa[gy*WWID+gx]) : 0.f;
        tg[r][cc] = ok ? __bfloat162float(sg[gy*WWID+gx]) : 0.f;
    }
    __syncthreads();
    float da = bias[c], dg = bias[c+64];
#pragma unroll
    for (int di = 0; di < 3; di++)
#pragma unroll
        for (int dj = 0; dj < 3; dj++) {
            da += w[c*9 + di*3 + dj]      * ta[threadIdx.y+di][threadIdx.x+dj];
            dg += w[(64+c)*9 + di*3 + dj] * tg[threadIdx.y+di][threadIdx.x+dj];
        }
    int gy = ty0 + threadIdx.y, gx = tx0 + threadIdx.x;
    out[(size_t)ca*HWSZ + gy*WWID + gx] = __float2bfloat16(da);
    out[(size_t)cg*HWSZ + gy*WWID + gx] = __float2bfloat16(dg);

    float wd = g_dctR[c*56 + (gy >> 2)] * g_dctC[c*56 + (gx >> 2)];
    rA[tid] = da; rB[tid] = da*da; rC[tid] = wd*da*dg; rD[tid] = wd*dg;
    __syncthreads();
    for (int s = 128; s > 0; s >>= 1) {
        if (tid < s) {
            rA[tid] += rA[tid+s]; rB[tid] += rB[tid+s];
            rC[tid] += rC[tid+s]; rD[tid] += rD[tid+s];
        }
        __syncthreads();
    }
    if (tid == 0) {
        atomicAdd(&g_instS[bc], rA[0]);
        atomicAdd(&g_instQ[bc], rB[0]);
        atomicAdd(&g_scay[bc],  rC[0]);
        atomicAdd(&g_scay2[bc], rD[0]);
    }
}

// ---------------- instnorm finish + SCA pool finish + SE ----------------
__global__ void k_se(const float* __restrict__ fc1, const float* __restrict__ fc2,
                     const float* __restrict__ inw, const float* __restrict__ inb) {
    int b = blockIdx.x, c = threadIdx.x;
    int bc = b*64 + c;
    float m = g_instS[bc] * (1.f/HWSZ);
    float var = g_instQ[bc] * (1.f/HWSZ) - m*m;
    float iv = rsqrtf(var + 1e-5f);
    g_instMean[bc] = m; g_instInv[bc] = iv;
    float A = iv*inw[c];
    __shared__ float ys[64];
    ys[c] = (A*g_scay[bc] + (inb[c] - m*A)*g_scay2[bc]) * (1.f/16.f);
    __syncthreads();
    float h[4];
#pragma unroll
    for (int j = 0; j < 4; j++) {
        float s = 0.f;
#pragma unroll
        for (int k = 0; k < 64; k++) s += fc1[j*64 + k] * ys[k];
        h[j] = fmaxf(s, 0.f);
    }
    float z = 0.f;
#pragma unroll
    for (int j = 0; j < 4; j++) z += fc2[c*4 + j] * h[j];
    g_z[bc] = 1.f / (1.f + expf(-z));
}

// ---------------- per-patch spectral transform, in-place fp16 ----------------
__global__ __launch_bounds__(128) void k_fftapply_rb() {
    if (g_fftNonId == 0) return;
    int bc = blockIdx.x;
    int c  = bc & 127;
    __shared__ __align__(16) float Ms[4096];
    __shared__ __align__(16) float pat[64*60];
    int tid = threadIdx.x;
    const float* msrc = g_M + c*4096;
    for (int i = tid; i < 4096; i += 128) Ms[i] = msrc[i];
    fp16* plane = (fp16*)g_buf2a + (size_t)bc*HWSZ;
    int og = tid & 15, pg = tid >> 4;
    for (int bp = 0; bp < 14; bp++) {
        for (int i = tid; i < 3584; i += 128) {
            int r = i / 224, wcol = i - r*224;
            int p = r & 7, band = r >> 3, pc = wcol >> 3, q = wcol & 7;
            pat[(p*8+q)*60 + band*28 + pc] = __half2float(plane[(bp*16 + r)*224 + wcol]);
        }
        __syncthreads();
        ull acc[4][4];
#pragma unroll
        for (int j = 0; j < 4; j++)
#pragma unroll
            for (int u = 0; u < 4; u++) acc[j][u] = 0ULL;
        if (pg < 7) {
            const float* pI = pat + pg*8;
            for (int k = 0; k < 64; k++) {
                ulonglong2 va = *(const ulonglong2*)(pI + k*60);
                ulonglong2 vb = *(const ulonglong2*)(pI + k*60 + 4);
                float4 wv = *(const float4*)(Ms + k*64 + og*4);
                float wav[4] = {wv.x, wv.y, wv.z, wv.w};
#pragma unroll
                for (int j = 0; j < 4; j++) {
                    ull wp = pack2(wav[j]);
                    acc[j][0] = fma2(va.x, wp, acc[j][0]);
                    acc[j][1] = fma2(va.y, wp, acc[j][1]);
                    acc[j][2] = fma2(vb.x, wp, acc[j][2]);
                    acc[j][3] = fma2(vb.y, wp, acc[j][3]);
                }
            }
        }
        __syncthreads();
        if (pg < 7) {
#pragma unroll
            for (int j = 0; j < 4; j++) {
                int o = og*4 + j;
                ulonglong2 s0, s1;
                s0.x = acc[j][0]; s0.y = acc[j][1];
                s1.x = acc[j][2]; s1.y = acc[j][3];
                *(ulonglong2*)(pat + o*60 + pg*8) = s0;
                *(ulonglong2*)(pat + o*60 + pg*8 + 4) = s1;
            }
        }
        __syncthreads();
        for (int i = tid; i < 3584; i += 128) {
            int r = i / 224, wcol = i - r*224;
            int p = r & 7, band = r >> 3, pc = wcol >> 3, q = wcol & 7;
            plane[(bp*16 + r)*224 + wcol] = __float2half(pat[(p*8+q)*60 + band*28 + pc]);
        }
        __syncthreads();
    }
}

// ---------------- DFFN depthwise 3x3 pair + gelu gate (fp16 io) ----------------
__global__ __launch_bounds__(256) void k_dw_gelu(const float* __restrict__ w) {
    int bc = blockIdx.z;
    int c = bc & 63, b = bc >> 6;
    __shared__ float t1[10][34], t2[10][34];
    int tx0 = blockIdx.x*32, ty0 = blockIdx.y*8;
    int tid = threadIdx.y*32 + threadIdx.x;
    const fp16* s1 = (const fp16*)g_buf2a + (size_t)(b*128 + c)*HWSZ;
    const fp16* s2 = (const fp16*)g_buf2a + (size_t)(b*128 + 64 + c)*HWSZ;
    for (int i = tid; i < 340; i += 256) {
        int r = i/34, cc = i - r*34;
        int gy = ty0 + r - 1, gx = tx0 + cc - 1;
        bool ok = (gy >= 0 && gy < HH && gx >= 0 && gx < WWID);
        t1[r][cc] = ok ? __half2float(s1[gy*WWID+gx]) : 0.f;
        t2[r][cc] = ok ? __half2float(s2[gy*WWID+gx]) : 0.f;
    }
    __syncthreads();
    float d1 = 0.f, d2 = 0.f;
#pragma unroll
    for (int di = 0; di < 3; di++)
#pragma unroll
        for (int dj = 0; dj < 3; dj++) {
            d1 += w[c*9 + di*3 + dj]      * t1[threadIdx.y+di][threadIdx.x+dj];
            d2 += w[(64+c)*9 + di*3 + dj] * t2[threadIdx.y+di][threadIdx.x+dj];
        }
    float gel = 0.5f * d1 * (1.f + erff(d1 * 0.70710678118f));
    ((fp16*)g_bufc)[(size_t)bc*HWSZ + (ty0+threadIdx.y)*WWID + tx0 + threadIdx.x]
        = __float2half(gel * d2);
}

// ---------------- launch ----------------
extern "C" void kernel_launch(void* const* d_in, const int* in_sizes, int n_in,
                              void* d_out, int out_size)
{
    (void)in_sizes; (void)n_in; (void)out_size;
    const float* x       = (const float*)d_in[0];
    const float* n1_w    = (const float*)d_in[1];
    const float* n1_b    = (const float*)d_in[2];
    const float* conv1_w = (const float*)d_in[3];
    const float* conv1_b = (const float*)d_in[4];
    const float* conv2_w = (const float*)d_in[5];
    const float* conv2_b = (const float*)d_in[6];
    const float* in_w    = (const float*)d_in[7];
    const float* in_b    = (const float*)d_in[8];
    const float* fc1_w   = (const float*)d_in[9];
    const float* fc2_w   = (const float*)d_in[10];
    const float* conv3_w = (const float*)d_in[11];
    const float* conv3_b = (const float*)d_in[12];
    const float* beta    = (const float*)d_in[13];
    const float* n2n_w   = (const float*)d_in[14];
    const float* n2n_b   = (const float*)d_in[15];
    const float* conv4_w = (const float*)d_in[16];
    const float* conv4_b = (const float*)d_in[17];
    const float* conv5_w = (const float*)d_in[18];
    const float* conv5_b = (const float*)d_in[19];
    const float* ln_w    = (const float*)d_in[20];
    const float* ln_b    = (const float*)d_in[21];
    const float* pin_w   = (const float*)d_in[22];
    const float* dw_w    = (const float*)d_in[23];
    const float* fft_w   = (const float*)d_in[24];
    const float* pout_w  = (const float*)d_in[25];

    float *t2a, *t2b, *tc, *ty;
    cudaGetSymbolAddress((void**)&t2a, g_buf2a);
    cudaGetSymbolAddress((void**)&t2b, g_buf2b);
    cudaGetSymbolAddress((void**)&tc,  g_bufc);
    cudaGetSymbolAddress((void**)&ty,  g_y);

    bf16* c1bf = (bf16*)t2b;                          // conv1 output [b,128,HW]
    bf16* dwbf = c1bf + (size_t)BB*C2*HWSZ;           // dw output    [b,128,HW]
    fp16* resh = (fp16*)t2b;                          // residual fp16 (c1bf region, free after dw)
    fp16* pinh = (fp16*)t2a;
    fp16* gmh  = (fp16*)tc;
    fp16* yh   = (fp16*)ty;

    const int GB = NPIX / 128;     // 3136 tiles (128 px each)

    k_init<<<64, 128>>>(fft_w);
    {
        dim3 g(32, 8);
        k_wprep_all<<<g, 256>>>(conv1_w, conv3_w, conv4_w, conv5_w, pin_w, pout_w);
    }

    // conv1: LN(n1) + 64->128 + bias  -> bf16 (oc halves interleaved)
    k_tc<2,1,0,1><<<GB*2, 256>>>(x, WF_CONV1, conv1_b, n1_w, n1_b, 1e-6f,
                                 nullptr, nullptr, nullptr, (float*)c1bf, 128);

    // depthwise pair + conv2 bias (bf16 io) + IN stats + SCA pool partials
    {
        dim3 g(7, 28, BB*CCH), blk(32, 8);
        k_dw_stats2<<<g, blk>>>(c1bf, conv2_w, conv2_b, dwbf);
    }
    // instnorm finish + pool finish + SE
    k_se<<<BB, 64>>>(fc1_w, fc2_w, in_w, in_b);

    // conv3 with inline instnorm-gate-z staging + residual -> fp16 (c1bf region free)
    k_tc<1,4,1,2><<<GB, 256>>>((const float*)dwbf, WF_CONV3, conv3_b, in_w, in_b, 0.f,
                               x, beta, nullptr, (float*)resh, 64);
    // fused conv4 + SimpleGate + conv5 -> y fp16
    k_tc45<<<GB, 256>>>(resh, conv4_b, n2n_w, n2n_b, conv5_b, yh);

    // DFFN: LN(fp16 y) + pin (64->128) -> fp16 in g_buf2a (oc halves interleaved)
    k_tc<2,6,0,2><<<GB*2, 256>>>((const float*)yh, WF_PIN, nullptr, ln_w, ln_b, 1e-5f,
                                 nullptr, nullptr, nullptr, (float*)pinh, 128);
    // patch spectral transform in-place fp16 (skips when identity)
    k_fftapply_rb<<<BB*C2, 128>>>();
    // depthwise pair + gelu gate -> fp16 g_bufc
    {
        dim3 g(7, 28, BB*CCH), blk(32, 8);
        k_dw_gelu<<<g, blk>>>(dw_w);
    }
    // pout (fp16 in) + y(fp16) -> d_out fp32
    k_tc<1,5,2,2><<<GB, 256>>>((const float*)gmh, WF_POUT, nullptr, nullptr, nullptr, 0.f,
                               nullptr, nullptr, (const float*)yh, (float*)d_out, 64);
}